// round 7
// baseline (speedup 1.0000x reference)
#include <cuda_runtime.h>
#include <cuda_bf16.h>
#include <cstdint>

#define NN   50000
#define EE   800000
#define HH   4
#define CC   32
#define HC   128
#define NGR  64
#define NOUT 10
#define NB_SCAN 49   // ceil(NN/1024)
#define STR  68      // smem row stride in 32-bit words (conflict-free for quad loads)

// ---------------- scratch (device globals; no allocation allowed) ------------
__device__ float g_h[NN * HC];
__device__ float g_acc[NN * HC];
__device__ float g_x[NN * HC];
__device__ float g_as[NN * HH];
__device__ float g_ad[NN * HH];
__device__ float g_pool[NGR * CC];
__device__ float g_cnt[NGR];
// CSR by destination
__device__ int g_cnt_i[NN];
__device__ int g_rowptr[NN + 1];
__device__ int g_cursor[NN];
__device__ int g_csrc[EE];
__device__ int g_bsum[NB_SCAN];
__device__ int g_boff[NB_SCAN];
// bf16-split transposed weights Wt[n][k] per GAT layer
__device__ unsigned short g_WtHi[2][HC * HC];
__device__ unsigned short g_WtLo[2][HC * HC];

__device__ __forceinline__ float lrelu(float v) { return v > 0.f ? v : 0.2f * v; }
__device__ __forceinline__ float sel4(float4 a, int hd) {
    return (hd == 0) ? a.x : (hd == 1) ? a.y : (hd == 2) ? a.z : a.w;
}

// ---------------- W -> bf16 hi/lo transposed prep ----------------------------
__global__ void k_prepWt(const float* __restrict__ W, int layer) {
    int i = blockIdx.x * blockDim.x + threadIdx.x;  // i = k*128 + n
    if (i >= HC * HC) return;
    int k = i >> 7, n = i & 127;
    float w = W[i];
    __nv_bfloat16 hb = __float2bfloat16(w);
    __nv_bfloat16 lb = __float2bfloat16(w - __bfloat162float(hb));
    g_WtHi[layer][n * HC + k] = __bfloat16_as_ushort(hb);
    g_WtLo[layer][n * HC + k] = __bfloat16_as_ushort(lb);
}

// ---------------- mma.sync bf16-split GEMM128 + attention epilogue -----------
#define MMA_BF16(c, A0, A1, A2, A3, B0, B1) \
    asm volatile("mma.sync.aligned.m16n8k16.row.col.f32.bf16.bf16.f32 " \
        "{%0,%1,%2,%3}, {%4,%5,%6,%7}, {%8,%9}, {%0,%1,%2,%3};" \
        : "+f"((c)[0]), "+f"((c)[1]), "+f"((c)[2]), "+f"((c)[3]) \
        : "r"(A0), "r"(A1), "r"(A2), "r"(A3), "r"(B0), "r"(B1))

#define SMEM_MMA (4 * 128 * STR * 4 + 1024)

__global__ __launch_bounds__(256, 1) void k_gemm128mma(
    const float* __restrict__ X, int layer,
    const float* __restrict__ aws, const float* __restrict__ awd) {
    extern __shared__ __align__(16) char smem[];
    uint32_t* xh = reinterpret_cast<uint32_t*>(smem);
    uint32_t* xl = xh + 128 * STR;
    uint32_t* wh = xl + 128 * STR;
    uint32_t* wl = wh + 128 * STR;
    float* sws = reinterpret_cast<float*>(wl + 128 * STR);
    float* swd = sws + 128;
    int tid = threadIdx.x, lane = tid & 31, wid = tid >> 5;
    int gid = lane >> 2, tg = lane & 3;
    int row0 = blockIdx.x * 128;

    if (tid < 128) { sws[tid] = aws[tid]; swd[tid] = awd[tid]; }
    {
        const uint32_t* gh = reinterpret_cast<const uint32_t*>(g_WtHi[layer]);
        const uint32_t* gl = reinterpret_cast<const uint32_t*>(g_WtLo[layer]);
        for (int i = tid; i < 128 * 64; i += 256) {
            int r = i >> 6, w = i & 63;
            wh[r * STR + w] = gh[i];
            wl[r * STR + w] = gl[i];
        }
    }
    {
        const float4* X4 = reinterpret_cast<const float4*>(X);
        for (int i = tid; i < 128 * 32; i += 256) {
            int r = i >> 5, q = i & 31;
            int grow = row0 + r;
            float4 v = (grow < NN) ? X4[(size_t)grow * 32 + q] : make_float4(0.f, 0.f, 0.f, 0.f);
            float vv[4] = {v.x, v.y, v.z, v.w};
#pragma unroll
            for (int q2 = 0; q2 < 2; q2++) {
                __nv_bfloat16 h0 = __float2bfloat16(vv[2 * q2]);
                __nv_bfloat16 h1 = __float2bfloat16(vv[2 * q2 + 1]);
                __nv_bfloat16 l0 = __float2bfloat16(vv[2 * q2] - __bfloat162float(h0));
                __nv_bfloat16 l1 = __float2bfloat16(vv[2 * q2 + 1] - __bfloat162float(h1));
                xh[r * STR + 2 * q + q2] =
                    ((uint32_t)__bfloat16_as_ushort(h1) << 16) | __bfloat16_as_ushort(h0);
                xl[r * STR + 2 * q + q2] =
                    ((uint32_t)__bfloat16_as_ushort(l1) << 16) | __bfloat16_as_ushort(l0);
            }
        }
    }
    __syncthreads();

    float acc[16][4];
#pragma unroll
    for (int t = 0; t < 16; t++)
#pragma unroll
        for (int j = 0; j < 4; j++) acc[t][j] = 0.f;

    int m0 = wid * 16;
    const uint32_t* xrh = xh + (m0 + gid) * STR + tg;
    const uint32_t* xrl = xl + (m0 + gid) * STR + tg;
#pragma unroll 1
    for (int kk = 0; kk < 8; kk++) {
        int kw = kk * 8;
        uint32_t ah0 = xrh[kw],           ah2 = xrh[kw + 4];
        uint32_t ah1 = xrh[kw + 8 * STR], ah3 = xrh[kw + 8 * STR + 4];
        uint32_t al0 = xrl[kw],           al2 = xrl[kw + 4];
        uint32_t al1 = xrl[kw + 8 * STR], al3 = xrl[kw + 8 * STR + 4];
#pragma unroll
        for (int t = 0; t < 16; t++) {
            const uint32_t* wrh = wh + (t * 8 + gid) * STR + kw + tg;
            const uint32_t* wrl = wl + (t * 8 + gid) * STR + kw + tg;
            uint32_t bh0 = wrh[0], bh1 = wrh[4];
            uint32_t bl0 = wrl[0], bl1 = wrl[4];
            MMA_BF16(acc[t], ah0, ah1, ah2, ah3, bh0, bh1);
            MMA_BF16(acc[t], ah0, ah1, ah2, ah3, bl0, bl1);
            MMA_BF16(acc[t], al0, al1, al2, al3, bh0, bh1);
        }
    }

    int r0 = row0 + m0 + gid, r1 = r0 + 8;
#pragma unroll
    for (int t = 0; t < 16; t++) {
        int col = t * 8 + 2 * tg;
        if (r0 < NN) *reinterpret_cast<float2*>(&g_h[(size_t)r0 * HC + col]) =
            make_float2(acc[t][0], acc[t][1]);
        if (r1 < NN) *reinterpret_cast<float2*>(&g_h[(size_t)r1 * HC + col]) =
            make_float2(acc[t][2], acc[t][3]);
    }
#pragma unroll
    for (int h = 0; h < 4; h++) {
        float ps0 = 0.f, pd0 = 0.f, ps1 = 0.f, pd1 = 0.f;
#pragma unroll
        for (int j = 0; j < 4; j++) {
            int t = 4 * h + j;
            int col = t * 8 + 2 * tg;
            float w0 = sws[col], w1 = sws[col + 1];
            float v0 = swd[col], v1 = swd[col + 1];
            ps0 = fmaf(acc[t][0], w0, fmaf(acc[t][1], w1, ps0));
            pd0 = fmaf(acc[t][0], v0, fmaf(acc[t][1], v1, pd0));
            ps1 = fmaf(acc[t][2], w0, fmaf(acc[t][3], w1, ps1));
            pd1 = fmaf(acc[t][2], v0, fmaf(acc[t][3], v1, pd1));
        }
#pragma unroll
        for (int o = 1; o <= 2; o <<= 1) {
            ps0 += __shfl_xor_sync(0xffffffffu, ps0, o);
            pd0 += __shfl_xor_sync(0xffffffffu, pd0, o);
            ps1 += __shfl_xor_sync(0xffffffffu, ps1, o);
            pd1 += __shfl_xor_sync(0xffffffffu, pd1, o);
        }
        if (tg == 0) {
            if (r0 < NN) { g_as[r0 * HH + h] = ps0; g_ad[r0 * HH + h] = pd0; }
            if (r1 < NN) { g_as[r1 * HH + h] = ps1; g_ad[r1 * HH + h] = pd1; }
        }
    }
}

// ---------------- CSR build ---------------------------------------------------
__global__ void k_count(const int* __restrict__ dst) {
    int e = blockIdx.x * blockDim.x + threadIdx.x;
    if (e < EE) atomicAdd(&g_cnt_i[dst[e]], 1);
}

__global__ void k_scan1() {
    __shared__ int wsum[32];
    int t = threadIdx.x, b = blockIdx.x;
    int i = b * 1024 + t;
    int v = (i < NN) ? g_cnt_i[i] : 0;
    int incl = v;
#pragma unroll
    for (int o = 1; o < 32; o <<= 1) {
        int n = __shfl_up_sync(0xffffffffu, incl, o);
        if ((t & 31) >= o) incl += n;
    }
    if ((t & 31) == 31) wsum[t >> 5] = incl;
    __syncthreads();
    if (t < 32) {
        int wv = wsum[t];
#pragma unroll
        for (int o = 1; o < 32; o <<= 1) {
            int n = __shfl_up_sync(0xffffffffu, wv, o);
            if (t >= o) wv += n;
        }
        wsum[t] = wv;
    }
    __syncthreads();
    int excl = incl - v + ((t >= 32) ? wsum[(t >> 5) - 1] : 0);
    if (i < NN) g_rowptr[i] = excl;
    if (t == 1023) g_bsum[b] = excl + v;
}

__global__ void k_scan2() {
    __shared__ int w0s;
    int t = threadIdx.x;
    int v = (t < NB_SCAN) ? g_bsum[t] : 0;
    int incl = v;
#pragma unroll
    for (int o = 1; o < 32; o <<= 1) {
        int n = __shfl_up_sync(0xffffffffu, incl, o);
        if ((t & 31) >= o) incl += n;
    }
    if (t == 31) w0s = incl;
    __syncthreads();
    if (t >= 32) incl += w0s;
    if (t < NB_SCAN) g_boff[t] = incl - v;
}

__global__ void k_scan3() {
    int i = blockIdx.x * blockDim.x + threadIdx.x;
    if (i < NN) {
        int v = g_rowptr[i] + g_boff[i >> 10];
        g_rowptr[i] = v;
        g_cursor[i] = v;
    }
    if (i == 0) g_rowptr[NN] = EE;
}

__global__ void k_fill(const int* __restrict__ src, const int* __restrict__ dst) {
    int e = blockIdx.x * blockDim.x + threadIdx.x;
    if (e >= EE) return;
    int pos = atomicAdd(&g_cursor[dst[e]], 1);
    g_csrc[pos] = src[e];
}

// ---------------- fused GAT aggregation: warp per dst node, 4-way unroll ------
__global__ void k_gat_aggr(const float* __restrict__ bias) {
    int w = (blockIdx.x * blockDim.x + threadIdx.x) >> 5;
    if (w >= NN) return;
    int lane = threadIdx.x & 31;
    int row0 = g_rowptr[w], row1 = g_rowptr[w + 1];
    float4 ad4 = reinterpret_cast<const float4*>(g_ad)[w];
    float4 as_self = reinterpret_cast<const float4*>(g_as)[w];
    int hd = lane >> 3;
    float ad_l = sel4(ad4, hd);
    const float4* AS = reinterpret_cast<const float4*>(g_as);
    const float4* HV = reinterpret_cast<const float4*>(g_h);
    float4 acc = make_float4(0.f, 0.f, 0.f, 0.f);
    float z = 0.f;
    int k = row0;
    for (; k + 4 <= row1; k += 4) {
        int s0 = g_csrc[k], s1 = g_csrc[k + 1], s2 = g_csrc[k + 2], s3 = g_csrc[k + 3];
        float4 a0 = AS[s0], a1 = AS[s1], a2 = AS[s2], a3 = AS[s3];
        float4 h0 = HV[s0 * 32 + lane], h1 = HV[s1 * 32 + lane];
        float4 h2 = HV[s2 * 32 + lane], h3 = HV[s3 * 32 + lane];
        float w0 = __expf(lrelu(sel4(a0, hd) + ad_l));
        float w1 = __expf(lrelu(sel4(a1, hd) + ad_l));
        float w2 = __expf(lrelu(sel4(a2, hd) + ad_l));
        float w3 = __expf(lrelu(sel4(a3, hd) + ad_l));
        z += (w0 + w1) + (w2 + w3);
        acc.x = fmaf(w0, h0.x, fmaf(w1, h1.x, fmaf(w2, h2.x, fmaf(w3, h3.x, acc.x))));
        acc.y = fmaf(w0, h0.y, fmaf(w1, h1.y, fmaf(w2, h2.y, fmaf(w3, h3.y, acc.y))));
        acc.z = fmaf(w0, h0.z, fmaf(w1, h1.z, fmaf(w2, h2.z, fmaf(w3, h3.z, acc.z))));
        acc.w = fmaf(w0, h0.w, fmaf(w1, h1.w, fmaf(w2, h2.w, fmaf(w3, h3.w, acc.w))));
    }
    for (; k < row1; k++) {
        int s = g_csrc[k];
        float4 a = AS[s];
        float4 hv = HV[s * 32 + lane];
        float wgt = __expf(lrelu(sel4(a, hd) + ad_l));
        z += wgt;
        acc.x = fmaf(wgt, hv.x, acc.x);
        acc.y = fmaf(wgt, hv.y, acc.y);
        acc.z = fmaf(wgt, hv.z, acc.z);
        acc.w = fmaf(wgt, hv.w, acc.w);
    }
    float wsf = __expf(lrelu(sel4(as_self, hd) + ad_l));
    z += wsf;
    float4 hs = HV[w * 32 + lane];
    acc.x = fmaf(wsf, hs.x, acc.x);
    acc.y = fmaf(wsf, hs.y, acc.y);
    acc.z = fmaf(wsf, hs.z, acc.z);
    acc.w = fmaf(wsf, hs.w, acc.w);
    float inv = 1.f / (z + 1e-16f);
    float4 b = reinterpret_cast<const float4*>(bias)[lane];
    float4 r;
    r.x = fmaxf(acc.x * inv + b.x, 0.f);
    r.y = fmaxf(acc.y * inv + b.y, 0.f);
    r.z = fmaxf(acc.z * inv + b.z, 0.f);
    r.w = fmaxf(acc.w * inv + b.w, 0.f);
    reinterpret_cast<float4*>(g_x)[w * 32 + lane] = r;
}

// ---------------- CSR gather, 32-wide (8 lanes / dst), 4-way unroll -----------
__global__ void k_csr_aggr32(const float* __restrict__ P, float* __restrict__ Agg,
                             int mean) {
    int q = (blockIdx.x * blockDim.x + threadIdx.x) >> 3;
    if (q >= NN) return;
    int lane = threadIdx.x & 7;
    int row0 = g_rowptr[q], row1 = g_rowptr[q + 1];
    const float4* P4 = reinterpret_cast<const float4*>(P);
    float4 acc = make_float4(0.f, 0.f, 0.f, 0.f);
    int k = row0;
    for (; k + 4 <= row1; k += 4) {
        int s0 = g_csrc[k], s1 = g_csrc[k + 1], s2 = g_csrc[k + 2], s3 = g_csrc[k + 3];
        float4 p0 = P4[s0 * 8 + lane], p1 = P4[s1 * 8 + lane];
        float4 p2 = P4[s2 * 8 + lane], p3 = P4[s3 * 8 + lane];
        acc.x += (p0.x + p1.x) + (p2.x + p3.x);
        acc.y += (p0.y + p1.y) + (p2.y + p3.y);
        acc.z += (p0.z + p1.z) + (p2.z + p3.z);
        acc.w += (p0.w + p1.w) + (p2.w + p3.w);
    }
    for (; k < row1; k++) {
        int s = g_csrc[k];
        float4 p = P4[s * 8 + lane];
        acc.x += p.x; acc.y += p.y; acc.z += p.z; acc.w += p.w;
    }
    if (mean) {
        float inv = 1.f / fmaxf((float)(row1 - row0), 1.f);
        acc.x *= inv; acc.y *= inv; acc.z *= inv; acc.w *= inv;
    }
    reinterpret_cast<float4*>(Agg)[q * 8 + lane] = acc;
}

// ---------------- fused dual projection: Ya = X@Wa, Yb = X@Wb ----------------
template <int FIN>
__global__ __launch_bounds__(256) void k_proj2(
    const float* __restrict__ X, const float* __restrict__ Wa,
    const float* __restrict__ Wb, float* __restrict__ Ya, float* __restrict__ Yb) {
    __shared__ float Xs[64][FIN];
    int t = threadIdx.x, tx = t & 31, ty = t >> 5;
    int row0 = blockIdx.x * 64;
    const float4* Xg = reinterpret_cast<const float4*>(X);
    for (int i = t; i < 64 * (FIN / 4); i += 256) {
        int r = i / (FIN / 4), kq = i % (FIN / 4);
        int row = row0 + r;
        float4 v = (row < NN) ? Xg[row * (FIN / 4) + kq] : make_float4(0.f, 0.f, 0.f, 0.f);
        *reinterpret_cast<float4*>(&Xs[r][kq * 4]) = v;
    }
    __syncthreads();
    float a[8], b[8];
#pragma unroll
    for (int r = 0; r < 8; r++) { a[r] = 0.f; b[r] = 0.f; }
#pragma unroll 4
    for (int k = 0; k < FIN; k++) {
        float wa = __ldg(&Wa[k * CC + tx]);
        float wb = __ldg(&Wb[k * CC + tx]);
#pragma unroll
        for (int r = 0; r < 8; r++) {
            float xv = Xs[ty * 8 + r][k];
            a[r] = fmaf(xv, wa, a[r]);
            b[r] = fmaf(xv, wb, b[r]);
        }
    }
#pragma unroll
    for (int r = 0; r < 8; r++) {
        int row = row0 + ty * 8 + r;
        if (row < NN) {
            Ya[row * CC + tx] = a[r];
            Yb[row * CC + tx] = b[r];
        }
    }
}

// ---------------- elementwise combine: Y = relu(A + B + bias) ----------------
__global__ void k_combine(const float* __restrict__ A, const float* __restrict__ B,
                          const float* __restrict__ bias, float* __restrict__ Y) {
    int tid = blockIdx.x * blockDim.x + threadIdx.x;
    if (tid >= NN * 8) return;
    int c = tid & 7;
    float4 a = reinterpret_cast<const float4*>(A)[tid];
    float4 b = reinterpret_cast<const float4*>(B)[tid];
    float4 bb = reinterpret_cast<const float4*>(bias)[c];
    float4 r;
    r.x = fmaxf(a.x + b.x + bb.x, 0.f);
    r.y = fmaxf(a.y + b.y + bb.y, 0.f);
    r.z = fmaxf(a.z + b.z + bb.z, 0.f);
    r.w = fmaxf(a.w + b.w + bb.w, 0.f);
    reinterpret_cast<float4*>(Y)[tid] = r;
}

// ---------------- global mean pool (8 lanes/node, float4 atomics) ------------
__global__ void k_pool(const int* __restrict__ batch, const float* __restrict__ X) {
    int tid = blockIdx.x * blockDim.x + threadIdx.x;
    if (tid >= NN * 8) return;
    int node = tid >> 3, c = tid & 7;
    int b = batch[node];
    float4 v = reinterpret_cast<const float4*>(X)[node * 8 + c];
    atomicAdd(reinterpret_cast<float4*>(g_pool) + b * 8 + c, v);
    if (c == 0) atomicAdd(&g_cnt[b], 1.f);
}

// ---------------- MLP head (single tiny block) -------------------------------
__global__ void k_head(const float* __restrict__ Wf1, const float* __restrict__ bf1,
                       const float* __restrict__ Wf2, const float* __restrict__ bf2,
                       float* __restrict__ out) {
    __shared__ float t1[NGR * CC];
    int t = threadIdx.x;
    for (int idx = t; idx < NGR * CC; idx += blockDim.x) {
        int g = idx >> 5, c = idx & 31;
        float inv = 1.f / fmaxf(g_cnt[g], 1.f);
        float s = 0.f;
#pragma unroll
        for (int k = 0; k < CC; k++) s = fmaf(g_pool[g * CC + k] * inv, Wf1[k * CC + c], s);
        t1[idx] = fmaxf(s + bf1[c], 0.f);
    }
    __syncthreads();
    for (int idx = t; idx < NGR * NOUT; idx += blockDim.x) {
        int g = idx / NOUT, o = idx - g * NOUT;
        float s = 0.f;
#pragma unroll
        for (int k = 0; k < CC; k++) s = fmaf(t1[g * CC + k], Wf2[k * NOUT + o], s);
        out[idx] = s + bf2[o];
    }
}

// =============================================================================
extern "C" void kernel_launch(void* const* d_in, const int* in_sizes, int n_in,
                              void* d_out, int out_size) {
    const float* x   = (const float*)d_in[0];
    const int*   ei  = (const int*)d_in[1];
    const int*   bat = (const int*)d_in[2];
    const float* W1  = (const float*)d_in[3];
    const float* as1 = (const float*)d_in[4];
    const float* ad1 = (const float*)d_in[5];
    const float* b1  = (const float*)d_in[6];
    const float* W2  = (const float*)d_in[7];
    const float* as2 = (const float*)d_in[8];
    const float* ad2 = (const float*)d_in[9];
    const float* b2  = (const float*)d_in[10];
    const float* W3r = (const float*)d_in[11];
    const float* W3l = (const float*)d_in[12];
    const float* b3  = (const float*)d_in[13];
    const float* W4l = (const float*)d_in[14];
    const float* b4l = (const float*)d_in[15];
    const float* W4r = (const float*)d_in[16];
    const float* Wf1 = (const float*)d_in[17];
    const float* bf1 = (const float*)d_in[18];
    const float* Wf2 = (const float*)d_in[19];
    const float* bf2 = (const float*)d_in[20];
    const int* src = ei;
    const int* dst = ei + EE;
    float* out = (float*)d_out;

    static float *p_h = nullptr, *p_acc, *p_x, *p_pool, *p_cnt;
    static int* p_cnt_i;
    static bool attr_done = false;
    if (!p_h) {
        cudaGetSymbolAddress((void**)&p_h, g_h);
        cudaGetSymbolAddress((void**)&p_acc, g_acc);
        cudaGetSymbolAddress((void**)&p_x, g_x);
        cudaGetSymbolAddress((void**)&p_pool, g_pool);
        cudaGetSymbolAddress((void**)&p_cnt, g_cnt);
        cudaGetSymbolAddress((void**)&p_cnt_i, g_cnt_i);
    }
    if (!attr_done) {
        cudaFuncSetAttribute(k_gemm128mma, cudaFuncAttributeMaxDynamicSharedMemorySize, SMEM_MMA);
        attr_done = true;
    }

    const int T = 256;
    const int gE    = (EE + T - 1) / T;
    const int gWNN  = (NN * 32 + T - 1) / T;   // warp per node
    const int gQ8   = (NN * 8 + T - 1) / T;    // 8 lanes per node
    const int gR64  = (NN + 63) / 64;          // 64-row tiles
    const int gTC   = (NN + 127) / 128;        // 128-row MMA tiles

    // ---- W prep (bf16 split, transposed) + CSR build ----
    k_prepWt<<<(HC * HC + T - 1) / T, T>>>(W1, 0);
    k_prepWt<<<(HC * HC + T - 1) / T, T>>>(W2, 1);
    cudaMemsetAsync(p_cnt_i, 0, NN * sizeof(int));
    k_count<<<gE, T>>>(dst);
    k_scan1<<<NB_SCAN, 1024>>>();
    k_scan2<<<1, 64>>>();
    k_scan3<<<(NN + 1023) / 1024, 1024>>>();
    k_fill<<<gE, T>>>(src, dst);

    // ---- GAT layer 1 ----
    k_gemm128mma<<<gTC, 256, SMEM_MMA>>>(x, 0, as1, ad1);
    k_gat_aggr<<<gWNN, T>>>(b1);

    // ---- GAT layer 2 ----
    k_gemm128mma<<<gTC, 256, SMEM_MMA>>>(p_x, 1, as2, ad2);
    k_gat_aggr<<<gWNN, T>>>(b2);

    // ---- GraphConv: x3 = relu(segsum((x2@W3r)[src]) + x2@W3l + b3) ----
    k_proj2<HC><<<gR64, 256>>>(p_x, W3r, W3l, p_acc, p_h);   // P=g_acc, Q=g_h
    k_csr_aggr32<<<gQ8, T>>>(p_acc, p_x, 0);                 // Agg -> g_x
    k_combine<<<gQ8, T>>>(p_x, p_h, b3, p_acc);              // x3 -> g_acc

    // ---- SAGEConv: x4 = relu(mean((x3@W4l)[src]) + x3@W4r + b4l) ----
    k_proj2<CC><<<gR64, 256>>>(p_acc, W4l, W4r, p_x, p_h);   // P2=g_x, R=g_h
    k_csr_aggr32<<<gQ8, T>>>(p_x, p_acc, 1);                 // mean -> g_acc
    k_combine<<<gQ8, T>>>(p_acc, p_h, b4l, p_x);             // x4 -> g_x

    // ---- pool + head ----
    cudaMemsetAsync(p_pool, 0, NGR * CC * sizeof(float));
    cudaMemsetAsync(p_cnt, 0, NGR * sizeof(float));
    k_pool<<<(NN * 8 + T - 1) / T, T>>>(bat, p_x);
    k_head<<<1, 1024>>>(Wf1, bf1, Wf2, bf2, out);
}

// round 8
// speedup vs baseline: 1.1237x; 1.1237x over previous
#include <cuda_runtime.h>
#include <cuda_bf16.h>
#include <cstdint>

#define NN   50000
#define EE   800000
#define HH   4
#define CC   32
#define HC   128
#define NGR  64
#define NOUT 10
#define NB_SCAN 49   // ceil(NN/1024)
#define STR  68      // smem row stride in 32-bit words

// ---------------- scratch (device globals; no allocation allowed) ------------
__device__ float g_h[NN * HC];
__device__ float g_acc[NN * HC];
__device__ float g_x[NN * HC];
__device__ float g_as[NN * HH];
__device__ float g_ad[NN * HH];
__device__ float g_pool[NGR * CC];
__device__ float g_cnt[NGR];
// CSR by destination
__device__ int g_cnt_i[NN];
__device__ int g_rowptr[NN + 1];
__device__ int g_cursor[NN];
__device__ int g_csrc[EE];
__device__ int g_bsum[NB_SCAN];
__device__ int g_boff[NB_SCAN];
// bf16-split transposed weights Wt[n][k] per GAT layer
__device__ unsigned short g_WtHi[2][HC * HC];
__device__ unsigned short g_WtLo[2][HC * HC];

__device__ __forceinline__ float lrelu(float v) { return v > 0.f ? v : 0.2f * v; }
__device__ __forceinline__ float sel4(float4 a, int hd) {
    return (hd == 0) ? a.x : (hd == 1) ? a.y : (hd == 2) ? a.z : a.w;
}

// ---------------- W -> bf16 hi/lo transposed prep ----------------------------
__global__ void k_prepWt(const float* __restrict__ W, int layer) {
    int i = blockIdx.x * blockDim.x + threadIdx.x;  // i = k*128 + n
    if (i >= HC * HC) return;
    int k = i >> 7, n = i & 127;
    float w = W[i];
    __nv_bfloat16 hb = __float2bfloat16(w);
    __nv_bfloat16 lb = __float2bfloat16(w - __bfloat162float(hb));
    g_WtHi[layer][n * HC + k] = __bfloat16_as_ushort(hb);
    g_WtLo[layer][n * HC + k] = __bfloat16_as_ushort(lb);
}

// ---------------- mma.sync bf16-split GEMM128 + attention epilogue -----------
#define MMA_BF16(c, A0, A1, A2, A3, B0, B1) \
    asm volatile("mma.sync.aligned.m16n8k16.row.col.f32.bf16.bf16.f32 " \
        "{%0,%1,%2,%3}, {%4,%5,%6,%7}, {%8,%9}, {%0,%1,%2,%3};" \
        : "+f"((c)[0]), "+f"((c)[1]), "+f"((c)[2]), "+f"((c)[3]) \
        : "r"(A0), "r"(A1), "r"(A2), "r"(A3), "r"(B0), "r"(B1))

#define SMEM_MMA (4 * 128 * STR * 4 + 1024)

__global__ __launch_bounds__(256, 1) void k_gemm128mma(
    const float* __restrict__ X, int layer,
    const float* __restrict__ aws, const float* __restrict__ awd) {
    extern __shared__ __align__(16) char smem[];
    uint32_t* xh = reinterpret_cast<uint32_t*>(smem);
    uint32_t* xl = xh + 128 * STR;
    uint32_t* wh = xl + 128 * STR;
    uint32_t* wl = wh + 128 * STR;
    float* sws = reinterpret_cast<float*>(wl + 128 * STR);
    float* swd = sws + 128;
    int tid = threadIdx.x, lane = tid & 31, wid = tid >> 5;
    int gid = lane >> 2, tg = lane & 3;
    int row0 = blockIdx.x * 128;

    if (tid < 128) { sws[tid] = aws[tid]; swd[tid] = awd[tid]; }
    {
        const uint32_t* gh = reinterpret_cast<const uint32_t*>(g_WtHi[layer]);
        const uint32_t* gl = reinterpret_cast<const uint32_t*>(g_WtLo[layer]);
        for (int i = tid; i < 128 * 64; i += 256) {
            int r = i >> 6, w = i & 63;
            wh[r * STR + w] = gh[i];
            wl[r * STR + w] = gl[i];
        }
    }
    {
        const float4* X4 = reinterpret_cast<const float4*>(X);
        for (int i = tid; i < 128 * 32; i += 256) {
            int r = i >> 5, q = i & 31;
            int grow = row0 + r;
            float4 v = (grow < NN) ? X4[(size_t)grow * 32 + q] : make_float4(0.f, 0.f, 0.f, 0.f);
            float vv[4] = {v.x, v.y, v.z, v.w};
#pragma unroll
            for (int q2 = 0; q2 < 2; q2++) {
                __nv_bfloat16 h0 = __float2bfloat16(vv[2 * q2]);
                __nv_bfloat16 h1 = __float2bfloat16(vv[2 * q2 + 1]);
                __nv_bfloat16 l0 = __float2bfloat16(vv[2 * q2] - __bfloat162float(h0));
                __nv_bfloat16 l1 = __float2bfloat16(vv[2 * q2 + 1] - __bfloat162float(h1));
                xh[r * STR + 2 * q + q2] =
                    ((uint32_t)__bfloat16_as_ushort(h1) << 16) | __bfloat16_as_ushort(h0);
                xl[r * STR + 2 * q + q2] =
                    ((uint32_t)__bfloat16_as_ushort(l1) << 16) | __bfloat16_as_ushort(l0);
            }
        }
    }
    __syncthreads();

    float acc[16][4];
#pragma unroll
    for (int t = 0; t < 16; t++)
#pragma unroll
        for (int j = 0; j < 4; j++) acc[t][j] = 0.f;

    int m0 = wid * 16;
    const uint32_t* xrh = xh + (m0 + gid) * STR + tg;
    const uint32_t* xrl = xl + (m0 + gid) * STR + tg;
#pragma unroll 1
    for (int kk = 0; kk < 8; kk++) {
        int kw = kk * 8;
        uint32_t ah0 = xrh[kw],           ah2 = xrh[kw + 4];
        uint32_t ah1 = xrh[kw + 8 * STR], ah3 = xrh[kw + 8 * STR + 4];
        uint32_t al0 = xrl[kw],           al2 = xrl[kw + 4];
        uint32_t al1 = xrl[kw + 8 * STR], al3 = xrl[kw + 8 * STR + 4];
#pragma unroll
        for (int t = 0; t < 16; t++) {
            const uint32_t* wrh = wh + (t * 8 + gid) * STR + kw + tg;
            const uint32_t* wrl = wl + (t * 8 + gid) * STR + kw + tg;
            uint32_t bh0 = wrh[0], bh1 = wrh[4];
            uint32_t bl0 = wrl[0], bl1 = wrl[4];
            MMA_BF16(acc[t], ah0, ah1, ah2, ah3, bh0, bh1);
            MMA_BF16(acc[t], ah0, ah1, ah2, ah3, bl0, bl1);
            MMA_BF16(acc[t], al0, al1, al2, al3, bh0, bh1);
        }
    }

    int r0 = row0 + m0 + gid, r1 = r0 + 8;
#pragma unroll
    for (int t = 0; t < 16; t++) {
        int col = t * 8 + 2 * tg;
        if (r0 < NN) *reinterpret_cast<float2*>(&g_h[(size_t)r0 * HC + col]) =
            make_float2(acc[t][0], acc[t][1]);
        if (r1 < NN) *reinterpret_cast<float2*>(&g_h[(size_t)r1 * HC + col]) =
            make_float2(acc[t][2], acc[t][3]);
    }
#pragma unroll
    for (int h = 0; h < 4; h++) {
        float ps0 = 0.f, pd0 = 0.f, ps1 = 0.f, pd1 = 0.f;
#pragma unroll
        for (int j = 0; j < 4; j++) {
            int t = 4 * h + j;
            int col = t * 8 + 2 * tg;
            float w0 = sws[col], w1 = sws[col + 1];
            float v0 = swd[col], v1 = swd[col + 1];
            ps0 = fmaf(acc[t][0], w0, fmaf(acc[t][1], w1, ps0));
            pd0 = fmaf(acc[t][0], v0, fmaf(acc[t][1], v1, pd0));
            ps1 = fmaf(acc[t][2], w0, fmaf(acc[t][3], w1, ps1));
            pd1 = fmaf(acc[t][2], v0, fmaf(acc[t][3], v1, pd1));
        }
#pragma unroll
        for (int o = 1; o <= 2; o <<= 1) {
            ps0 += __shfl_xor_sync(0xffffffffu, ps0, o);
            pd0 += __shfl_xor_sync(0xffffffffu, pd0, o);
            ps1 += __shfl_xor_sync(0xffffffffu, ps1, o);
            pd1 += __shfl_xor_sync(0xffffffffu, pd1, o);
        }
        if (tg == 0) {
            if (r0 < NN) { g_as[r0 * HH + h] = ps0; g_ad[r0 * HH + h] = pd0; }
            if (r1 < NN) { g_as[r1 * HH + h] = ps1; g_ad[r1 * HH + h] = pd1; }
        }
    }
}

// ---------------- CSR build ---------------------------------------------------
__global__ void k_count(const int* __restrict__ dst) {
    int e = blockIdx.x * blockDim.x + threadIdx.x;
    if (e < EE) atomicAdd(&g_cnt_i[dst[e]], 1);
}

__global__ void k_scan1() {
    __shared__ int wsum[32];
    int t = threadIdx.x, b = blockIdx.x;
    int i = b * 1024 + t;
    int v = (i < NN) ? g_cnt_i[i] : 0;
    int incl = v;
#pragma unroll
    for (int o = 1; o < 32; o <<= 1) {
        int n = __shfl_up_sync(0xffffffffu, incl, o);
        if ((t & 31) >= o) incl += n;
    }
    if ((t & 31) == 31) wsum[t >> 5] = incl;
    __syncthreads();
    if (t < 32) {
        int wv = wsum[t];
#pragma unroll
        for (int o = 1; o < 32; o <<= 1) {
            int n = __shfl_up_sync(0xffffffffu, wv, o);
            if (t >= o) wv += n;
        }
        wsum[t] = wv;
    }
    __syncthreads();
    int excl = incl - v + ((t >= 32) ? wsum[(t >> 5) - 1] : 0);
    if (i < NN) g_rowptr[i] = excl;
    if (t == 1023) g_bsum[b] = excl + v;
}

__global__ void k_scan2() {
    __shared__ int w0s;
    int t = threadIdx.x;
    int v = (t < NB_SCAN) ? g_bsum[t] : 0;
    int incl = v;
#pragma unroll
    for (int o = 1; o < 32; o <<= 1) {
        int n = __shfl_up_sync(0xffffffffu, incl, o);
        if ((t & 31) >= o) incl += n;
    }
    if (t == 31) w0s = incl;
    __syncthreads();
    if (t >= 32) incl += w0s;
    if (t < NB_SCAN) g_boff[t] = incl - v;
}

__global__ void k_scan3() {
    int i = blockIdx.x * blockDim.x + threadIdx.x;
    if (i < NN) {
        int v = g_rowptr[i] + g_boff[i >> 10];
        g_rowptr[i] = v;
        g_cursor[i] = v;
    }
    if (i == 0) g_rowptr[NN] = EE;
}

__global__ void k_fill(const int* __restrict__ src, const int* __restrict__ dst) {
    int e = blockIdx.x * blockDim.x + threadIdx.x;
    if (e >= EE) return;
    int pos = atomicAdd(&g_cursor[dst[e]], 1);
    g_csrc[pos] = src[e];
}

// ---------------- fused GAT aggregation: warp per dst node (round-6 form) -----
__global__ void k_gat_aggr(const float* __restrict__ bias) {
    int w = (blockIdx.x * blockDim.x + threadIdx.x) >> 5;
    if (w >= NN) return;
    int lane = threadIdx.x & 31;
    int row0 = g_rowptr[w], row1 = g_rowptr[w + 1];
    float4 ad4 = reinterpret_cast<const float4*>(g_ad)[w];
    float4 as_self = reinterpret_cast<const float4*>(g_as)[w];
    int hd = lane >> 3;
    float ad_l = sel4(ad4, hd);
    float4 acc = make_float4(0.f, 0.f, 0.f, 0.f);
    float z = 0.f;
    int s = (row0 < row1) ? g_csrc[row0] : 0;
    for (int k = row0; k < row1; k++) {
        int s_next = (k + 1 < row1) ? g_csrc[k + 1] : 0;
        float4 a = reinterpret_cast<const float4*>(g_as)[s];
        float4 hv = reinterpret_cast<const float4*>(g_h)[s * 32 + lane];
        float wgt = __expf(lrelu(sel4(a, hd) + ad_l));
        z += wgt;
        acc.x = fmaf(wgt, hv.x, acc.x);
        acc.y = fmaf(wgt, hv.y, acc.y);
        acc.z = fmaf(wgt, hv.z, acc.z);
        acc.w = fmaf(wgt, hv.w, acc.w);
        s = s_next;
    }
    float wsf = __expf(lrelu(sel4(as_self, hd) + ad_l));
    z += wsf;
    float4 hs = reinterpret_cast<const float4*>(g_h)[w * 32 + lane];
    acc.x = fmaf(wsf, hs.x, acc.x);
    acc.y = fmaf(wsf, hs.y, acc.y);
    acc.z = fmaf(wsf, hs.z, acc.z);
    acc.w = fmaf(wsf, hs.w, acc.w);
    float inv = 1.f / (z + 1e-16f);
    float4 b = reinterpret_cast<const float4*>(bias)[lane];
    float4 r;
    r.x = fmaxf(acc.x * inv + b.x, 0.f);
    r.y = fmaxf(acc.y * inv + b.y, 0.f);
    r.z = fmaxf(acc.z * inv + b.z, 0.f);
    r.w = fmaxf(acc.w * inv + b.w, 0.f);
    reinterpret_cast<float4*>(g_x)[w * 32 + lane] = r;
}

// ---------------- GraphConv epilogue: Y = relu(gather(P) + Q + bias) ----------
__global__ void k_gc_final(const float* __restrict__ P, const float* __restrict__ Q,
                           const float* __restrict__ bias, float* __restrict__ Y) {
    int q = (blockIdx.x * blockDim.x + threadIdx.x) >> 3;
    if (q >= NN) return;
    int lane = threadIdx.x & 7;
    int row0 = g_rowptr[q], row1 = g_rowptr[q + 1];
    const float4* P4 = reinterpret_cast<const float4*>(P);
    float4 acc = make_float4(0.f, 0.f, 0.f, 0.f);
    int s = (row0 < row1) ? g_csrc[row0] : 0;
    for (int k = row0; k < row1; k++) {
        int s_next = (k + 1 < row1) ? g_csrc[k + 1] : 0;
        float4 p = P4[s * 8 + lane];
        acc.x += p.x; acc.y += p.y; acc.z += p.z; acc.w += p.w;
        s = s_next;
    }
    float4 qq = reinterpret_cast<const float4*>(Q)[q * 8 + lane];
    float4 bb = reinterpret_cast<const float4*>(bias)[lane];
    float4 r;
    r.x = fmaxf(acc.x + qq.x + bb.x, 0.f);
    r.y = fmaxf(acc.y + qq.y + bb.y, 0.f);
    r.z = fmaxf(acc.z + qq.z + bb.z, 0.f);
    r.w = fmaxf(acc.w + qq.w + bb.w, 0.f);
    reinterpret_cast<float4*>(Y)[q * 8 + lane] = r;
}

// ---------------- SAGE epilogue + pool: pool += relu(mean(P) + Q + bias) ------
__global__ void k_sage_final(const float* __restrict__ P, const float* __restrict__ Q,
                             const float* __restrict__ bias,
                             const int* __restrict__ batch) {
    int q = (blockIdx.x * blockDim.x + threadIdx.x) >> 3;
    if (q >= NN) return;
    int lane = threadIdx.x & 7;
    int row0 = g_rowptr[q], row1 = g_rowptr[q + 1];
    const float4* P4 = reinterpret_cast<const float4*>(P);
    float4 acc = make_float4(0.f, 0.f, 0.f, 0.f);
    int s = (row0 < row1) ? g_csrc[row0] : 0;
    for (int k = row0; k < row1; k++) {
        int s_next = (k + 1 < row1) ? g_csrc[k + 1] : 0;
        float4 p = P4[s * 8 + lane];
        acc.x += p.x; acc.y += p.y; acc.z += p.z; acc.w += p.w;
        s = s_next;
    }
    float inv = 1.f / fmaxf((float)(row1 - row0), 1.f);
    float4 qq = reinterpret_cast<const float4*>(Q)[q * 8 + lane];
    float4 bb = reinterpret_cast<const float4*>(bias)[lane];
    float4 r;
    r.x = fmaxf(fmaf(acc.x, inv, qq.x) + bb.x, 0.f);
    r.y = fmaxf(fmaf(acc.y, inv, qq.y) + bb.y, 0.f);
    r.z = fmaxf(fmaf(acc.z, inv, qq.z) + bb.z, 0.f);
    r.w = fmaxf(fmaf(acc.w, inv, qq.w) + bb.w, 0.f);
    int b = batch[q];
    atomicAdd(reinterpret_cast<float4*>(g_pool) + b * 8 + lane, r);
    if (lane == 0) atomicAdd(&g_cnt[b], 1.f);
}

// ---------------- fused dual projection: Ya = X@Wa, Yb = X@Wb ----------------
template <int FIN>
__global__ __launch_bounds__(256) void k_proj2(
    const float* __restrict__ X, const float* __restrict__ Wa,
    const float* __restrict__ Wb, float* __restrict__ Ya, float* __restrict__ Yb) {
    __shared__ float Xs[64][FIN];
    int t = threadIdx.x, tx = t & 31, ty = t >> 5;
    int row0 = blockIdx.x * 64;
    const float4* Xg = reinterpret_cast<const float4*>(X);
    for (int i = t; i < 64 * (FIN / 4); i += 256) {
        int r = i / (FIN / 4), kq = i % (FIN / 4);
        int row = row0 + r;
        float4 v = (row < NN) ? Xg[row * (FIN / 4) + kq] : make_float4(0.f, 0.f, 0.f, 0.f);
        *reinterpret_cast<float4*>(&Xs[r][kq * 4]) = v;
    }
    __syncthreads();
    float a[8], b[8];
#pragma unroll
    for (int r = 0; r < 8; r++) { a[r] = 0.f; b[r] = 0.f; }
#pragma unroll 4
    for (int k = 0; k < FIN; k++) {
        float wa = __ldg(&Wa[k * CC + tx]);
        float wb = __ldg(&Wb[k * CC + tx]);
#pragma unroll
        for (int r = 0; r < 8; r++) {
            float xv = Xs[ty * 8 + r][k];
            a[r] = fmaf(xv, wa, a[r]);
            b[r] = fmaf(xv, wb, b[r]);
        }
    }
#pragma unroll
    for (int r = 0; r < 8; r++) {
        int row = row0 + ty * 8 + r;
        if (row < NN) {
            Ya[row * CC + tx] = a[r];
            Yb[row * CC + tx] = b[r];
        }
    }
}

// ---------------- MLP head (single tiny block) -------------------------------
__global__ void k_head(const float* __restrict__ Wf1, const float* __restrict__ bf1,
                       const float* __restrict__ Wf2, const float* __restrict__ bf2,
                       float* __restrict__ out) {
    __shared__ float t1[NGR * CC];
    int t = threadIdx.x;
    for (int idx = t; idx < NGR * CC; idx += blockDim.x) {
        int g = idx >> 5, c = idx & 31;
        float inv = 1.f / fmaxf(g_cnt[g], 1.f);
        float s = 0.f;
#pragma unroll
        for (int k = 0; k < CC; k++) s = fmaf(g_pool[g * CC + k] * inv, Wf1[k * CC + c], s);
        t1[idx] = fmaxf(s + bf1[c], 0.f);
    }
    __syncthreads();
    for (int idx = t; idx < NGR * NOUT; idx += blockDim.x) {
        int g = idx / NOUT, o = idx - g * NOUT;
        float s = 0.f;
#pragma unroll
        for (int k = 0; k < CC; k++) s = fmaf(t1[g * CC + k], Wf2[k * NOUT + o], s);
        out[idx] = s + bf2[o];
    }
}

// =============================================================================
extern "C" void kernel_launch(void* const* d_in, const int* in_sizes, int n_in,
                              void* d_out, int out_size) {
    const float* x   = (const float*)d_in[0];
    const int*   ei  = (const int*)d_in[1];
    const int*   bat = (const int*)d_in[2];
    const float* W1  = (const float*)d_in[3];
    const float* as1 = (const float*)d_in[4];
    const float* ad1 = (const float*)d_in[5];
    const float* b1  = (const float*)d_in[6];
    const float* W2  = (const float*)d_in[7];
    const float* as2 = (const float*)d_in[8];
    const float* ad2 = (const float*)d_in[9];
    const float* b2  = (const float*)d_in[10];
    const float* W3r = (const float*)d_in[11];
    const float* W3l = (const float*)d_in[12];
    const float* b3  = (const float*)d_in[13];
    const float* W4l = (const float*)d_in[14];
    const float* b4l = (const float*)d_in[15];
    const float* W4r = (const float*)d_in[16];
    const float* Wf1 = (const float*)d_in[17];
    const float* bf1 = (const float*)d_in[18];
    const float* Wf2 = (const float*)d_in[19];
    const float* bf2 = (const float*)d_in[20];
    const int* src = ei;
    const int* dst = ei + EE;
    float* out = (float*)d_out;

    static float *p_h = nullptr, *p_acc, *p_x, *p_pool, *p_cnt;
    static int* p_cnt_i;
    static bool init_done = false;
    static cudaStream_t s2;
    static cudaEvent_t e1, e2;
    if (!p_h) {
        cudaGetSymbolAddress((void**)&p_h, g_h);
        cudaGetSymbolAddress((void**)&p_acc, g_acc);
        cudaGetSymbolAddress((void**)&p_x, g_x);
        cudaGetSymbolAddress((void**)&p_pool, g_pool);
        cudaGetSymbolAddress((void**)&p_cnt, g_cnt);
        cudaGetSymbolAddress((void**)&p_cnt_i, g_cnt_i);
    }
    if (!init_done) {
        cudaFuncSetAttribute(k_gemm128mma, cudaFuncAttributeMaxDynamicSharedMemorySize, SMEM_MMA);
        cudaStreamCreateWithFlags(&s2, cudaStreamNonBlocking);
        cudaEventCreateWithFlags(&e1, cudaEventDisableTiming);
        cudaEventCreateWithFlags(&e2, cudaEventDisableTiming);
        init_done = true;
    }

    const int T = 256;
    const int gE    = (EE + T - 1) / T;
    const int gWNN  = (NN * 32 + T - 1) / T;   // warp per node
    const int gQ8   = (NN * 8 + T - 1) / T;    // 8 lanes per node
    const int gR64  = (NN + 63) / 64;          // 64-row tiles
    const int gTC   = (NN + 127) / 128;        // 128-row MMA tiles

    // ---- fork: CSR build on side stream, overlapped with W prep + GEMM1 ----
    cudaEventRecord(e1, 0);
    cudaStreamWaitEvent(s2, e1, 0);
    cudaMemsetAsync(p_cnt_i, 0, NN * sizeof(int), s2);
    k_count<<<gE, T, 0, s2>>>(dst);
    k_scan1<<<NB_SCAN, 1024, 0, s2>>>();
    k_scan2<<<1, 64, 0, s2>>>();
    k_scan3<<<(NN + 1023) / 1024, 1024, 0, s2>>>();
    k_fill<<<gE, T, 0, s2>>>(src, dst);
    cudaMemsetAsync(p_pool, 0, NGR * CC * sizeof(float), s2);
    cudaMemsetAsync(p_cnt, 0, NGR * sizeof(float), s2);
    cudaEventRecord(e2, s2);

    // main stream: W prep + GAT layer-1 GEMM (independent of CSR)
    k_prepWt<<<(HC * HC + T - 1) / T, T>>>(W1, 0);
    k_prepWt<<<(HC * HC + T - 1) / T, T>>>(W2, 1);
    k_gemm128mma<<<gTC, 256, SMEM_MMA>>>(x, 0, as1, ad1);
    cudaStreamWaitEvent(0, e2, 0);     // CSR + pool-zero ready

    // ---- GAT layer 1 aggregation ----
    k_gat_aggr<<<gWNN, T>>>(b1);

    // ---- GAT layer 2 ----
    k_gemm128mma<<<gTC, 256, SMEM_MMA>>>(p_x, 1, as2, ad2);
    k_gat_aggr<<<gWNN, T>>>(b2);

    // ---- GraphConv: x3 = relu(segsum((x2@W3r)[src]) + x2@W3l + b3) ----
    k_proj2<HC><<<gR64, 256>>>(p_x, W3r, W3l, p_acc, p_h);    // Ya=g_acc, Yb=g_h
    k_gc_final<<<gQ8, T>>>(p_acc, p_h, b3, p_x);              // x3 -> g_x

    // ---- SAGEConv + pool: pool += relu(mean((x3@W4l)[src]) + x3@W4r + b4l) ----
    k_proj2<CC><<<gR64, 256>>>(p_x, W4l, W4r, p_acc, p_h);    // Ya=g_acc, Yb=g_h
    k_sage_final<<<gQ8, T>>>(p_acc, p_h, b4l, bat);           // pool atomics

    // ---- head ----
    k_head<<<1, 1024>>>(Wf1, bf1, Wf2, bf2, out);
}

// round 10
// speedup vs baseline: 1.1315x; 1.0070x over previous
#include <cuda_runtime.h>
#include <cuda_bf16.h>
#include <cuda_fp16.h>
#include <cstdint>

#define NN   50000
#define EE   800000
#define HH   4
#define CC   32
#define HC   128
#define NGR  64
#define NOUT 10
#define NB_SCAN 49   // ceil(NN/1024)
#define STR  68      // smem row stride in 32-bit words

// ---------------- scratch (device globals; no allocation allowed) ------------
__device__ float g_h[NN * HC];          // proj scratch (GraphConv/SAGE)
__device__ uint32_t g_h16[NN * 64];     // GAT h in half2 (64 words = 128 halves/row)
__device__ float g_acc[NN * HC];
__device__ float g_x[NN * HC];
__device__ float g_as[NN * HH];
__device__ float g_ad[NN * HH];
__device__ float g_pool[NGR * CC];
__device__ float g_cnt[NGR];
// CSR by destination
__device__ int g_cnt_i[NN];
__device__ int g_rowptr[NN + 1];
__device__ int g_cursor[NN];
__device__ int g_csrc[EE];
__device__ int g_bsum[NB_SCAN];
__device__ int g_boff[NB_SCAN];
// bf16-split transposed weights Wt[n][k] per GAT layer
__device__ unsigned short g_WtHi[2][HC * HC];
__device__ unsigned short g_WtLo[2][HC * HC];

__device__ __forceinline__ float lrelu(float v) { return v > 0.f ? v : 0.2f * v; }
__device__ __forceinline__ float sel4(float4 a, int hd) {
    return (hd == 0) ? a.x : (hd == 1) ? a.y : (hd == 2) ? a.z : a.w;
}
__device__ __forceinline__ uint32_t pack_h2(float a, float b) {
    __half2 h = __floats2half2_rn(a, b);
    return *reinterpret_cast<uint32_t*>(&h);
}

// ---------------- W -> bf16 hi/lo transposed prep ----------------------------
__global__ void k_prepWt(const float* __restrict__ W, int layer) {
    int i = blockIdx.x * blockDim.x + threadIdx.x;  // i = k*128 + n
    if (i >= HC * HC) return;
    int k = i >> 7, n = i & 127;
    float w = W[i];
    __nv_bfloat16 hb = __float2bfloat16(w);
    __nv_bfloat16 lb = __float2bfloat16(w - __bfloat162float(hb));
    g_WtHi[layer][n * HC + k] = __bfloat16_as_ushort(hb);
    g_WtLo[layer][n * HC + k] = __bfloat16_as_ushort(lb);
}

// ---------------- mma.sync bf16-split GEMM128 + attention epilogue -----------
#define MMA_BF16(c, A0, A1, A2, A3, B0, B1) \
    asm volatile("mma.sync.aligned.m16n8k16.row.col.f32.bf16.bf16.f32 " \
        "{%0,%1,%2,%3}, {%4,%5,%6,%7}, {%8,%9}, {%0,%1,%2,%3};" \
        : "+f"((c)[0]), "+f"((c)[1]), "+f"((c)[2]), "+f"((c)[3]) \
        : "r"(A0), "r"(A1), "r"(A2), "r"(A3), "r"(B0), "r"(B1))

#define SMEM_MMA (4 * 128 * STR * 4 + 1024)

__global__ __launch_bounds__(256, 1) void k_gemm128mma(
    const float* __restrict__ X, int layer,
    const float* __restrict__ aws, const float* __restrict__ awd) {
    extern __shared__ __align__(16) char smem[];
    uint32_t* xh = reinterpret_cast<uint32_t*>(smem);
    uint32_t* xl = xh + 128 * STR;
    uint32_t* wh = xl + 128 * STR;
    uint32_t* wl = wh + 128 * STR;
    float* sws = reinterpret_cast<float*>(wl + 128 * STR);
    float* swd = sws + 128;
    int tid = threadIdx.x, lane = tid & 31, wid = tid >> 5;
    int gid = lane >> 2, tg = lane & 3;
    int row0 = blockIdx.x * 128;

    if (tid < 128) { sws[tid] = aws[tid]; swd[tid] = awd[tid]; }
    {
        const uint32_t* gh = reinterpret_cast<const uint32_t*>(g_WtHi[layer]);
        const uint32_t* gl = reinterpret_cast<const uint32_t*>(g_WtLo[layer]);
        for (int i = tid; i < 128 * 64; i += 256) {
            int r = i >> 6, w = i & 63;
            wh[r * STR + w] = gh[i];
            wl[r * STR + w] = gl[i];
        }
    }
    {
        const float4* X4 = reinterpret_cast<const float4*>(X);
        for (int i = tid; i < 128 * 32; i += 256) {
            int r = i >> 5, q = i & 31;
            int grow = row0 + r;
            float4 v = (grow < NN) ? X4[(size_t)grow * 32 + q] : make_float4(0.f, 0.f, 0.f, 0.f);
            float vv[4] = {v.x, v.y, v.z, v.w};
#pragma unroll
            for (int q2 = 0; q2 < 2; q2++) {
                __nv_bfloat16 h0 = __float2bfloat16(vv[2 * q2]);
                __nv_bfloat16 h1 = __float2bfloat16(vv[2 * q2 + 1]);
                __nv_bfloat16 l0 = __float2bfloat16(vv[2 * q2] - __bfloat162float(h0));
                __nv_bfloat16 l1 = __float2bfloat16(vv[2 * q2 + 1] - __bfloat162float(h1));
                xh[r * STR + 2 * q + q2] =
                    ((uint32_t)__bfloat16_as_ushort(h1) << 16) | __bfloat16_as_ushort(h0);
                xl[r * STR + 2 * q + q2] =
                    ((uint32_t)__bfloat16_as_ushort(l1) << 16) | __bfloat16_as_ushort(l0);
            }
        }
    }
    __syncthreads();

    float acc[16][4];
#pragma unroll
    for (int t = 0; t < 16; t++)
#pragma unroll
        for (int j = 0; j < 4; j++) acc[t][j] = 0.f;

    int m0 = wid * 16;
    const uint32_t* xrh = xh + (m0 + gid) * STR + tg;
    const uint32_t* xrl = xl + (m0 + gid) * STR + tg;
#pragma unroll 1
    for (int kk = 0; kk < 8; kk++) {
        int kw = kk * 8;
        uint32_t ah0 = xrh[kw],           ah2 = xrh[kw + 4];
        uint32_t ah1 = xrh[kw + 8 * STR], ah3 = xrh[kw + 8 * STR + 4];
        uint32_t al0 = xrl[kw],           al2 = xrl[kw + 4];
        uint32_t al1 = xrl[kw + 8 * STR], al3 = xrl[kw + 8 * STR + 4];
#pragma unroll
        for (int t = 0; t < 16; t++) {
            const uint32_t* wrh = wh + (t * 8 + gid) * STR + kw + tg;
            const uint32_t* wrl = wl + (t * 8 + gid) * STR + kw + tg;
            uint32_t bh0 = wrh[0], bh1 = wrh[4];
            uint32_t bl0 = wrl[0], bl1 = wrl[4];
            MMA_BF16(acc[t], ah0, ah1, ah2, ah3, bh0, bh1);
            MMA_BF16(acc[t], ah0, ah1, ah2, ah3, bl0, bl1);
            MMA_BF16(acc[t], al0, al1, al2, al3, bh0, bh1);
        }
    }

    // epilogue: store h rows as half2 + attention logits
    int r0 = row0 + m0 + gid, r1 = r0 + 8;
#pragma unroll
    for (int t = 0; t < 16; t++) {
        int cidx = t * 4 + tg;   // half2-word column (of 64)
        if (r0 < NN) g_h16[(size_t)r0 * 64 + cidx] = pack_h2(acc[t][0], acc[t][1]);
        if (r1 < NN) g_h16[(size_t)r1 * 64 + cidx] = pack_h2(acc[t][2], acc[t][3]);
    }
#pragma unroll
    for (int h = 0; h < 4; h++) {
        float ps0 = 0.f, pd0 = 0.f, ps1 = 0.f, pd1 = 0.f;
#pragma unroll
        for (int j = 0; j < 4; j++) {
            int t = 4 * h + j;
            int col = t * 8 + 2 * tg;
            float w0 = sws[col], w1 = sws[col + 1];
            float v0 = swd[col], v1 = swd[col + 1];
            ps0 = fmaf(acc[t][0], w0, fmaf(acc[t][1], w1, ps0));
            pd0 = fmaf(acc[t][0], v0, fmaf(acc[t][1], v1, pd0));
            ps1 = fmaf(acc[t][2], w0, fmaf(acc[t][3], w1, ps1));
            pd1 = fmaf(acc[t][2], v0, fmaf(acc[t][3], v1, pd1));
        }
#pragma unroll
        for (int o = 1; o <= 2; o <<= 1) {
            ps0 += __shfl_xor_sync(0xffffffffu, ps0, o);
            pd0 += __shfl_xor_sync(0xffffffffu, pd0, o);
            ps1 += __shfl_xor_sync(0xffffffffu, ps1, o);
            pd1 += __shfl_xor_sync(0xffffffffu, pd1, o);
        }
        if (tg == 0) {
            if (r0 < NN) { g_as[r0 * HH + h] = ps0; g_ad[r0 * HH + h] = pd0; }
            if (r1 < NN) { g_as[r1 * HH + h] = ps1; g_ad[r1 * HH + h] = pd1; }
        }
    }
}

// ---------------- CSR build ---------------------------------------------------
__global__ void k_count(const int* __restrict__ dst) {
    int e = blockIdx.x * blockDim.x + threadIdx.x;
    if (e < EE) atomicAdd(&g_cnt_i[dst[e]], 1);
}

__global__ void k_scan1() {
    __shared__ int wsum[32];
    int t = threadIdx.x, b = blockIdx.x;
    int i = b * 1024 + t;
    int v = (i < NN) ? g_cnt_i[i] : 0;
    int incl = v;
#pragma unroll
    for (int o = 1; o < 32; o <<= 1) {
        int n = __shfl_up_sync(0xffffffffu, incl, o);
        if ((t & 31) >= o) incl += n;
    }
    if ((t & 31) == 31) wsum[t >> 5] = incl;
    __syncthreads();
    if (t < 32) {
        int wv = wsum[t];
#pragma unroll
        for (int o = 1; o < 32; o <<= 1) {
            int n = __shfl_up_sync(0xffffffffu, wv, o);
            if (t >= o) wv += n;
        }
        wsum[t] = wv;
    }
    __syncthreads();
    int excl = incl - v + ((t >= 32) ? wsum[(t >> 5) - 1] : 0);
    if (i < NN) g_rowptr[i] = excl;
    if (t == 1023) g_bsum[b] = excl + v;
}

__global__ void k_scan2() {
    __shared__ int w0s;
    int t = threadIdx.x;
    int v = (t < NB_SCAN) ? g_bsum[t] : 0;
    int incl = v;
#pragma unroll
    for (int o = 1; o < 32; o <<= 1) {
        int n = __shfl_up_sync(0xffffffffu, incl, o);
        if ((t & 31) >= o) incl += n;
    }
    if (t == 31) w0s = incl;
    __syncthreads();
    if (t >= 32) incl += w0s;
    if (t < NB_SCAN) g_boff[t] = incl - v;
}

__global__ void k_scan3() {
    int i = blockIdx.x * blockDim.x + threadIdx.x;
    if (i < NN) {
        int v = g_rowptr[i] + g_boff[i >> 10];
        g_rowptr[i] = v;
        g_cursor[i] = v;
    }
    if (i == 0) g_rowptr[NN] = EE;
}

__global__ void k_fill(const int* __restrict__ src, const int* __restrict__ dst) {
    int e = blockIdx.x * blockDim.x + threadIdx.x;
    if (e >= EE) return;
    int pos = atomicAdd(&g_cursor[dst[e]], 1);
    g_csrc[pos] = src[e];
}

// ---------------- fused GAT aggregation: warp per dst node, fp16 h gather -----
__global__ void k_gat_aggr(const float* __restrict__ bias) {
    int w = (blockIdx.x * blockDim.x + threadIdx.x) >> 5;
    if (w >= NN) return;
    int lane = threadIdx.x & 31;
    int row0 = g_rowptr[w], row1 = g_rowptr[w + 1];
    float4 ad4 = reinterpret_cast<const float4*>(g_ad)[w];
    float4 as_self = reinterpret_cast<const float4*>(g_as)[w];
    int hd = lane >> 3;
    float ad_l = sel4(ad4, hd);
    const uint2* HV = reinterpret_cast<const uint2*>(g_h16);
    float4 acc = make_float4(0.f, 0.f, 0.f, 0.f);
    float z = 0.f;
    int s = (row0 < row1) ? g_csrc[row0] : 0;
    for (int k = row0; k < row1; k++) {
        int s_next = (k + 1 < row1) ? g_csrc[k + 1] : 0;
        float4 a = reinterpret_cast<const float4*>(g_as)[s];
        uint2 hw = HV[s * 32 + lane];
        float wgt = __expf(lrelu(sel4(a, hd) + ad_l));
        float2 f01 = __half22float2(*reinterpret_cast<__half2*>(&hw.x));
        float2 f23 = __half22float2(*reinterpret_cast<__half2*>(&hw.y));
        z += wgt;
        acc.x = fmaf(wgt, f01.x, acc.x);
        acc.y = fmaf(wgt, f01.y, acc.y);
        acc.z = fmaf(wgt, f23.x, acc.z);
        acc.w = fmaf(wgt, f23.y, acc.w);
        s = s_next;
    }
    float wsf = __expf(lrelu(sel4(as_self, hd) + ad_l));
    z += wsf;
    uint2 hw = HV[w * 32 + lane];
    float2 s01 = __half22float2(*reinterpret_cast<__half2*>(&hw.x));
    float2 s23 = __half22float2(*reinterpret_cast<__half2*>(&hw.y));
    acc.x = fmaf(wsf, s01.x, acc.x);
    acc.y = fmaf(wsf, s01.y, acc.y);
    acc.z = fmaf(wsf, s23.x, acc.z);
    acc.w = fmaf(wsf, s23.y, acc.w);
    float inv = 1.f / (z + 1e-16f);
    float4 b = reinterpret_cast<const float4*>(bias)[lane];
    float4 r;
    r.x = fmaxf(acc.x * inv + b.x, 0.f);
    r.y = fmaxf(acc.y * inv + b.y, 0.f);
    r.z = fmaxf(acc.z * inv + b.z, 0.f);
    r.w = fmaxf(acc.w * inv + b.w, 0.f);
    reinterpret_cast<float4*>(g_x)[w * 32 + lane] = r;
}

// ---------------- GraphConv epilogue: Y = relu(gather(P) + Q + bias) ----------
__global__ void k_gc_final(const float* __restrict__ P, const float* __restrict__ Q,
                           const float* __restrict__ bias, float* __restrict__ Y) {
    int q = (blockIdx.x * blockDim.x + threadIdx.x) >> 3;
    if (q >= NN) return;
    int lane = threadIdx.x & 7;
    int row0 = g_rowptr[q], row1 = g_rowptr[q + 1];
    const float4* P4 = reinterpret_cast<const float4*>(P);
    float4 acc = make_float4(0.f, 0.f, 0.f, 0.f);
    int s = (row0 < row1) ? g_csrc[row0] : 0;
    for (int k = row0; k < row1; k++) {
        int s_next = (k + 1 < row1) ? g_csrc[k + 1] : 0;
        float4 p = P4[s * 8 + lane];
        acc.x += p.x; acc.y += p.y; acc.z += p.z; acc.w += p.w;
        s = s_next;
    }
    float4 qq = reinterpret_cast<const float4*>(Q)[q * 8 + lane];
    float4 bb = reinterpret_cast<const float4*>(bias)[lane];
    float4 r;
    r.x = fmaxf(acc.x + qq.x + bb.x, 0.f);
    r.y = fmaxf(acc.y + qq.y + bb.y, 0.f);
    r.z = fmaxf(acc.z + qq.z + bb.z, 0.f);
    r.w = fmaxf(acc.w + qq.w + bb.w, 0.f);
    reinterpret_cast<float4*>(Y)[q * 8 + lane] = r;
}

// ---------------- SAGE epilogue + pool: pool += relu(mean(P) + Q + bias) ------
__global__ void k_sage_final(const float* __restrict__ P, const float* __restrict__ Q,
                             const float* __restrict__ bias,
                             const int* __restrict__ batch) {
    int q = (blockIdx.x * blockDim.x + threadIdx.x) >> 3;
    if (q >= NN) return;
    int lane = threadIdx.x & 7;
    int row0 = g_rowptr[q], row1 = g_rowptr[q + 1];
    const float4* P4 = reinterpret_cast<const float4*>(P);
    float4 acc = make_float4(0.f, 0.f, 0.f, 0.f);
    int s = (row0 < row1) ? g_csrc[row0] : 0;
    for (int k = row0; k < row1; k++) {
        int s_next = (k + 1 < row1) ? g_csrc[k + 1] : 0;
        float4 p = P4[s * 8 + lane];
        acc.x += p.x; acc.y += p.y; acc.z += p.z; acc.w += p.w;
        s = s_next;
    }
    float inv = 1.f / fmaxf((float)(row1 - row0), 1.f);
    float4 qq = reinterpret_cast<const float4*>(Q)[q * 8 + lane];
    float4 bb = reinterpret_cast<const float4*>(bias)[lane];
    float4 r;
    r.x = fmaxf(fmaf(acc.x, inv, qq.x) + bb.x, 0.f);
    r.y = fmaxf(fmaf(acc.y, inv, qq.y) + bb.y, 0.f);
    r.z = fmaxf(fmaf(acc.z, inv, qq.z) + bb.z, 0.f);
    r.w = fmaxf(fmaf(acc.w, inv, qq.w) + bb.w, 0.f);
    int b = batch[q];
    atomicAdd(reinterpret_cast<float4*>(g_pool) + b * 8 + lane, r);
    if (lane == 0) atomicAdd(&g_cnt[b], 1.f);
}

// ---------------- fused dual projection: Ya = X@Wa, Yb = X@Wb ----------------
template <int FIN>
__global__ __launch_bounds__(256) void k_proj2(
    const float* __restrict__ X, const float* __restrict__ Wa,
    const float* __restrict__ Wb, float* __restrict__ Ya, float* __restrict__ Yb) {
    __shared__ float Xs[64][FIN];
    int t = threadIdx.x, tx = t & 31, ty = t >> 5;
    int row0 = blockIdx.x * 64;
    const float4* Xg = reinterpret_cast<const float4*>(X);
    for (int i = t; i < 64 * (FIN / 4); i += 256) {
        int r = i / (FIN / 4), kq = i % (FIN / 4);
        int row = row0 + r;
        float4 v = (row < NN) ? Xg[row * (FIN / 4) + kq] : make_float4(0.f, 0.f, 0.f, 0.f);
        *reinterpret_cast<float4*>(&Xs[r][kq * 4]) = v;
    }
    __syncthreads();
    float a[8], b[8];
#pragma unroll
    for (int r = 0; r < 8; r++) { a[r] = 0.f; b[r] = 0.f; }
#pragma unroll 4
    for (int k = 0; k < FIN; k++) {
        float wa = __ldg(&Wa[k * CC + tx]);
        float wb = __ldg(&Wb[k * CC + tx]);
#pragma unroll
        for (int r = 0; r < 8; r++) {
            float xv = Xs[ty * 8 + r][k];
            a[r] = fmaf(xv, wa, a[r]);
            b[r] = fmaf(xv, wb, b[r]);
        }
    }
#pragma unroll
    for (int r = 0; r < 8; r++) {
        int row = row0 + ty * 8 + r;
        if (row < NN) {
            Ya[row * CC + tx] = a[r];
            Yb[row * CC + tx] = b[r];
        }
    }
}

// ---------------- MLP head (single tiny block) -------------------------------
__global__ void k_head(const float* __restrict__ Wf1, const float* __restrict__ bf1,
                       const float* __restrict__ Wf2, const float* __restrict__ bf2,
                       float* __restrict__ out) {
    __shared__ float t1[NGR * CC];
    int t = threadIdx.x;
    for (int idx = t; idx < NGR * CC; idx += blockDim.x) {
        int g = idx >> 5, c = idx & 31;
        float inv = 1.f / fmaxf(g_cnt[g], 1.f);
        float s = 0.f;
#pragma unroll
        for (int k = 0; k < CC; k++) s = fmaf(g_pool[g * CC + k] * inv, Wf1[k * CC + c], s);
        t1[idx] = fmaxf(s + bf1[c], 0.f);
    }
    __syncthreads();
    for (int idx = t; idx < NGR * NOUT; idx += blockDim.x) {
        int g = idx / NOUT, o = idx - g * NOUT;
        float s = 0.f;
#pragma unroll
        for (int k = 0; k < CC; k++) s = fmaf(t1[g * CC + k], Wf2[k * NOUT + o], s);
        out[idx] = s + bf2[o];
    }
}

// =============================================================================
extern "C" void kernel_launch(void* const* d_in, const int* in_sizes, int n_in,
                              void* d_out, int out_size) {
    const float* x   = (const float*)d_in[0];
    const int*   ei  = (const int*)d_in[1];
    const int*   bat = (const int*)d_in[2];
    const float* W1  = (const float*)d_in[3];
    const float* as1 = (const float*)d_in[4];
    const float* ad1 = (const float*)d_in[5];
    const float* b1  = (const float*)d_in[6];
    const float* W2  = (const float*)d_in[7];
    const float* as2 = (const float*)d_in[8];
    const float* ad2 = (const float*)d_in[9];
    const float* b2  = (const float*)d_in[10];
    const float* W3r = (const float*)d_in[11];
    const float* W3l = (const float*)d_in[12];
    const float* b3  = (const float*)d_in[13];
    const float* W4l = (const float*)d_in[14];
    const float* b4l = (const float*)d_in[15];
    const float* W4r = (const float*)d_in[16];
    const float* Wf1 = (const float*)d_in[17];
    const float* bf1 = (const float*)d_in[18];
    const float* Wf2 = (const float*)d_in[19];
    const float* bf2 = (const float*)d_in[20];
    const int* src = ei;
    const int* dst = ei + EE;
    float* out = (float*)d_out;

    static float *p_h = nullptr, *p_acc, *p_x, *p_pool, *p_cnt;
    static int* p_cnt_i;
    static bool init_done = false;
    static cudaStream_t s2;
    static cudaEvent_t e1, e2;
    if (!p_h) {
        cudaGetSymbolAddress((void**)&p_h, g_h);
        cudaGetSymbolAddress((void**)&p_acc, g_acc);
        cudaGetSymbolAddress((void**)&p_x, g_x);
        cudaGetSymbolAddress((void**)&p_pool, g_pool);
        cudaGetSymbolAddress((void**)&p_cnt, g_cnt);
        cudaGetSymbolAddress((void**)&p_cnt_i, g_cnt_i);
    }
    if (!init_done) {
        cudaFuncSetAttribute(k_gemm128mma, cudaFuncAttributeMaxDynamicSharedMemorySize, SMEM_MMA);
        cudaStreamCreateWithFlags(&s2, cudaStreamNonBlocking);
        cudaEventCreateWithFlags(&e1, cudaEventDisableTiming);
        cudaEventCreateWithFlags(&e2, cudaEventDisableTiming);
        init_done = true;
    }

    const int T = 256;
    const int gE    = (EE + T - 1) / T;
    const int gWNN  = (NN * 32 + T - 1) / T;   // warp per node
    const int gQ8   = (NN * 8 + T - 1) / T;    // 8 lanes per node
    const int gR64  = (NN + 63) / 64;          // 64-row tiles
    const int gTC   = (NN + 127) / 128;        // 128-row MMA tiles

    // ---- fork: CSR build on side stream, overlapped with W prep + GEMM1 ----
    cudaEventRecord(e1, 0);
    cudaStreamWaitEvent(s2, e1, 0);
    cudaMemsetAsync(p_cnt_i, 0, NN * sizeof(int), s2);
    k_count<<<gE, T, 0, s2>>>(dst);
    k_scan1<<<NB_SCAN, 1024, 0, s2>>>();
    k_scan2<<<1, 64, 0, s2>>>();
    k_scan3<<<(NN + 1023) / 1024, 1024, 0, s2>>>();
    k_fill<<<gE, T, 0, s2>>>(src, dst);
    cudaMemsetAsync(p_pool, 0, NGR * CC * sizeof(float), s2);
    cudaMemsetAsync(p_cnt, 0, NGR * sizeof(float), s2);
    cudaEventRecord(e2, s2);

    // main stream: W prep + GAT layer-1 GEMM (independent of CSR)
    k_prepWt<<<(HC * HC + T - 1) / T, T>>>(W1, 0);
    k_prepWt<<<(HC * HC + T - 1) / T, T>>>(W2, 1);
    k_gemm128mma<<<gTC, 256, SMEM_MMA>>>(x, 0, as1, ad1);
    cudaStreamWaitEvent(0, e2, 0);     // CSR + pool-zero ready

    // ---- GAT layer 1 aggregation ----
    k_gat_aggr<<<gWNN, T>>>(b1);

    // ---- GAT layer 2 ----
    k_gemm128mma<<<gTC, 256, SMEM_MMA>>>(p_x, 1, as2, ad2);
    k_gat_aggr<<<gWNN, T>>>(b2);

    // ---- GraphConv: x3 = relu(segsum((x2@W3r)[src]) + x2@W3l + b3) ----
    k_proj2<HC><<<gR64, 256>>>(p_x, W3r, W3l, p_acc, p_h);    // Ya=g_acc, Yb=g_h
    k_gc_final<<<gQ8, T>>>(p_acc, p_h, b3, p_x);              // x3 -> g_x

    // ---- SAGEConv + pool: pool += relu(mean((x3@W4l)[src]) + x3@W4r + b4l) ----
    k_proj2<CC><<<gR64, 256>>>(p_x, W4l, W4r, p_acc, p_h);    // Ya=g_acc, Yb=g_h
    k_sage_final<<<gQ8, T>>>(p_acc, p_h, b4l, bat);           // pool atomics

    // ---- head ----
    k_head<<<1, 1024>>>(Wf1, bf1, Wf2, bf2, out);
}

// round 11
// speedup vs baseline: 1.2000x; 1.0605x over previous
#include <cuda_runtime.h>
#include <cuda_bf16.h>
#include <cuda_fp16.h>
#include <cstdint>

#define NN   50000
#define EE   800000
#define HH   4
#define CC   32
#define HC   128
#define NGR  64
#define NOUT 10
#define NB_SCAN 49   // ceil(NN/1024)
#define STR  68      // smem row stride in 32-bit words

// ---------------- scratch (device globals; no allocation allowed) ------------
__device__ float g_h[NN * HC];          // proj scratch (GraphConv/SAGE)
__device__ uint32_t g_h16[NN * 64];     // GAT h in half2 (64 words = 128 halves/row)
__device__ float g_acc[NN * HC];
__device__ float g_x[NN * HC];
__device__ float g_as[NN * HH];
__device__ float g_ad[NN * HH];
__device__ float g_pool[NGR * CC];
__device__ float g_cnt[NGR];
// CSR by destination
__device__ int g_cnt_i[NN];
__device__ int g_rowptr[NN + 1];
__device__ int g_cursor[NN];
__device__ int g_csrc[EE];
__device__ int g_bsum[NB_SCAN];
__device__ int g_boff[NB_SCAN];
// bf16-split transposed weights Wt[n][k] per GAT layer
__device__ unsigned short g_WtHi[2][HC * HC];
__device__ unsigned short g_WtLo[2][HC * HC];

__device__ __forceinline__ float lrelu(float v) { return v > 0.f ? v : 0.2f * v; }
__device__ __forceinline__ float sel4(float4 a, int hd) {
    return (hd == 0) ? a.x : (hd == 1) ? a.y : (hd == 2) ? a.z : a.w;
}
__device__ __forceinline__ uint32_t pack_h2(float a, float b) {
    __half2 h = __floats2half2_rn(a, b);
    return *reinterpret_cast<uint32_t*>(&h);
}

// ---------------- W -> bf16 hi/lo transposed prep (both layers) ---------------
__global__ void k_prepWt2(const float* __restrict__ W1, const float* __restrict__ W2) {
    int i = blockIdx.x * blockDim.x + threadIdx.x;  // i = k*128 + n
    if (i >= HC * HC) return;
    int layer = blockIdx.y;
    const float* W = layer ? W2 : W1;
    int k = i >> 7, n = i & 127;
    float w = W[i];
    __nv_bfloat16 hb = __float2bfloat16(w);
    __nv_bfloat16 lb = __float2bfloat16(w - __bfloat162float(hb));
    g_WtHi[layer][n * HC + k] = __bfloat16_as_ushort(hb);
    g_WtLo[layer][n * HC + k] = __bfloat16_as_ushort(lb);
}

// ---------------- mma.sync bf16-split GEMM (64-row tiles, occ 2) --------------
#define MMA_BF16(c, A0, A1, A2, A3, B0, B1) \
    asm volatile("mma.sync.aligned.m16n8k16.row.col.f32.bf16.bf16.f32 " \
        "{%0,%1,%2,%3}, {%4,%5,%6,%7}, {%8,%9}, {%0,%1,%2,%3};" \
        : "+f"((c)[0]), "+f"((c)[1]), "+f"((c)[2]), "+f"((c)[3]) \
        : "r"(A0), "r"(A1), "r"(A2), "r"(A3), "r"(B0), "r"(B1))

// smem: xh 64*STR | xl 64*STR | wh 128*STR | wl 128*STR | sws 128f | swd 128f
#define SMEM_MMA ((2 * 64 + 2 * 128) * STR * 4 + 1024)

__global__ __launch_bounds__(256, 2) void k_gemm128mma(
    const float* __restrict__ X, int layer,
    const float* __restrict__ aws, const float* __restrict__ awd) {
    extern __shared__ __align__(16) char smem[];
    uint32_t* xh = reinterpret_cast<uint32_t*>(smem);
    uint32_t* xl = xh + 64 * STR;
    uint32_t* wh = xl + 64 * STR;
    uint32_t* wl = wh + 128 * STR;
    float* sws = reinterpret_cast<float*>(wl + 128 * STR);
    float* swd = sws + 128;
    int tid = threadIdx.x, lane = tid & 31, wid = tid >> 5;
    int gid = lane >> 2, tg = lane & 3;
    int row0 = blockIdx.x * 64;

    if (tid < 128) { sws[tid] = aws[tid]; swd[tid] = awd[tid]; }
    // W images -> smem, uint4 (row stride 68 words = 17 uint4)
    {
        const uint4* gh4 = reinterpret_cast<const uint4*>(g_WtHi[layer]);
        const uint4* gl4 = reinterpret_cast<const uint4*>(g_WtLo[layer]);
        uint4* wh4 = reinterpret_cast<uint4*>(wh);
        uint4* wl4 = reinterpret_cast<uint4*>(wl);
        for (int i = tid; i < 128 * 16; i += 256) {
            int r = i >> 4, q = i & 15;
            wh4[r * 17 + q] = gh4[i];
            wl4[r * 17 + q] = gl4[i];
        }
    }
    // X tile (64 rows) -> bf16 hi/lo packed words
    {
        const float4* X4 = reinterpret_cast<const float4*>(X);
        for (int i = tid; i < 64 * 32; i += 256) {
            int r = i >> 5, q = i & 31;
            int grow = row0 + r;
            float4 v = (grow < NN) ? X4[(size_t)grow * 32 + q] : make_float4(0.f, 0.f, 0.f, 0.f);
            float vv[4] = {v.x, v.y, v.z, v.w};
#pragma unroll
            for (int q2 = 0; q2 < 2; q2++) {
                __nv_bfloat16 h0 = __float2bfloat16(vv[2 * q2]);
                __nv_bfloat16 h1 = __float2bfloat16(vv[2 * q2 + 1]);
                __nv_bfloat16 l0 = __float2bfloat16(vv[2 * q2] - __bfloat162float(h0));
                __nv_bfloat16 l1 = __float2bfloat16(vv[2 * q2 + 1] - __bfloat162float(h1));
                xh[r * STR + 2 * q + q2] =
                    ((uint32_t)__bfloat16_as_ushort(h1) << 16) | __bfloat16_as_ushort(h0);
                xl[r * STR + 2 * q + q2] =
                    ((uint32_t)__bfloat16_as_ushort(l1) << 16) | __bfloat16_as_ushort(l0);
            }
        }
    }
    __syncthreads();

    // warp tiling: rows (wid&3)*16..+15, cols (wid>>2)*64..+63
    int warpM = (wid & 3) * 16;
    int n0 = (wid >> 2) * 64;
    float acc[8][4];
#pragma unroll
    for (int t = 0; t < 8; t++)
#pragma unroll
        for (int j = 0; j < 4; j++) acc[t][j] = 0.f;

    const uint32_t* xrh = xh + (warpM + gid) * STR + tg;
    const uint32_t* xrl = xl + (warpM + gid) * STR + tg;
#pragma unroll 1
    for (int kk = 0; kk < 8; kk++) {
        int kw = kk * 8;
        uint32_t ah0 = xrh[kw],           ah2 = xrh[kw + 4];
        uint32_t ah1 = xrh[kw + 8 * STR], ah3 = xrh[kw + 8 * STR + 4];
        uint32_t al0 = xrl[kw],           al2 = xrl[kw + 4];
        uint32_t al1 = xrl[kw + 8 * STR], al3 = xrl[kw + 8 * STR + 4];
#pragma unroll
        for (int t = 0; t < 8; t++) {
            const uint32_t* wrh = wh + (n0 + t * 8 + gid) * STR + kw + tg;
            const uint32_t* wrl = wl + (n0 + t * 8 + gid) * STR + kw + tg;
            uint32_t bh0 = wrh[0], bh1 = wrh[4];
            uint32_t bl0 = wrl[0], bl1 = wrl[4];
            MMA_BF16(acc[t], ah0, ah1, ah2, ah3, bh0, bh1);
            MMA_BF16(acc[t], ah0, ah1, ah2, ah3, bl0, bl1);
            MMA_BF16(acc[t], al0, al1, al2, al3, bh0, bh1);
        }
    }

    // epilogue: store h rows as half2 + attention logits (this warp: 2 heads)
    int r0 = row0 + warpM + gid, r1 = r0 + 8;
#pragma unroll
    for (int t = 0; t < 8; t++) {
        int cidx = (n0 >> 1) + t * 4 + tg;   // half2-word column (of 64)
        if (r0 < NN) g_h16[(size_t)r0 * 64 + cidx] = pack_h2(acc[t][0], acc[t][1]);
        if (r1 < NN) g_h16[(size_t)r1 * 64 + cidx] = pack_h2(acc[t][2], acc[t][3]);
    }
#pragma unroll
    for (int hh = 0; hh < 2; hh++) {
        int h = (n0 >> 5) + hh;
        float ps0 = 0.f, pd0 = 0.f, ps1 = 0.f, pd1 = 0.f;
#pragma unroll
        for (int j = 0; j < 4; j++) {
            int t = hh * 4 + j;
            int col = n0 + t * 8 + 2 * tg;
            float w0 = sws[col], w1 = sws[col + 1];
            float v0 = swd[col], v1 = swd[col + 1];
            ps0 = fmaf(acc[t][0], w0, fmaf(acc[t][1], w1, ps0));
            pd0 = fmaf(acc[t][0], v0, fmaf(acc[t][1], v1, pd0));
            ps1 = fmaf(acc[t][2], w0, fmaf(acc[t][3], w1, ps1));
            pd1 = fmaf(acc[t][2], v0, fmaf(acc[t][3], v1, pd1));
        }
#pragma unroll
        for (int o = 1; o <= 2; o <<= 1) {
            ps0 += __shfl_xor_sync(0xffffffffu, ps0, o);
            pd0 += __shfl_xor_sync(0xffffffffu, pd0, o);
            ps1 += __shfl_xor_sync(0xffffffffu, ps1, o);
            pd1 += __shfl_xor_sync(0xffffffffu, pd1, o);
        }
        if (tg == 0) {
            if (r0 < NN) { g_as[r0 * HH + h] = ps0; g_ad[r0 * HH + h] = pd0; }
            if (r1 < NN) { g_as[r1 * HH + h] = ps1; g_ad[r1 * HH + h] = pd1; }
        }
    }
}

// ---------------- CSR build ---------------------------------------------------
__global__ void k_count(const int* __restrict__ dst) {
    int e = blockIdx.x * blockDim.x + threadIdx.x;
    if (e < EE) atomicAdd(&g_cnt_i[dst[e]], 1);
}

__global__ void k_scan1() {
    __shared__ int wsum[32];
    int t = threadIdx.x, b = blockIdx.x;
    int i = b * 1024 + t;
    int v = (i < NN) ? g_cnt_i[i] : 0;
    int incl = v;
#pragma unroll
    for (int o = 1; o < 32; o <<= 1) {
        int n = __shfl_up_sync(0xffffffffu, incl, o);
        if ((t & 31) >= o) incl += n;
    }
    if ((t & 31) == 31) wsum[t >> 5] = incl;
    __syncthreads();
    if (t < 32) {
        int wv = wsum[t];
#pragma unroll
        for (int o = 1; o < 32; o <<= 1) {
            int n = __shfl_up_sync(0xffffffffu, wv, o);
            if (t >= o) wv += n;
        }
        wsum[t] = wv;
    }
    __syncthreads();
    int excl = incl - v + ((t >= 32) ? wsum[(t >> 5) - 1] : 0);
    if (i < NN) g_rowptr[i] = excl;
    if (t == 1023) g_bsum[b] = excl + v;
}

__global__ void k_scan2() {
    __shared__ int w0s;
    int t = threadIdx.x;
    int v = (t < NB_SCAN) ? g_bsum[t] : 0;
    int incl = v;
#pragma unroll
    for (int o = 1; o < 32; o <<= 1) {
        int n = __shfl_up_sync(0xffffffffu, incl, o);
        if ((t & 31) >= o) incl += n;
    }
    if (t == 31) w0s = incl;
    __syncthreads();
    if (t >= 32) incl += w0s;
    if (t < NB_SCAN) g_boff[t] = incl - v;
}

__global__ void k_scan3() {
    int i = blockIdx.x * blockDim.x + threadIdx.x;
    if (i < NN) {
        int v = g_rowptr[i] + g_boff[i >> 10];
        g_rowptr[i] = v;
        g_cursor[i] = v;
    }
    if (i == 0) g_rowptr[NN] = EE;
}

__global__ void k_fill(const int* __restrict__ src, const int* __restrict__ dst) {
    int e = blockIdx.x * blockDim.x + threadIdx.x;
    if (e >= EE) return;
    int pos = atomicAdd(&g_cursor[dst[e]], 1);
    g_csrc[pos] = src[e];
}

// ---------------- fused GAT aggregation: warp per dst node, fp16 h gather -----
__global__ void k_gat_aggr(const float* __restrict__ bias) {
    int w = (blockIdx.x * blockDim.x + threadIdx.x) >> 5;
    if (w >= NN) return;
    int lane = threadIdx.x & 31;
    int row0 = g_rowptr[w], row1 = g_rowptr[w + 1];
    float4 ad4 = reinterpret_cast<const float4*>(g_ad)[w];
    float4 as_self = reinterpret_cast<const float4*>(g_as)[w];
    int hd = lane >> 3;
    float ad_l = sel4(ad4, hd);
    const uint2* HV = reinterpret_cast<const uint2*>(g_h16);
    float4 acc = make_float4(0.f, 0.f, 0.f, 0.f);
    float z = 0.f;
    int s = (row0 < row1) ? g_csrc[row0] : 0;
    for (int k = row0; k < row1; k++) {
        int s_next = (k + 1 < row1) ? g_csrc[k + 1] : 0;
        float4 a = reinterpret_cast<const float4*>(g_as)[s];
        uint2 hw = HV[s * 32 + lane];
        float wgt = __expf(lrelu(sel4(a, hd) + ad_l));
        float2 f01 = __half22float2(*reinterpret_cast<__half2*>(&hw.x));
        float2 f23 = __half22float2(*reinterpret_cast<__half2*>(&hw.y));
        z += wgt;
        acc.x = fmaf(wgt, f01.x, acc.x);
        acc.y = fmaf(wgt, f01.y, acc.y);
        acc.z = fmaf(wgt, f23.x, acc.z);
        acc.w = fmaf(wgt, f23.y, acc.w);
        s = s_next;
    }
    float wsf = __expf(lrelu(sel4(as_self, hd) + ad_l));
    z += wsf;
    uint2 hw = HV[w * 32 + lane];
    float2 s01 = __half22float2(*reinterpret_cast<__half2*>(&hw.x));
    float2 s23 = __half22float2(*reinterpret_cast<__half2*>(&hw.y));
    acc.x = fmaf(wsf, s01.x, acc.x);
    acc.y = fmaf(wsf, s01.y, acc.y);
    acc.z = fmaf(wsf, s23.x, acc.z);
    acc.w = fmaf(wsf, s23.y, acc.w);
    float inv = 1.f / (z + 1e-16f);
    float4 b = reinterpret_cast<const float4*>(bias)[lane];
    float4 r;
    r.x = fmaxf(acc.x * inv + b.x, 0.f);
    r.y = fmaxf(acc.y * inv + b.y, 0.f);
    r.z = fmaxf(acc.z * inv + b.z, 0.f);
    r.w = fmaxf(acc.w * inv + b.w, 0.f);
    reinterpret_cast<float4*>(g_x)[w * 32 + lane] = r;
}

// ---------------- GraphConv epilogue: Y = relu(gather(P) + Q + bias) ----------
__global__ void k_gc_final(const float* __restrict__ P, const float* __restrict__ Q,
                           const float* __restrict__ bias, float* __restrict__ Y) {
    int q = (blockIdx.x * blockDim.x + threadIdx.x) >> 3;
    if (q >= NN) return;
    int lane = threadIdx.x & 7;
    int row0 = g_rowptr[q], row1 = g_rowptr[q + 1];
    const float4* P4 = reinterpret_cast<const float4*>(P);
    float4 acc = make_float4(0.f, 0.f, 0.f, 0.f);
    int s = (row0 < row1) ? g_csrc[row0] : 0;
    for (int k = row0; k < row1; k++) {
        int s_next = (k + 1 < row1) ? g_csrc[k + 1] : 0;
        float4 p = P4[s * 8 + lane];
        acc.x += p.x; acc.y += p.y; acc.z += p.z; acc.w += p.w;
        s = s_next;
    }
    float4 qq = reinterpret_cast<const float4*>(Q)[q * 8 + lane];
    float4 bb = reinterpret_cast<const float4*>(bias)[lane];
    float4 r;
    r.x = fmaxf(acc.x + qq.x + bb.x, 0.f);
    r.y = fmaxf(acc.y + qq.y + bb.y, 0.f);
    r.z = fmaxf(acc.z + qq.z + bb.z, 0.f);
    r.w = fmaxf(acc.w + qq.w + bb.w, 0.f);
    reinterpret_cast<float4*>(Y)[q * 8 + lane] = r;
}

// ---------------- SAGE epilogue + pool: pool += relu(mean(P) + Q + bias) ------
__global__ void k_sage_final(const float* __restrict__ P, const float* __restrict__ Q,
                             const float* __restrict__ bias,
                             const int* __restrict__ batch) {
    int q = (blockIdx.x * blockDim.x + threadIdx.x) >> 3;
    if (q >= NN) return;
    int lane = threadIdx.x & 7;
    int row0 = g_rowptr[q], row1 = g_rowptr[q + 1];
    const float4* P4 = reinterpret_cast<const float4*>(P);
    float4 acc = make_float4(0.f, 0.f, 0.f, 0.f);
    int s = (row0 < row1) ? g_csrc[row0] : 0;
    for (int k = row0; k < row1; k++) {
        int s_next = (k + 1 < row1) ? g_csrc[k + 1] : 0;
        float4 p = P4[s * 8 + lane];
        acc.x += p.x; acc.y += p.y; acc.z += p.z; acc.w += p.w;
        s = s_next;
    }
    float inv = 1.f / fmaxf((float)(row1 - row0), 1.f);
    float4 qq = reinterpret_cast<const float4*>(Q)[q * 8 + lane];
    float4 bb = reinterpret_cast<const float4*>(bias)[lane];
    float4 r;
    r.x = fmaxf(fmaf(acc.x, inv, qq.x) + bb.x, 0.f);
    r.y = fmaxf(fmaf(acc.y, inv, qq.y) + bb.y, 0.f);
    r.z = fmaxf(fmaf(acc.z, inv, qq.z) + bb.z, 0.f);
    r.w = fmaxf(fmaf(acc.w, inv, qq.w) + bb.w, 0.f);
    int b = batch[q];
    atomicAdd(reinterpret_cast<float4*>(g_pool) + b * 8 + lane, r);
    if (lane == 0) atomicAdd(&g_cnt[b], 1.f);
}

// ---------------- fused dual projection: Ya = X@Wa, Yb = X@Wb ----------------
template <int FIN>
__global__ __launch_bounds__(256) void k_proj2(
    const float* __restrict__ X, const float* __restrict__ Wa,
    const float* __restrict__ Wb, float* __restrict__ Ya, float* __restrict__ Yb) {
    __shared__ float Xs[64][FIN];
    int t = threadIdx.x, tx = t & 31, ty = t >> 5;
    int row0 = blockIdx.x * 64;
    const float4* Xg = reinterpret_cast<const float4*>(X);
    for (int i = t; i < 64 * (FIN / 4); i += 256) {
        int r = i / (FIN / 4), kq = i % (FIN / 4);
        int row = row0 + r;
        float4 v = (row < NN) ? Xg[row * (FIN / 4) + kq] : make_float4(0.f, 0.f, 0.f, 0.f);
        *reinterpret_cast<float4*>(&Xs[r][kq * 4]) = v;
    }
    __syncthreads();
    float a[8], b[8];
#pragma unroll
    for (int r = 0; r < 8; r++) { a[r] = 0.f; b[r] = 0.f; }
#pragma unroll 4
    for (int k = 0; k < FIN; k++) {
        float wa = __ldg(&Wa[k * CC + tx]);
        float wb = __ldg(&Wb[k * CC + tx]);
#pragma unroll
        for (int r = 0; r < 8; r++) {
            float xv = Xs[ty * 8 + r][k];
            a[r] = fmaf(xv, wa, a[r]);
            b[r] = fmaf(xv, wb, b[r]);
        }
    }
#pragma unroll
    for (int r = 0; r < 8; r++) {
        int row = row0 + ty * 8 + r;
        if (row < NN) {
            Ya[row * CC + tx] = a[r];
            Yb[row * CC + tx] = b[r];
        }
    }
}

// ---------------- MLP head (single tiny block) -------------------------------
__global__ void k_head(const float* __restrict__ Wf1, const float* __restrict__ bf1,
                       const float* __restrict__ Wf2, const float* __restrict__ bf2,
                       float* __restrict__ out) {
    __shared__ float t1[NGR * CC];
    int t = threadIdx.x;
    for (int idx = t; idx < NGR * CC; idx += blockDim.x) {
        int g = idx >> 5, c = idx & 31;
        float inv = 1.f / fmaxf(g_cnt[g], 1.f);
        float s = 0.f;
#pragma unroll
        for (int k = 0; k < CC; k++) s = fmaf(g_pool[g * CC + k] * inv, Wf1[k * CC + c], s);
        t1[idx] = fmaxf(s + bf1[c], 0.f);
    }
    __syncthreads();
    for (int idx = t; idx < NGR * NOUT; idx += blockDim.x) {
        int g = idx / NOUT, o = idx - g * NOUT;
        float s = 0.f;
#pragma unroll
        for (int k = 0; k < CC; k++) s = fmaf(t1[g * CC + k], Wf2[k * NOUT + o], s);
        out[idx] = s + bf2[o];
    }
}

// =============================================================================
extern "C" void kernel_launch(void* const* d_in, const int* in_sizes, int n_in,
                              void* d_out, int out_size) {
    const float* x   = (const float*)d_in[0];
    const int*   ei  = (const int*)d_in[1];
    const int*   bat = (const int*)d_in[2];
    const float* W1  = (const float*)d_in[3];
    const float* as1 = (const float*)d_in[4];
    const float* ad1 = (const float*)d_in[5];
    const float* b1  = (const float*)d_in[6];
    const float* W2  = (const float*)d_in[7];
    const float* as2 = (const float*)d_in[8];
    const float* ad2 = (const float*)d_in[9];
    const float* b2  = (const float*)d_in[10];
    const float* W3r = (const float*)d_in[11];
    const float* W3l = (const float*)d_in[12];
    const float* b3  = (const float*)d_in[13];
    const float* W4l = (const float*)d_in[14];
    const float* b4l = (const float*)d_in[15];
    const float* W4r = (const float*)d_in[16];
    const float* Wf1 = (const float*)d_in[17];
    const float* bf1 = (const float*)d_in[18];
    const float* Wf2 = (const float*)d_in[19];
    const float* bf2 = (const float*)d_in[20];
    const int* src = ei;
    const int* dst = ei + EE;
    float* out = (float*)d_out;

    static float *p_h = nullptr, *p_acc, *p_x, *p_pool, *p_cnt;
    static int* p_cnt_i;
    static bool init_done = false;
    static cudaStream_t s2;
    static cudaEvent_t e1, e2;
    if (!p_h) {
        cudaGetSymbolAddress((void**)&p_h, g_h);
        cudaGetSymbolAddress((void**)&p_acc, g_acc);
        cudaGetSymbolAddress((void**)&p_x, g_x);
        cudaGetSymbolAddress((void**)&p_pool, g_pool);
        cudaGetSymbolAddress((void**)&p_cnt, g_cnt);
        cudaGetSymbolAddress((void**)&p_cnt_i, g_cnt_i);
    }
    if (!init_done) {
        cudaFuncSetAttribute(k_gemm128mma, cudaFuncAttributeMaxDynamicSharedMemorySize, SMEM_MMA);
        cudaStreamCreateWithFlags(&s2, cudaStreamNonBlocking);
        cudaEventCreateWithFlags(&e1, cudaEventDisableTiming);
        cudaEventCreateWithFlags(&e2, cudaEventDisableTiming);
        init_done = true;
    }

    const int T = 256;
    const int gE    = (EE + T - 1) / T;
    const int gWNN  = (NN * 32 + T - 1) / T;   // warp per node
    const int gQ8   = (NN * 8 + T - 1) / T;    // 8 lanes per node
    const int gR64  = (NN + 63) / 64;          // 64-row tiles
    const int gTC   = (NN + 63) / 64;          // 64-row MMA tiles

    // ---- fork: CSR build on side stream, overlapped with W prep + GEMM1 ----
    cudaEventRecord(e1, 0);
    cudaStreamWaitEvent(s2, e1, 0);
    cudaMemsetAsync(p_cnt_i, 0, NN * sizeof(int), s2);
    k_count<<<gE, T, 0, s2>>>(dst);
    k_scan1<<<NB_SCAN, 1024, 0, s2>>>();
    k_scan2<<<1, 64, 0, s2>>>();
    k_scan3<<<(NN + 1023) / 1024, 1024, 0, s2>>>();
    k_fill<<<gE, T, 0, s2>>>(src, dst);
    cudaMemsetAsync(p_pool, 0, NGR * CC * sizeof(float), s2);
    cudaMemsetAsync(p_cnt, 0, NGR * sizeof(float), s2);
    cudaEventRecord(e2, s2);

    // main stream: W prep + GAT layer-1 GEMM (independent of CSR)
    {
        dim3 gp((HC * HC + T - 1) / T, 2);
        k_prepWt2<<<gp, T>>>(W1, W2);
    }
    k_gemm128mma<<<gTC, 256, SMEM_MMA>>>(x, 0, as1, ad1);
    cudaStreamWaitEvent(0, e2, 0);     // CSR + pool-zero ready

    // ---- GAT layer 1 aggregation ----
    k_gat_aggr<<<gWNN, T>>>(b1);

    // ---- GAT layer 2 ----
    k_gemm128mma<<<gTC, 256, SMEM_MMA>>>(p_x, 1, as2, ad2);
    k_gat_aggr<<<gWNN, T>>>(b2);

    // ---- GraphConv: x3 = relu(segsum((x2@W3r)[src]) + x2@W3l + b3) ----
    k_proj2<HC><<<gR64, 256>>>(p_x, W3r, W3l, p_acc, p_h);    // Ya=g_acc, Yb=g_h
    k_gc_final<<<gQ8, T>>>(p_acc, p_h, b3, p_x);              // x3 -> g_x

    // ---- SAGEConv + pool: pool += relu(mean((x3@W4l)[src]) + x3@W4r + b4l) ----
    k_proj2<CC><<<gR64, 256>>>(p_x, W4l, W4r, p_acc, p_h);    // Ya=g_acc, Yb=g_h
    k_sage_final<<<gQ8, T>>>(p_acc, p_h, b4l, bat);           // pool atomics

    // ---- head ----
    k_head<<<1, 1024>>>(Wf1, bf1, Wf2, bf2, out);
}

// round 12
// speedup vs baseline: 1.2504x; 1.0420x over previous
#include <cuda_runtime.h>
#include <cuda_bf16.h>
#include <cuda_fp16.h>
#include <cstdint>

#define NN   50000
#define EE   800000
#define HH   4
#define CC   32
#define HC   128
#define NGR  64
#define NOUT 10
#define NB_SCAN 49   // ceil(NN/1024)
#define STR  68      // smem row stride in 32-bit words

// ---------------- scratch (device globals; no allocation allowed) ------------
__device__ float g_h[NN * HC];          // proj scratch (GraphConv/SAGE)
__device__ uint32_t g_h16[NN * 64];     // GAT h in half2 (64 words = 128 halves/row)
__device__ float g_acc[NN * HC];
__device__ float g_x[NN * HC];
__device__ float g_as[NN * HH];
__device__ float g_ad[NN * HH];
__device__ float g_pool[NGR * CC];
__device__ float g_cnt[NGR];
// CSR by destination
__device__ int g_cnt_i[NN];
__device__ int g_rowptr[NN + 1];
__device__ int g_cursor[NN];
__device__ int g_csrc[EE];
__device__ int g_bsum[NB_SCAN];
__device__ int g_boff[NB_SCAN];
// bf16-split transposed weights Wt[n][k] per GAT layer
__device__ unsigned short g_WtHi[2][HC * HC];
__device__ unsigned short g_WtLo[2][HC * HC];

__device__ __forceinline__ float lrelu(float v) { return v > 0.f ? v : 0.2f * v; }
__device__ __forceinline__ uint32_t pack_h2(float a, float b) {
    __half2 h = __floats2half2_rn(a, b);
    return *reinterpret_cast<uint32_t*>(&h);
}

// ---------------- W -> bf16 hi/lo transposed prep (both layers) ---------------
__global__ void k_prepWt2(const float* __restrict__ W1, const float* __restrict__ W2) {
    int i = blockIdx.x * blockDim.x + threadIdx.x;  // i = k*128 + n
    if (i >= HC * HC) return;
    int layer = blockIdx.y;
    const float* W = layer ? W2 : W1;
    int k = i >> 7, n = i & 127;
    float w = W[i];
    __nv_bfloat16 hb = __float2bfloat16(w);
    __nv_bfloat16 lb = __float2bfloat16(w - __bfloat162float(hb));
    g_WtHi[layer][n * HC + k] = __bfloat16_as_ushort(hb);
    g_WtLo[layer][n * HC + k] = __bfloat16_as_ushort(lb);
}

// ---------------- mma.sync bf16-split GEMM (64-row tiles, occ 2) --------------
#define MMA_BF16(c, A0, A1, A2, A3, B0, B1) \
    asm volatile("mma.sync.aligned.m16n8k16.row.col.f32.bf16.bf16.f32 " \
        "{%0,%1,%2,%3}, {%4,%5,%6,%7}, {%8,%9}, {%0,%1,%2,%3};" \
        : "+f"((c)[0]), "+f"((c)[1]), "+f"((c)[2]), "+f"((c)[3]) \
        : "r"(A0), "r"(A1), "r"(A2), "r"(A3), "r"(B0), "r"(B1))

// smem: xh 64*STR | xl 64*STR | wh 128*STR | wl 128*STR | sws 128f | swd 128f
#define SMEM_MMA ((2 * 64 + 2 * 128) * STR * 4 + 1024)

__global__ __launch_bounds__(256, 2) void k_gemm128mma(
    const float* __restrict__ X, int layer,
    const float* __restrict__ aws, const float* __restrict__ awd) {
    extern __shared__ __align__(16) char smem[];
    uint32_t* xh = reinterpret_cast<uint32_t*>(smem);
    uint32_t* xl = xh + 64 * STR;
    uint32_t* wh = xl + 64 * STR;
    uint32_t* wl = wh + 128 * STR;
    float* sws = reinterpret_cast<float*>(wl + 128 * STR);
    float* swd = sws + 128;
    int tid = threadIdx.x, lane = tid & 31, wid = tid >> 5;
    int gid = lane >> 2, tg = lane & 3;
    int row0 = blockIdx.x * 64;

    if (tid < 128) { sws[tid] = aws[tid]; swd[tid] = awd[tid]; }
    // W images -> smem, uint4 (row stride 68 words = 17 uint4)
    {
        const uint4* gh4 = reinterpret_cast<const uint4*>(g_WtHi[layer]);
        const uint4* gl4 = reinterpret_cast<const uint4*>(g_WtLo[layer]);
        uint4* wh4 = reinterpret_cast<uint4*>(wh);
        uint4* wl4 = reinterpret_cast<uint4*>(wl);
        for (int i = tid; i < 128 * 16; i += 256) {
            int r = i >> 4, q = i & 15;
            wh4[r * 17 + q] = gh4[i];
            wl4[r * 17 + q] = gl4[i];
        }
    }
    // X tile (64 rows) -> bf16 hi/lo packed words
    {
        const float4* X4 = reinterpret_cast<const float4*>(X);
        for (int i = tid; i < 64 * 32; i += 256) {
            int r = i >> 5, q = i & 31;
            int grow = row0 + r;
            float4 v = (grow < NN) ? X4[(size_t)grow * 32 + q] : make_float4(0.f, 0.f, 0.f, 0.f);
            float vv[4] = {v.x, v.y, v.z, v.w};
#pragma unroll
            for (int q2 = 0; q2 < 2; q2++) {
                __nv_bfloat16 h0 = __float2bfloat16(vv[2 * q2]);
                __nv_bfloat16 h1 = __float2bfloat16(vv[2 * q2 + 1]);
                __nv_bfloat16 l0 = __float2bfloat16(vv[2 * q2] - __bfloat162float(h0));
                __nv_bfloat16 l1 = __float2bfloat16(vv[2 * q2 + 1] - __bfloat162float(h1));
                xh[r * STR + 2 * q + q2] =
                    ((uint32_t)__bfloat16_as_ushort(h1) << 16) | __bfloat16_as_ushort(h0);
                xl[r * STR + 2 * q + q2] =
                    ((uint32_t)__bfloat16_as_ushort(l1) << 16) | __bfloat16_as_ushort(l0);
            }
        }
    }
    __syncthreads();

    // warp tiling: rows (wid&3)*16..+15, cols (wid>>2)*64..+63
    int warpM = (wid & 3) * 16;
    int n0 = (wid >> 2) * 64;
    float acc[8][4];
#pragma unroll
    for (int t = 0; t < 8; t++)
#pragma unroll
        for (int j = 0; j < 4; j++) acc[t][j] = 0.f;

    const uint32_t* xrh = xh + (warpM + gid) * STR + tg;
    const uint32_t* xrl = xl + (warpM + gid) * STR + tg;
#pragma unroll 1
    for (int kk = 0; kk < 8; kk++) {
        int kw = kk * 8;
        uint32_t ah0 = xrh[kw],           ah2 = xrh[kw + 4];
        uint32_t ah1 = xrh[kw + 8 * STR], ah3 = xrh[kw + 8 * STR + 4];
        uint32_t al0 = xrl[kw],           al2 = xrl[kw + 4];
        uint32_t al1 = xrl[kw + 8 * STR], al3 = xrl[kw + 8 * STR + 4];
#pragma unroll
        for (int t = 0; t < 8; t++) {
            const uint32_t* wrh = wh + (n0 + t * 8 + gid) * STR + kw + tg;
            const uint32_t* wrl = wl + (n0 + t * 8 + gid) * STR + kw + tg;
            uint32_t bh0 = wrh[0], bh1 = wrh[4];
            uint32_t bl0 = wrl[0], bl1 = wrl[4];
            MMA_BF16(acc[t], ah0, ah1, ah2, ah3, bh0, bh1);
            MMA_BF16(acc[t], ah0, ah1, ah2, ah3, bl0, bl1);
            MMA_BF16(acc[t], al0, al1, al2, al3, bh0, bh1);
        }
    }

    // epilogue: store h rows as half2 + attention logits (this warp: 2 heads)
    int r0 = row0 + warpM + gid, r1 = r0 + 8;
#pragma unroll
    for (int t = 0; t < 8; t++) {
        int cidx = (n0 >> 1) + t * 4 + tg;   // half2-word column (of 64)
        if (r0 < NN) g_h16[(size_t)r0 * 64 + cidx] = pack_h2(acc[t][0], acc[t][1]);
        if (r1 < NN) g_h16[(size_t)r1 * 64 + cidx] = pack_h2(acc[t][2], acc[t][3]);
    }
#pragma unroll
    for (int hh = 0; hh < 2; hh++) {
        int h = (n0 >> 5) + hh;
        float ps0 = 0.f, pd0 = 0.f, ps1 = 0.f, pd1 = 0.f;
#pragma unroll
        for (int j = 0; j < 4; j++) {
            int t = hh * 4 + j;
            int col = n0 + t * 8 + 2 * tg;
            float w0 = sws[col], w1 = sws[col + 1];
            float v0 = swd[col], v1 = swd[col + 1];
            ps0 = fmaf(acc[t][0], w0, fmaf(acc[t][1], w1, ps0));
            pd0 = fmaf(acc[t][0], v0, fmaf(acc[t][1], v1, pd0));
            ps1 = fmaf(acc[t][2], w0, fmaf(acc[t][3], w1, ps1));
            pd1 = fmaf(acc[t][2], v0, fmaf(acc[t][3], v1, pd1));
        }
#pragma unroll
        for (int o = 1; o <= 2; o <<= 1) {
            ps0 += __shfl_xor_sync(0xffffffffu, ps0, o);
            pd0 += __shfl_xor_sync(0xffffffffu, pd0, o);
            ps1 += __shfl_xor_sync(0xffffffffu, ps1, o);
            pd1 += __shfl_xor_sync(0xffffffffu, pd1, o);
        }
        if (tg == 0) {
            if (r0 < NN) { g_as[r0 * HH + h] = ps0; g_ad[r0 * HH + h] = pd0; }
            if (r1 < NN) { g_as[r1 * HH + h] = ps1; g_ad[r1 * HH + h] = pd1; }
        }
    }
}

// ---------------- CSR build ---------------------------------------------------
__global__ void k_count(const int* __restrict__ dst) {
    int e = blockIdx.x * blockDim.x + threadIdx.x;
    if (e < EE) atomicAdd(&g_cnt_i[dst[e]], 1);
}

__global__ void k_scan1() {
    __shared__ int wsum[32];
    int t = threadIdx.x, b = blockIdx.x;
    int i = b * 1024 + t;
    int v = (i < NN) ? g_cnt_i[i] : 0;
    int incl = v;
#pragma unroll
    for (int o = 1; o < 32; o <<= 1) {
        int n = __shfl_up_sync(0xffffffffu, incl, o);
        if ((t & 31) >= o) incl += n;
    }
    if ((t & 31) == 31) wsum[t >> 5] = incl;
    __syncthreads();
    if (t < 32) {
        int wv = wsum[t];
#pragma unroll
        for (int o = 1; o < 32; o <<= 1) {
            int n = __shfl_up_sync(0xffffffffu, wv, o);
            if (t >= o) wv += n;
        }
        wsum[t] = wv;
    }
    __syncthreads();
    int excl = incl - v + ((t >= 32) ? wsum[(t >> 5) - 1] : 0);
    if (i < NN) g_rowptr[i] = excl;
    if (t == 1023) g_bsum[b] = excl + v;
}

__global__ void k_scan2() {
    __shared__ int w0s;
    int t = threadIdx.x;
    int v = (t < NB_SCAN) ? g_bsum[t] : 0;
    int incl = v;
#pragma unroll
    for (int o = 1; o < 32; o <<= 1) {
        int n = __shfl_up_sync(0xffffffffu, incl, o);
        if ((t & 31) >= o) incl += n;
    }
    if (t == 31) w0s = incl;
    __syncthreads();
    if (t >= 32) incl += w0s;
    if (t < NB_SCAN) g_boff[t] = incl - v;
}

__global__ void k_scan3() {
    int i = blockIdx.x * blockDim.x + threadIdx.x;
    if (i < NN) {
        int v = g_rowptr[i] + g_boff[i >> 10];
        g_rowptr[i] = v;
        g_cursor[i] = v;
    }
    if (i == 0) g_rowptr[NN] = EE;
}

__global__ void k_fill(const int* __restrict__ src, const int* __restrict__ dst) {
    int e = blockIdx.x * blockDim.x + threadIdx.x;
    if (e >= EE) return;
    int pos = atomicAdd(&g_cursor[dst[e]], 1);
    g_csrc[pos] = src[e];
}

// ---------------- fused GAT aggregation: warp per dst, depth-2 pipeline -------
__global__ void k_gat_aggr(const float* __restrict__ bias) {
    int w = (blockIdx.x * blockDim.x + threadIdx.x) >> 5;
    if (w >= NN) return;
    int lane = threadIdx.x & 31;
    int row0 = g_rowptr[w], row1 = g_rowptr[w + 1];
    int hd = lane >> 3;
    float ad_l = g_as[0], dummy;  // placeholder init overwritten below
    ad_l = g_ad[w * HH + hd];
    (void)dummy;
    const uint2* HV = reinterpret_cast<const uint2*>(g_h16);
    float4 acc = make_float4(0.f, 0.f, 0.f, 0.f);
    float z = 0.f;
    if (row0 < row1) {
        int s = g_csrc[row0];
        float as_l = g_as[s * HH + hd];
        uint2 hw = HV[s * 32 + lane];
        for (int k = row0; k < row1; k++) {
            // prefetch next edge's payload before consuming current
            int k2 = k + 1;
            int s2 = (k2 < row1) ? g_csrc[k2] : 0;
            float as2 = g_as[s2 * HH + hd];
            uint2 hw2 = HV[s2 * 32 + lane];
            float wgt = __expf(lrelu(as_l + ad_l));
            float2 f01 = __half22float2(*reinterpret_cast<__half2*>(&hw.x));
            float2 f23 = __half22float2(*reinterpret_cast<__half2*>(&hw.y));
            z += wgt;
            acc.x = fmaf(wgt, f01.x, acc.x);
            acc.y = fmaf(wgt, f01.y, acc.y);
            acc.z = fmaf(wgt, f23.x, acc.z);
            acc.w = fmaf(wgt, f23.y, acc.w);
            as_l = as2; hw = hw2;
        }
    }
    // self loop
    float as_self = g_as[w * HH + hd];
    float wsf = __expf(lrelu(as_self + ad_l));
    z += wsf;
    uint2 hws = HV[w * 32 + lane];
    float2 s01 = __half22float2(*reinterpret_cast<__half2*>(&hws.x));
    float2 s23 = __half22float2(*reinterpret_cast<__half2*>(&hws.y));
    acc.x = fmaf(wsf, s01.x, acc.x);
    acc.y = fmaf(wsf, s01.y, acc.y);
    acc.z = fmaf(wsf, s23.x, acc.z);
    acc.w = fmaf(wsf, s23.y, acc.w);
    float inv = 1.f / (z + 1e-16f);
    float4 b = reinterpret_cast<const float4*>(bias)[lane];
    float4 r;
    r.x = fmaxf(acc.x * inv + b.x, 0.f);
    r.y = fmaxf(acc.y * inv + b.y, 0.f);
    r.z = fmaxf(acc.z * inv + b.z, 0.f);
    r.w = fmaxf(acc.w * inv + b.w, 0.f);
    reinterpret_cast<float4*>(g_x)[w * 32 + lane] = r;
}

// ---------------- GraphConv epilogue: Y = relu(gather(P) + Q + bias) ----------
__global__ void k_gc_final(const float* __restrict__ P, const float* __restrict__ Q,
                           const float* __restrict__ bias, float* __restrict__ Y) {
    int q = (blockIdx.x * blockDim.x + threadIdx.x) >> 3;
    if (q >= NN) return;
    int lane = threadIdx.x & 7;
    int row0 = g_rowptr[q], row1 = g_rowptr[q + 1];
    const float4* P4 = reinterpret_cast<const float4*>(P);
    float4 acc = make_float4(0.f, 0.f, 0.f, 0.f);
    int s = (row0 < row1) ? g_csrc[row0] : 0;
    for (int k = row0; k < row1; k++) {
        int s_next = (k + 1 < row1) ? g_csrc[k + 1] : 0;
        float4 p = P4[s * 8 + lane];
        acc.x += p.x; acc.y += p.y; acc.z += p.z; acc.w += p.w;
        s = s_next;
    }
    float4 qq = reinterpret_cast<const float4*>(Q)[q * 8 + lane];
    float4 bb = reinterpret_cast<const float4*>(bias)[lane];
    float4 r;
    r.x = fmaxf(acc.x + qq.x + bb.x, 0.f);
    r.y = fmaxf(acc.y + qq.y + bb.y, 0.f);
    r.z = fmaxf(acc.z + qq.z + bb.z, 0.f);
    r.w = fmaxf(acc.w + qq.w + bb.w, 0.f);
    reinterpret_cast<float4*>(Y)[q * 8 + lane] = r;
}

// ---------------- SAGE epilogue + pool: pool += relu(mean(P) + Q + bias) ------
__global__ void k_sage_final(const float* __restrict__ P, const float* __restrict__ Q,
                             const float* __restrict__ bias,
                             const int* __restrict__ batch) {
    int q = (blockIdx.x * blockDim.x + threadIdx.x) >> 3;
    if (q >= NN) return;
    int lane = threadIdx.x & 7;
    int row0 = g_rowptr[q], row1 = g_rowptr[q + 1];
    const float4* P4 = reinterpret_cast<const float4*>(P);
    float4 acc = make_float4(0.f, 0.f, 0.f, 0.f);
    int s = (row0 < row1) ? g_csrc[row0] : 0;
    for (int k = row0; k < row1; k++) {
        int s_next = (k + 1 < row1) ? g_csrc[k + 1] : 0;
        float4 p = P4[s * 8 + lane];
        acc.x += p.x; acc.y += p.y; acc.z += p.z; acc.w += p.w;
        s = s_next;
    }
    float inv = 1.f / fmaxf((float)(row1 - row0), 1.f);
    float4 qq = reinterpret_cast<const float4*>(Q)[q * 8 + lane];
    float4 bb = reinterpret_cast<const float4*>(bias)[lane];
    float4 r;
    r.x = fmaxf(fmaf(acc.x, inv, qq.x) + bb.x, 0.f);
    r.y = fmaxf(fmaf(acc.y, inv, qq.y) + bb.y, 0.f);
    r.z = fmaxf(fmaf(acc.z, inv, qq.z) + bb.z, 0.f);
    r.w = fmaxf(fmaf(acc.w, inv, qq.w) + bb.w, 0.f);
    int b = batch[q];
    atomicAdd(reinterpret_cast<float4*>(g_pool) + b * 8 + lane, r);
    if (lane == 0) atomicAdd(&g_cnt[b], 1.f);
}

// ---------------- fused dual projection: Ya = X@Wa, Yb = X@Wb ----------------
template <int FIN>
__global__ __launch_bounds__(256) void k_proj2(
    const float* __restrict__ X, const float* __restrict__ Wa,
    const float* __restrict__ Wb, float* __restrict__ Ya, float* __restrict__ Yb) {
    __shared__ float Xs[64][FIN];
    int t = threadIdx.x, tx = t & 31, ty = t >> 5;
    int row0 = blockIdx.x * 64;
    const float4* Xg = reinterpret_cast<const float4*>(X);
    for (int i = t; i < 64 * (FIN / 4); i += 256) {
        int r = i / (FIN / 4), kq = i % (FIN / 4);
        int row = row0 + r;
        float4 v = (row < NN) ? Xg[row * (FIN / 4) + kq] : make_float4(0.f, 0.f, 0.f, 0.f);
        *reinterpret_cast<float4*>(&Xs[r][kq * 4]) = v;
    }
    __syncthreads();
    float a[8], b[8];
#pragma unroll
    for (int r = 0; r < 8; r++) { a[r] = 0.f; b[r] = 0.f; }
#pragma unroll 4
    for (int k = 0; k < FIN; k++) {
        float wa = __ldg(&Wa[k * CC + tx]);
        float wb = __ldg(&Wb[k * CC + tx]);
#pragma unroll
        for (int r = 0; r < 8; r++) {
            float xv = Xs[ty * 8 + r][k];
            a[r] = fmaf(xv, wa, a[r]);
            b[r] = fmaf(xv, wb, b[r]);
        }
    }
#pragma unroll
    for (int r = 0; r < 8; r++) {
        int row = row0 + ty * 8 + r;
        if (row < NN) {
            Ya[row * CC + tx] = a[r];
            Yb[row * CC + tx] = b[r];
        }
    }
}

// ---------------- MLP head (single tiny block) -------------------------------
__global__ void k_head(const float* __restrict__ Wf1, const float* __restrict__ bf1,
                       const float* __restrict__ Wf2, const float* __restrict__ bf2,
                       float* __restrict__ out) {
    __shared__ float t1[NGR * CC];
    int t = threadIdx.x;
    for (int idx = t; idx < NGR * CC; idx += blockDim.x) {
        int g = idx >> 5, c = idx & 31;
        float inv = 1.f / fmaxf(g_cnt[g], 1.f);
        float s = 0.f;
#pragma unroll
        for (int k = 0; k < CC; k++) s = fmaf(g_pool[g * CC + k] * inv, Wf1[k * CC + c], s);
        t1[idx] = fmaxf(s + bf1[c], 0.f);
    }
    __syncthreads();
    for (int idx = t; idx < NGR * NOUT; idx += blockDim.x) {
        int g = idx / NOUT, o = idx - g * NOUT;
        float s = 0.f;
#pragma unroll
        for (int k = 0; k < CC; k++) s = fmaf(t1[g * CC + k], Wf2[k * NOUT + o], s);
        out[idx] = s + bf2[o];
    }
}

// =============================================================================
extern "C" void kernel_launch(void* const* d_in, const int* in_sizes, int n_in,
                              void* d_out, int out_size) {
    const float* x   = (const float*)d_in[0];
    const int*   ei  = (const int*)d_in[1];
    const int*   bat = (const int*)d_in[2];
    const float* W1  = (const float*)d_in[3];
    const float* as1 = (const float*)d_in[4];
    const float* ad1 = (const float*)d_in[5];
    const float* b1  = (const float*)d_in[6];
    const float* W2  = (const float*)d_in[7];
    const float* as2 = (const float*)d_in[8];
    const float* ad2 = (const float*)d_in[9];
    const float* b2  = (const float*)d_in[10];
    const float* W3r = (const float*)d_in[11];
    const float* W3l = (const float*)d_in[12];
    const float* b3  = (const float*)d_in[13];
    const float* W4l = (const float*)d_in[14];
    const float* b4l = (const float*)d_in[15];
    const float* W4r = (const float*)d_in[16];
    const float* Wf1 = (const float*)d_in[17];
    const float* bf1 = (const float*)d_in[18];
    const float* Wf2 = (const float*)d_in[19];
    const float* bf2 = (const float*)d_in[20];
    const int* src = ei;
    const int* dst = ei + EE;
    float* out = (float*)d_out;

    static float *p_h = nullptr, *p_acc, *p_x, *p_pool, *p_cnt;
    static int* p_cnt_i;
    static bool init_done = false;
    static cudaStream_t s2;
    static cudaEvent_t e1, e2;
    if (!p_h) {
        cudaGetSymbolAddress((void**)&p_h, g_h);
        cudaGetSymbolAddress((void**)&p_acc, g_acc);
        cudaGetSymbolAddress((void**)&p_x, g_x);
        cudaGetSymbolAddress((void**)&p_pool, g_pool);
        cudaGetSymbolAddress((void**)&p_cnt, g_cnt);
        cudaGetSymbolAddress((void**)&p_cnt_i, g_cnt_i);
    }
    if (!init_done) {
        cudaFuncSetAttribute(k_gemm128mma, cudaFuncAttributeMaxDynamicSharedMemorySize, SMEM_MMA);
        cudaStreamCreateWithFlags(&s2, cudaStreamNonBlocking);
        cudaEventCreateWithFlags(&e1, cudaEventDisableTiming);
        cudaEventCreateWithFlags(&e2, cudaEventDisableTiming);
        init_done = true;
    }

    const int T = 256;
    const int gE    = (EE + T - 1) / T;
    const int gWNN  = (NN * 32 + T - 1) / T;   // warp per node
    const int gQ8   = (NN * 8 + T - 1) / T;    // 8 lanes per node
    const int gR64  = (NN + 63) / 64;          // 64-row tiles
    const int gTC   = (NN + 63) / 64;          // 64-row MMA tiles

    // ---- fork: CSR build on side stream, overlapped with W prep + GEMM1 ----
    cudaEventRecord(e1, 0);
    cudaStreamWaitEvent(s2, e1, 0);
    cudaMemsetAsync(p_cnt_i, 0, NN * sizeof(int), s2);
    k_count<<<gE, T, 0, s2>>>(dst);
    k_scan1<<<NB_SCAN, 1024, 0, s2>>>();
    k_scan2<<<1, 64, 0, s2>>>();
    k_scan3<<<(NN + 1023) / 1024, 1024, 0, s2>>>();
    k_fill<<<gE, T, 0, s2>>>(src, dst);
    cudaMemsetAsync(p_pool, 0, NGR * CC * sizeof(float), s2);
    cudaMemsetAsync(p_cnt, 0, NGR * sizeof(float), s2);
    cudaEventRecord(e2, s2);

    // main stream: W prep + GAT layer-1 GEMM (independent of CSR)
    {
        dim3 gp((HC * HC + T - 1) / T, 2);
        k_prepWt2<<<gp, T>>>(W1, W2);
    }
    k_gemm128mma<<<gTC, 256, SMEM_MMA>>>(x, 0, as1, ad1);
    cudaStreamWaitEvent(0, e2, 0);     // CSR + pool-zero ready

    // ---- GAT layer 1 aggregation ----
    k_gat_aggr<<<gWNN, T>>>(b1);

    // ---- GAT layer 2 ----
    k_gemm128mma<<<gTC, 256, SMEM_MMA>>>(p_x, 1, as2, ad2);
    k_gat_aggr<<<gWNN, T>>>(b2);

    // ---- GraphConv: x3 = relu(segsum((x2@W3r)[src]) + x2@W3l + b3) ----
    k_proj2<HC><<<gR64, 256>>>(p_x, W3r, W3l, p_acc, p_h);    // Ya=g_acc, Yb=g_h
    k_gc_final<<<gQ8, T>>>(p_acc, p_h, b3, p_x);              // x3 -> g_x

    // ---- SAGEConv + pool: pool += relu(mean((x3@W4l)[src]) + x3@W4r + b4l) ----
    k_proj2<CC><<<gR64, 256>>>(p_x, W4l, W4r, p_acc, p_h);    // Ya=g_acc, Yb=g_h
    k_sage_final<<<gQ8, T>>>(p_acc, p_h, b4l, bat);           // pool atomics

    // ---- head ----
    k_head<<<1, 1024>>>(Wf1, bf1, Wf2, bf2, out);
}

// round 13
// speedup vs baseline: 1.2918x; 1.0331x over previous
#include <cuda_runtime.h>
#include <cuda_bf16.h>
#include <cuda_fp16.h>
#include <cstdint>

#define NN   50000
#define EE   800000
#define HH   4
#define CC   32
#define HC   128
#define NGR  64
#define NOUT 10
#define NB_SCAN 49   // ceil(NN/1024)
#define STR  68      // smem row stride in 32-bit words

// ---------------- scratch (device globals; no allocation allowed) ------------
__device__ float g_h[NN * HC];          // proj scratch (GraphConv/SAGE)
__device__ uint32_t g_h16[NN * 64];     // GAT h in half2 (64 words = 128 halves/row)
__device__ float g_acc[NN * HC];
__device__ float g_x[NN * HC];
__device__ float g_as[NN * HH];
__device__ float g_ad[NN * HH];
__device__ float g_pool[NGR * CC];
__device__ float g_cnt[NGR];
// CSR by destination
__device__ int g_cnt_i[NN];
__device__ int g_rowptr[NN + 1];
__device__ int g_cursor[NN];
__device__ int g_csrc[EE];
__device__ int g_bsum[NB_SCAN];
__device__ int g_boff[NB_SCAN];
// bf16-split transposed weights Wt[n][k] per GAT layer
__device__ unsigned short g_WtHi[2][HC * HC];
__device__ unsigned short g_WtLo[2][HC * HC];

__device__ __forceinline__ float lrelu(float v) { return v > 0.f ? v : 0.2f * v; }
__device__ __forceinline__ uint32_t pack_h2(float a, float b) {
    __half2 h = __floats2half2_rn(a, b);
    return *reinterpret_cast<uint32_t*>(&h);
}

// ---------------- W -> bf16 hi/lo transposed prep (both layers) ---------------
__global__ void k_prepWt2(const float* __restrict__ W1, const float* __restrict__ W2) {
    int i = blockIdx.x * blockDim.x + threadIdx.x;  // i = k*128 + n
    if (i >= HC * HC) return;
    int layer = blockIdx.y;
    const float* W = layer ? W2 : W1;
    int k = i >> 7, n = i & 127;
    float w = W[i];
    __nv_bfloat16 hb = __float2bfloat16(w);
    __nv_bfloat16 lb = __float2bfloat16(w - __bfloat162float(hb));
    g_WtHi[layer][n * HC + k] = __bfloat16_as_ushort(hb);
    g_WtLo[layer][n * HC + k] = __bfloat16_as_ushort(lb);
}

// ---------------- mma.sync bf16-split GEMM (64-row tiles, occ 2) --------------
#define MMA_BF16(c, A0, A1, A2, A3, B0, B1) \
    asm volatile("mma.sync.aligned.m16n8k16.row.col.f32.bf16.bf16.f32 " \
        "{%0,%1,%2,%3}, {%4,%5,%6,%7}, {%8,%9}, {%0,%1,%2,%3};" \
        : "+f"((c)[0]), "+f"((c)[1]), "+f"((c)[2]), "+f"((c)[3]) \
        : "r"(A0), "r"(A1), "r"(A2), "r"(A3), "r"(B0), "r"(B1))

// smem: xh 64*STR | xl 64*STR | wh 128*STR | wl 128*STR | sws 128f | swd 128f
#define SMEM_MMA ((2 * 64 + 2 * 128) * STR * 4 + 1024)

__global__ __launch_bounds__(256, 2) void k_gemm128mma(
    const float* __restrict__ X, int layer,
    const float* __restrict__ aws, const float* __restrict__ awd) {
    extern __shared__ __align__(16) char smem[];
    uint32_t* xh = reinterpret_cast<uint32_t*>(smem);
    uint32_t* xl = xh + 64 * STR;
    uint32_t* wh = xl + 64 * STR;
    uint32_t* wl = wh + 128 * STR;
    float* sws = reinterpret_cast<float*>(wl + 128 * STR);
    float* swd = sws + 128;
    int tid = threadIdx.x, lane = tid & 31, wid = tid >> 5;
    int gid = lane >> 2, tg = lane & 3;
    int row0 = blockIdx.x * 64;

    if (tid < 128) { sws[tid] = aws[tid]; swd[tid] = awd[tid]; }
    // W images -> smem, uint4 (row stride 68 words = 17 uint4)
    {
        const uint4* gh4 = reinterpret_cast<const uint4*>(g_WtHi[layer]);
        const uint4* gl4 = reinterpret_cast<const uint4*>(g_WtLo[layer]);
        uint4* wh4 = reinterpret_cast<uint4*>(wh);
        uint4* wl4 = reinterpret_cast<uint4*>(wl);
        for (int i = tid; i < 128 * 16; i += 256) {
            int r = i >> 4, q = i & 15;
            wh4[r * 17 + q] = gh4[i];
            wl4[r * 17 + q] = gl4[i];
        }
    }
    // X tile (64 rows) -> bf16 hi/lo packed words
    {
        const float4* X4 = reinterpret_cast<const float4*>(X);
        for (int i = tid; i < 64 * 32; i += 256) {
            int r = i >> 5, q = i & 31;
            int grow = row0 + r;
            float4 v = (grow < NN) ? X4[(size_t)grow * 32 + q] : make_float4(0.f, 0.f, 0.f, 0.f);
            float vv[4] = {v.x, v.y, v.z, v.w};
#pragma unroll
            for (int q2 = 0; q2 < 2; q2++) {
                __nv_bfloat16 h0 = __float2bfloat16(vv[2 * q2]);
                __nv_bfloat16 h1 = __float2bfloat16(vv[2 * q2 + 1]);
                __nv_bfloat16 l0 = __float2bfloat16(vv[2 * q2] - __bfloat162float(h0));
                __nv_bfloat16 l1 = __float2bfloat16(vv[2 * q2 + 1] - __bfloat162float(h1));
                xh[r * STR + 2 * q + q2] =
                    ((uint32_t)__bfloat16_as_ushort(h1) << 16) | __bfloat16_as_ushort(h0);
                xl[r * STR + 2 * q + q2] =
                    ((uint32_t)__bfloat16_as_ushort(l1) << 16) | __bfloat16_as_ushort(l0);
            }
        }
    }
    __syncthreads();

    // warp tiling: rows (wid&3)*16..+15, cols (wid>>2)*64..+63
    int warpM = (wid & 3) * 16;
    int n0 = (wid >> 2) * 64;
    float acc[8][4];
#pragma unroll
    for (int t = 0; t < 8; t++)
#pragma unroll
        for (int j = 0; j < 4; j++) acc[t][j] = 0.f;

    const uint32_t* xrh = xh + (warpM + gid) * STR + tg;
    const uint32_t* xrl = xl + (warpM + gid) * STR + tg;
#pragma unroll 1
    for (int kk = 0; kk < 8; kk++) {
        int kw = kk * 8;
        uint32_t ah0 = xrh[kw],           ah2 = xrh[kw + 4];
        uint32_t ah1 = xrh[kw + 8 * STR], ah3 = xrh[kw + 8 * STR + 4];
        uint32_t al0 = xrl[kw],           al2 = xrl[kw + 4];
        uint32_t al1 = xrl[kw + 8 * STR], al3 = xrl[kw + 8 * STR + 4];
#pragma unroll
        for (int t = 0; t < 8; t++) {
            const uint32_t* wrh = wh + (n0 + t * 8 + gid) * STR + kw + tg;
            const uint32_t* wrl = wl + (n0 + t * 8 + gid) * STR + kw + tg;
            uint32_t bh0 = wrh[0], bh1 = wrh[4];
            uint32_t bl0 = wrl[0], bl1 = wrl[4];
            MMA_BF16(acc[t], ah0, ah1, ah2, ah3, bh0, bh1);
            MMA_BF16(acc[t], ah0, ah1, ah2, ah3, bl0, bl1);
            MMA_BF16(acc[t], al0, al1, al2, al3, bh0, bh1);
        }
    }

    // epilogue: store h rows as half2 + attention logits (this warp: 2 heads)
    int r0 = row0 + warpM + gid, r1 = r0 + 8;
#pragma unroll
    for (int t = 0; t < 8; t++) {
        int cidx = (n0 >> 1) + t * 4 + tg;   // half2-word column (of 64)
        if (r0 < NN) g_h16[(size_t)r0 * 64 + cidx] = pack_h2(acc[t][0], acc[t][1]);
        if (r1 < NN) g_h16[(size_t)r1 * 64 + cidx] = pack_h2(acc[t][2], acc[t][3]);
    }
#pragma unroll
    for (int hh = 0; hh < 2; hh++) {
        int h = (n0 >> 5) + hh;
        float ps0 = 0.f, pd0 = 0.f, ps1 = 0.f, pd1 = 0.f;
#pragma unroll
        for (int j = 0; j < 4; j++) {
            int t = hh * 4 + j;
            int col = n0 + t * 8 + 2 * tg;
            float w0 = sws[col], w1 = sws[col + 1];
            float v0 = swd[col], v1 = swd[col + 1];
            ps0 = fmaf(acc[t][0], w0, fmaf(acc[t][1], w1, ps0));
            pd0 = fmaf(acc[t][0], v0, fmaf(acc[t][1], v1, pd0));
            ps1 = fmaf(acc[t][2], w0, fmaf(acc[t][3], w1, ps1));
            pd1 = fmaf(acc[t][2], v0, fmaf(acc[t][3], v1, pd1));
        }
#pragma unroll
        for (int o = 1; o <= 2; o <<= 1) {
            ps0 += __shfl_xor_sync(0xffffffffu, ps0, o);
            pd0 += __shfl_xor_sync(0xffffffffu, pd0, o);
            ps1 += __shfl_xor_sync(0xffffffffu, ps1, o);
            pd1 += __shfl_xor_sync(0xffffffffu, pd1, o);
        }
        if (tg == 0) {
            if (r0 < NN) { g_as[r0 * HH + h] = ps0; g_ad[r0 * HH + h] = pd0; }
            if (r1 < NN) { g_as[r1 * HH + h] = ps1; g_ad[r1 * HH + h] = pd1; }
        }
    }
}

// ---------------- CSR build ---------------------------------------------------
__global__ void k_count(const int* __restrict__ dst) {
    int e = blockIdx.x * blockDim.x + threadIdx.x;
    if (e < EE) atomicAdd(&g_cnt_i[dst[e]], 1);
}

__global__ void k_scan1() {
    __shared__ int wsum[32];
    int t = threadIdx.x, b = blockIdx.x;
    int i = b * 1024 + t;
    int v = (i < NN) ? g_cnt_i[i] : 0;
    int incl = v;
#pragma unroll
    for (int o = 1; o < 32; o <<= 1) {
        int n = __shfl_up_sync(0xffffffffu, incl, o);
        if ((t & 31) >= o) incl += n;
    }
    if ((t & 31) == 31) wsum[t >> 5] = incl;
    __syncthreads();
    if (t < 32) {
        int wv = wsum[t];
#pragma unroll
        for (int o = 1; o < 32; o <<= 1) {
            int n = __shfl_up_sync(0xffffffffu, wv, o);
            if (t >= o) wv += n;
        }
        wsum[t] = wv;
    }
    __syncthreads();
    int excl = incl - v + ((t >= 32) ? wsum[(t >> 5) - 1] : 0);
    if (i < NN) g_rowptr[i] = excl;
    if (t == 1023) g_bsum[b] = excl + v;
}

__global__ void k_scan2() {
    __shared__ int w0s;
    int t = threadIdx.x;
    int v = (t < NB_SCAN) ? g_bsum[t] : 0;
    int incl = v;
#pragma unroll
    for (int o = 1; o < 32; o <<= 1) {
        int n = __shfl_up_sync(0xffffffffu, incl, o);
        if ((t & 31) >= o) incl += n;
    }
    if (t == 31) w0s = incl;
    __syncthreads();
    if (t >= 32) incl += w0s;
    if (t < NB_SCAN) g_boff[t] = incl - v;
}

__global__ void k_scan3() {
    int i = blockIdx.x * blockDim.x + threadIdx.x;
    if (i < NN) {
        int v = g_rowptr[i] + g_boff[i >> 10];
        g_rowptr[i] = v;
        g_cursor[i] = v;
    }
    if (i == 0) g_rowptr[NN] = EE;
}

__global__ void k_fill(const int* __restrict__ src, const int* __restrict__ dst) {
    int e = blockIdx.x * blockDim.x + threadIdx.x;
    if (e >= EE) return;
    int pos = atomicAdd(&g_cursor[dst[e]], 1);
    g_csrc[pos] = src[e];
}

// ---------------- fused GAT aggregation: 4 edges/warp-iter, 8 lanes/edge ------
// lane = g*8 + l : group g handles edge stream (base+g), sub-lane l covers
// features [16l, 16l+16) (one head: hd = l>>1). Cross-group butterfly at end.
__global__ void k_gat_aggr(const float* __restrict__ bias) {
    int w = (blockIdx.x * blockDim.x + threadIdx.x) >> 5;
    if (w >= NN) return;
    int lane = threadIdx.x & 31;
    int g = lane >> 3, l = lane & 7;
    int hd = l >> 1;
    int row0 = g_rowptr[w], row1 = g_rowptr[w + 1];
    float ad_l = g_ad[w * HH + hd];
    const uint4* HV4 = reinterpret_cast<const uint4*>(g_h16);
    float acc[16];
#pragma unroll
    for (int i = 0; i < 16; i++) acc[i] = 0.f;
    float z = 0.f;
    for (int base = row0; base < row1; base += 4) {
        int e = base + g;
        bool valid = e < row1;
        int s = valid ? g_csrc[e] : 0;
        float as_l = g_as[s * HH + hd];
        uint4 q0 = HV4[(size_t)s * 16 + l * 2];
        uint4 q1 = HV4[(size_t)s * 16 + l * 2 + 1];
        float wgt = valid ? __expf(lrelu(as_l + ad_l)) : 0.f;
        z += wgt;
        const uint32_t* qa = &q0.x;
        const uint32_t* qb = &q1.x;
#pragma unroll
        for (int j = 0; j < 4; j++) {
            float2 fa = __half22float2(*reinterpret_cast<const __half2*>(&qa[j]));
            float2 fb = __half22float2(*reinterpret_cast<const __half2*>(&qb[j]));
            acc[2 * j]     = fmaf(wgt, fa.x, acc[2 * j]);
            acc[2 * j + 1] = fmaf(wgt, fa.y, acc[2 * j + 1]);
            acc[8 + 2 * j]     = fmaf(wgt, fb.x, acc[8 + 2 * j]);
            acc[8 + 2 * j + 1] = fmaf(wgt, fb.y, acc[8 + 2 * j + 1]);
        }
    }
    // reduce across the 4 groups (xor 8 then 16 leaves l unchanged)
#pragma unroll
    for (int o = 8; o <= 16; o <<= 1) {
        z += __shfl_xor_sync(0xffffffffu, z, o);
#pragma unroll
        for (int i = 0; i < 16; i++)
            acc[i] += __shfl_xor_sync(0xffffffffu, acc[i], o);
    }
    // self loop (added once, post-reduction; all 4 copies stay identical)
    float as_self = g_as[w * HH + hd];
    float wsf = __expf(lrelu(as_self + ad_l));
    z += wsf;
    {
        uint4 q0 = HV4[(size_t)w * 16 + l * 2];
        uint4 q1 = HV4[(size_t)w * 16 + l * 2 + 1];
        const uint32_t* qa = &q0.x;
        const uint32_t* qb = &q1.x;
#pragma unroll
        for (int j = 0; j < 4; j++) {
            float2 fa = __half22float2(*reinterpret_cast<const __half2*>(&qa[j]));
            float2 fb = __half22float2(*reinterpret_cast<const __half2*>(&qb[j]));
            acc[2 * j]     = fmaf(wsf, fa.x, acc[2 * j]);
            acc[2 * j + 1] = fmaf(wsf, fa.y, acc[2 * j + 1]);
            acc[8 + 2 * j]     = fmaf(wsf, fb.x, acc[8 + 2 * j]);
            acc[8 + 2 * j + 1] = fmaf(wsf, fb.y, acc[8 + 2 * j + 1]);
        }
    }
    float inv = 1.f / (z + 1e-16f);
    // each lane writes one float4: j4 = l*4 + g -> features 16l+4g..+4 (= acc[4g..])
    int j4 = l * 4 + g;
    int fo = 4 * g;
    float4 b = reinterpret_cast<const float4*>(bias)[j4];
    float4 r;
    r.x = fmaxf(acc[fo + 0] * inv + b.x, 0.f);
    r.y = fmaxf(acc[fo + 1] * inv + b.y, 0.f);
    r.z = fmaxf(acc[fo + 2] * inv + b.z, 0.f);
    r.w = fmaxf(acc[fo + 3] * inv + b.w, 0.f);
    reinterpret_cast<float4*>(g_x)[w * 32 + j4] = r;
}

// ---------------- GraphConv epilogue: Y = relu(gather(P) + Q + bias) ----------
__global__ void k_gc_final(const float* __restrict__ P, const float* __restrict__ Q,
                           const float* __restrict__ bias, float* __restrict__ Y) {
    int q = (blockIdx.x * blockDim.x + threadIdx.x) >> 3;
    if (q >= NN) return;
    int lane = threadIdx.x & 7;
    int row0 = g_rowptr[q], row1 = g_rowptr[q + 1];
    const float4* P4 = reinterpret_cast<const float4*>(P);
    float4 acc = make_float4(0.f, 0.f, 0.f, 0.f);
    int s = (row0 < row1) ? g_csrc[row0] : 0;
    for (int k = row0; k < row1; k++) {
        int s_next = (k + 1 < row1) ? g_csrc[k + 1] : 0;
        float4 p = P4[s * 8 + lane];
        acc.x += p.x; acc.y += p.y; acc.z += p.z; acc.w += p.w;
        s = s_next;
    }
    float4 qq = reinterpret_cast<const float4*>(Q)[q * 8 + lane];
    float4 bb = reinterpret_cast<const float4*>(bias)[lane];
    float4 r;
    r.x = fmaxf(acc.x + qq.x + bb.x, 0.f);
    r.y = fmaxf(acc.y + qq.y + bb.y, 0.f);
    r.z = fmaxf(acc.z + qq.z + bb.z, 0.f);
    r.w = fmaxf(acc.w + qq.w + bb.w, 0.f);
    reinterpret_cast<float4*>(Y)[q * 8 + lane] = r;
}

// ---------------- SAGE epilogue + pool: pool += relu(mean(P) + Q + bias) ------
__global__ void k_sage_final(const float* __restrict__ P, const float* __restrict__ Q,
                             const float* __restrict__ bias,
                             const int* __restrict__ batch) {
    int q = (blockIdx.x * blockDim.x + threadIdx.x) >> 3;
    if (q >= NN) return;
    int lane = threadIdx.x & 7;
    int row0 = g_rowptr[q], row1 = g_rowptr[q + 1];
    const float4* P4 = reinterpret_cast<const float4*>(P);
    float4 acc = make_float4(0.f, 0.f, 0.f, 0.f);
    int s = (row0 < row1) ? g_csrc[row0] : 0;
    for (int k = row0; k < row1; k++) {
        int s_next = (k + 1 < row1) ? g_csrc[k + 1] : 0;
        float4 p = P4[s * 8 + lane];
        acc.x += p.x; acc.y += p.y; acc.z += p.z; acc.w += p.w;
        s = s_next;
    }
    float inv = 1.f / fmaxf((float)(row1 - row0), 1.f);
    float4 qq = reinterpret_cast<const float4*>(Q)[q * 8 + lane];
    float4 bb = reinterpret_cast<const float4*>(bias)[lane];
    float4 r;
    r.x = fmaxf(fmaf(acc.x, inv, qq.x) + bb.x, 0.f);
    r.y = fmaxf(fmaf(acc.y, inv, qq.y) + bb.y, 0.f);
    r.z = fmaxf(fmaf(acc.z, inv, qq.z) + bb.z, 0.f);
    r.w = fmaxf(fmaf(acc.w, inv, qq.w) + bb.w, 0.f);
    int b = batch[q];
    atomicAdd(reinterpret_cast<float4*>(g_pool) + b * 8 + lane, r);
    if (lane == 0) atomicAdd(&g_cnt[b], 1.f);
}

// ---------------- fused dual projection: Ya = X@Wa, Yb = X@Wb ----------------
template <int FIN>
__global__ __launch_bounds__(256) void k_proj2(
    const float* __restrict__ X, const float* __restrict__ Wa,
    const float* __restrict__ Wb, float* __restrict__ Ya, float* __restrict__ Yb) {
    __shared__ float Xs[64][FIN];
    int t = threadIdx.x, tx = t & 31, ty = t >> 5;
    int row0 = blockIdx.x * 64;
    const float4* Xg = reinterpret_cast<const float4*>(X);
    for (int i = t; i < 64 * (FIN / 4); i += 256) {
        int r = i / (FIN / 4), kq = i % (FIN / 4);
        int row = row0 + r;
        float4 v = (row < NN) ? Xg[row * (FIN / 4) + kq] : make_float4(0.f, 0.f, 0.f, 0.f);
        *reinterpret_cast<float4*>(&Xs[r][kq * 4]) = v;
    }
    __syncthreads();
    float a[8], b[8];
#pragma unroll
    for (int r = 0; r < 8; r++) { a[r] = 0.f; b[r] = 0.f; }
#pragma unroll 4
    for (int k = 0; k < FIN; k++) {
        float wa = __ldg(&Wa[k * CC + tx]);
        float wb = __ldg(&Wb[k * CC + tx]);
#pragma unroll
        for (int r = 0; r < 8; r++) {
            float xv = Xs[ty * 8 + r][k];
            a[r] = fmaf(xv, wa, a[r]);
            b[r] = fmaf(xv, wb, b[r]);
        }
    }
#pragma unroll
    for (int r = 0; r < 8; r++) {
        int row = row0 + ty * 8 + r;
        if (row < NN) {
            Ya[row * CC + tx] = a[r];
            Yb[row * CC + tx] = b[r];
        }
    }
}

// ---------------- MLP head (single tiny block) -------------------------------
__global__ void k_head(const float* __restrict__ Wf1, const float* __restrict__ bf1,
                       const float* __restrict__ Wf2, const float* __restrict__ bf2,
                       float* __restrict__ out) {
    __shared__ float t1[NGR * CC];
    int t = threadIdx.x;
    for (int idx = t; idx < NGR * CC; idx += blockDim.x) {
        int g = idx >> 5, c = idx & 31;
        float inv = 1.f / fmaxf(g_cnt[g], 1.f);
        float s = 0.f;
#pragma unroll
        for (int k = 0; k < CC; k++) s = fmaf(g_pool[g * CC + k] * inv, Wf1[k * CC + c], s);
        t1[idx] = fmaxf(s + bf1[c], 0.f);
    }
    __syncthreads();
    for (int idx = t; idx < NGR * NOUT; idx += blockDim.x) {
        int g = idx / NOUT, o = idx - g * NOUT;
        float s = 0.f;
#pragma unroll
        for (int k = 0; k < CC; k++) s = fmaf(t1[g * CC + k], Wf2[k * NOUT + o], s);
        out[idx] = s + bf2[o];
    }
}

// =============================================================================
extern "C" void kernel_launch(void* const* d_in, const int* in_sizes, int n_in,
                              void* d_out, int out_size) {
    const float* x   = (const float*)d_in[0];
    const int*   ei  = (const int*)d_in[1];
    const int*   bat = (const int*)d_in[2];
    const float* W1  = (const float*)d_in[3];
    const float* as1 = (const float*)d_in[4];
    const float* ad1 = (const float*)d_in[5];
    const float* b1  = (const float*)d_in[6];
    const float* W2  = (const float*)d_in[7];
    const float* as2 = (const float*)d_in[8];
    const float* ad2 = (const float*)d_in[9];
    const float* b2  = (const float*)d_in[10];
    const float* W3r = (const float*)d_in[11];
    const float* W3l = (const float*)d_in[12];
    const float* b3  = (const float*)d_in[13];
    const float* W4l = (const float*)d_in[14];
    const float* b4l = (const float*)d_in[15];
    const float* W4r = (const float*)d_in[16];
    const float* Wf1 = (const float*)d_in[17];
    const float* bf1 = (const float*)d_in[18];
    const float* Wf2 = (const float*)d_in[19];
    const float* bf2 = (const float*)d_in[20];
    const int* src = ei;
    const int* dst = ei + EE;
    float* out = (float*)d_out;

    static float *p_h = nullptr, *p_acc, *p_x, *p_pool, *p_cnt;
    static int* p_cnt_i;
    static bool init_done = false;
    static cudaStream_t s2;
    static cudaEvent_t e1, e2;
    if (!p_h) {
        cudaGetSymbolAddress((void**)&p_h, g_h);
        cudaGetSymbolAddress((void**)&p_acc, g_acc);
        cudaGetSymbolAddress((void**)&p_x, g_x);
        cudaGetSymbolAddress((void**)&p_pool, g_pool);
        cudaGetSymbolAddress((void**)&p_cnt, g_cnt);
        cudaGetSymbolAddress((void**)&p_cnt_i, g_cnt_i);
    }
    if (!init_done) {
        cudaFuncSetAttribute(k_gemm128mma, cudaFuncAttributeMaxDynamicSharedMemorySize, SMEM_MMA);
        cudaStreamCreateWithFlags(&s2, cudaStreamNonBlocking);
        cudaEventCreateWithFlags(&e1, cudaEventDisableTiming);
        cudaEventCreateWithFlags(&e2, cudaEventDisableTiming);
        init_done = true;
    }

    const int T = 256;
    const int gE    = (EE + T - 1) / T;
    const int gWNN  = (NN * 32 + T - 1) / T;   // warp per node
    const int gQ8   = (NN * 8 + T - 1) / T;    // 8 lanes per node
    const int gR64  = (NN + 63) / 64;          // 64-row tiles
    const int gTC   = (NN + 63) / 64;          // 64-row MMA tiles

    // ---- fork: CSR build on side stream, overlapped with W prep + GEMM1 ----
    cudaEventRecord(e1, 0);
    cudaStreamWaitEvent(s2, e1, 0);
    cudaMemsetAsync(p_cnt_i, 0, NN * sizeof(int), s2);
    k_count<<<gE, T, 0, s2>>>(dst);
    k_scan1<<<NB_SCAN, 1024, 0, s2>>>();
    k_scan2<<<1, 64, 0, s2>>>();
    k_scan3<<<(NN + 1023) / 1024, 1024, 0, s2>>>();
    k_fill<<<gE, T, 0, s2>>>(src, dst);
    cudaMemsetAsync(p_pool, 0, NGR * CC * sizeof(float), s2);
    cudaMemsetAsync(p_cnt, 0, NGR * sizeof(float), s2);
    cudaEventRecord(e2, s2);

    // main stream: W prep + GAT layer-1 GEMM (independent of CSR)
    {
        dim3 gp((HC * HC + T - 1) / T, 2);
        k_prepWt2<<<gp, T>>>(W1, W2);
    }
    k_gemm128mma<<<gTC, 256, SMEM_MMA>>>(x, 0, as1, ad1);
    cudaStreamWaitEvent(0, e2, 0);     // CSR + pool-zero ready

    // ---- GAT layer 1 aggregation ----
    k_gat_aggr<<<gWNN, T>>>(b1);

    // ---- GAT layer 2 ----
    k_gemm128mma<<<gTC, 256, SMEM_MMA>>>(p_x, 1, as2, ad2);
    k_gat_aggr<<<gWNN, T>>>(b2);

    // ---- GraphConv: x3 = relu(segsum((x2@W3r)[src]) + x2@W3l + b3) ----
    k_proj2<HC><<<gR64, 256>>>(p_x, W3r, W3l, p_acc, p_h);    // Ya=g_acc, Yb=g_h
    k_gc_final<<<gQ8, T>>>(p_acc, p_h, b3, p_x);              // x3 -> g_x

    // ---- SAGEConv + pool: pool += relu(mean((x3@W4l)[src]) + x3@W4r + b4l) ----
    k_proj2<CC><<<gR64, 256>>>(p_x, W4l, W4r, p_acc, p_h);    // Ya=g_acc, Yb=g_h
    k_sage_final<<<gQ8, T>>>(p_acc, p_h, b4l, bat);           // pool atomics

    // ---- head ----
    k_head<<<1, 1024>>>(Wf1, bf1, Wf2, bf2, out);
}

// round 14
// speedup vs baseline: 1.3682x; 1.0592x over previous
#include <cuda_runtime.h>
#include <cuda_bf16.h>
#include <cuda_fp16.h>
#include <cstdint>

#define NN   50000
#define EE   800000
#define HH   4
#define CC   32
#define HC   128
#define NGR  64
#define NOUT 10
#define NB_SCAN 49   // ceil(NN/1024)
#define STR  68      // smem row stride in 32-bit words

// ---------------- scratch (device globals; no allocation allowed) ------------
__device__ float g_h[NN * HC];          // proj scratch (GraphConv/SAGE)
__device__ uint32_t g_h16[NN * 64];     // GAT h in half2 (64 words = 128 halves/row)
__device__ float g_acc[NN * HC];
__device__ float g_x[NN * HC];
__device__ float g_as[NN * HH];
__device__ float g_ad[NN * HH];
__device__ float g_pool[NGR * CC];
__device__ float g_cnt[NGR];
// CSR by destination
__device__ int g_cnt_i[NN];
__device__ int g_rowptr[NN + 1];
__device__ int g_cursor[NN];
__device__ int g_csrc[EE];
__device__ int g_bsum[NB_SCAN];
__device__ int g_boff[NB_SCAN];
// bf16-split transposed weights Wt[n][k] per GAT layer
__device__ __align__(16) unsigned short g_WtHi[2][HC * HC];
__device__ __align__(16) unsigned short g_WtLo[2][HC * HC];
// bf16-split concatenated projection weights [64 out][K in] transposed
__device__ __align__(16) unsigned short g_W3Hi[64 * HC];
__device__ __align__(16) unsigned short g_W3Lo[64 * HC];
__device__ __align__(16) unsigned short g_W4Hi[64 * CC];
__device__ __align__(16) unsigned short g_W4Lo[64 * CC];

__device__ __forceinline__ float lrelu(float v) { return v > 0.f ? v : 0.2f * v; }
__device__ __forceinline__ uint32_t pack_h2(float a, float b) {
    __half2 h = __floats2half2_rn(a, b);
    return *reinterpret_cast<uint32_t*>(&h);
}
__device__ __forceinline__ void bf16split(float v, unsigned short& hi, unsigned short& lo) {
    __nv_bfloat16 hb = __float2bfloat16(v);
    __nv_bfloat16 lb = __float2bfloat16(v - __bfloat162float(hb));
    hi = __bfloat16_as_ushort(hb);
    lo = __bfloat16_as_ushort(lb);
}

// ---------------- W -> bf16 hi/lo transposed prep (GAT layers) ----------------
__global__ void k_prepWt2(const float* __restrict__ W1, const float* __restrict__ W2) {
    int i = blockIdx.x * blockDim.x + threadIdx.x;  // i = k*128 + n
    if (i >= HC * HC) return;
    int layer = blockIdx.y;
    const float* W = layer ? W2 : W1;
    int k = i >> 7, n = i & 127;
    unsigned short hi, lo;
    bf16split(W[i], hi, lo);
    g_WtHi[layer][n * HC + k] = hi;
    g_WtLo[layer][n * HC + k] = lo;
}

// ---------------- concat proj weights: [K][32]x2 -> [64][K] bf16 split --------
__global__ void k_prepWcat(const float* __restrict__ Wa, const float* __restrict__ Wb,
                           int K, int sel) {
    int i = blockIdx.x * blockDim.x + threadIdx.x;  // i = k*64 + n
    if (i >= K * 64) return;
    int k = i >> 6, n = i & 63;
    float w = (n < 32) ? Wa[k * 32 + n] : Wb[k * 32 + (n - 32)];
    unsigned short hi, lo;
    bf16split(w, hi, lo);
    if (sel == 0) { g_W3Hi[n * K + k] = hi; g_W3Lo[n * K + k] = lo; }
    else          { g_W4Hi[n * K + k] = hi; g_W4Lo[n * K + k] = lo; }
}

// ---------------- mma.sync bf16-split GEMM (64-row tiles, occ 2) --------------
#define MMA_BF16(c, A0, A1, A2, A3, B0, B1) \
    asm volatile("mma.sync.aligned.m16n8k16.row.col.f32.bf16.bf16.f32 " \
        "{%0,%1,%2,%3}, {%4,%5,%6,%7}, {%8,%9}, {%0,%1,%2,%3};" \
        : "+f"((c)[0]), "+f"((c)[1]), "+f"((c)[2]), "+f"((c)[3]) \
        : "r"(A0), "r"(A1), "r"(A2), "r"(A3), "r"(B0), "r"(B1))

// smem: xh 64*STR | xl 64*STR | wh 128*STR | wl 128*STR | sws 128f | swd 128f
#define SMEM_MMA ((2 * 64 + 2 * 128) * STR * 4 + 1024)

__global__ __launch_bounds__(256, 2) void k_gemm128mma(
    const float* __restrict__ X, int layer,
    const float* __restrict__ aws, const float* __restrict__ awd) {
    extern __shared__ __align__(16) char smem[];
    uint32_t* xh = reinterpret_cast<uint32_t*>(smem);
    uint32_t* xl = xh + 64 * STR;
    uint32_t* wh = xl + 64 * STR;
    uint32_t* wl = wh + 128 * STR;
    float* sws = reinterpret_cast<float*>(wl + 128 * STR);
    float* swd = sws + 128;
    int tid = threadIdx.x, lane = tid & 31, wid = tid >> 5;
    int gid = lane >> 2, tg = lane & 3;
    int row0 = blockIdx.x * 64;

    if (tid < 128) { sws[tid] = aws[tid]; swd[tid] = awd[tid]; }
    {
        const uint4* gh4 = reinterpret_cast<const uint4*>(g_WtHi[layer]);
        const uint4* gl4 = reinterpret_cast<const uint4*>(g_WtLo[layer]);
        uint4* wh4 = reinterpret_cast<uint4*>(wh);
        uint4* wl4 = reinterpret_cast<uint4*>(wl);
        for (int i = tid; i < 128 * 16; i += 256) {
            int r = i >> 4, q = i & 15;
            wh4[r * 17 + q] = gh4[i];
            wl4[r * 17 + q] = gl4[i];
        }
    }
    {
        const float4* X4 = reinterpret_cast<const float4*>(X);
        for (int i = tid; i < 64 * 32; i += 256) {
            int r = i >> 5, q = i & 31;
            int grow = row0 + r;
            float4 v = (grow < NN) ? X4[(size_t)grow * 32 + q] : make_float4(0.f, 0.f, 0.f, 0.f);
            float vv[4] = {v.x, v.y, v.z, v.w};
#pragma unroll
            for (int q2 = 0; q2 < 2; q2++) {
                unsigned short h0, l0, h1, l1;
                bf16split(vv[2 * q2], h0, l0);
                bf16split(vv[2 * q2 + 1], h1, l1);
                xh[r * STR + 2 * q + q2] = ((uint32_t)h1 << 16) | h0;
                xl[r * STR + 2 * q + q2] = ((uint32_t)l1 << 16) | l0;
            }
        }
    }
    __syncthreads();

    int warpM = (wid & 3) * 16;
    int n0 = (wid >> 2) * 64;
    float acc[8][4];
#pragma unroll
    for (int t = 0; t < 8; t++)
#pragma unroll
        for (int j = 0; j < 4; j++) acc[t][j] = 0.f;

    const uint32_t* xrh = xh + (warpM + gid) * STR + tg;
    const uint32_t* xrl = xl + (warpM + gid) * STR + tg;
#pragma unroll 1
    for (int kk = 0; kk < 8; kk++) {
        int kw = kk * 8;
        uint32_t ah0 = xrh[kw],           ah2 = xrh[kw + 4];
        uint32_t ah1 = xrh[kw + 8 * STR], ah3 = xrh[kw + 8 * STR + 4];
        uint32_t al0 = xrl[kw],           al2 = xrl[kw + 4];
        uint32_t al1 = xrl[kw + 8 * STR], al3 = xrl[kw + 8 * STR + 4];
#pragma unroll
        for (int t = 0; t < 8; t++) {
            const uint32_t* wrh = wh + (n0 + t * 8 + gid) * STR + kw + tg;
            const uint32_t* wrl = wl + (n0 + t * 8 + gid) * STR + kw + tg;
            uint32_t bh0 = wrh[0], bh1 = wrh[4];
            uint32_t bl0 = wrl[0], bl1 = wrl[4];
            MMA_BF16(acc[t], ah0, ah1, ah2, ah3, bh0, bh1);
            MMA_BF16(acc[t], ah0, ah1, ah2, ah3, bl0, bl1);
            MMA_BF16(acc[t], al0, al1, al2, al3, bh0, bh1);
        }
    }

    int r0 = row0 + warpM + gid, r1 = r0 + 8;
#pragma unroll
    for (int t = 0; t < 8; t++) {
        int cidx = (n0 >> 1) + t * 4 + tg;
        if (r0 < NN) g_h16[(size_t)r0 * 64 + cidx] = pack_h2(acc[t][0], acc[t][1]);
        if (r1 < NN) g_h16[(size_t)r1 * 64 + cidx] = pack_h2(acc[t][2], acc[t][3]);
    }
#pragma unroll
    for (int hh = 0; hh < 2; hh++) {
        int h = (n0 >> 5) + hh;
        float ps0 = 0.f, pd0 = 0.f, ps1 = 0.f, pd1 = 0.f;
#pragma unroll
        for (int j = 0; j < 4; j++) {
            int t = hh * 4 + j;
            int col = n0 + t * 8 + 2 * tg;
            float w0 = sws[col], w1 = sws[col + 1];
            float v0 = swd[col], v1 = swd[col + 1];
            ps0 = fmaf(acc[t][0], w0, fmaf(acc[t][1], w1, ps0));
            pd0 = fmaf(acc[t][0], v0, fmaf(acc[t][1], v1, pd0));
            ps1 = fmaf(acc[t][2], w0, fmaf(acc[t][3], w1, ps1));
            pd1 = fmaf(acc[t][2], v0, fmaf(acc[t][3], v1, pd1));
        }
#pragma unroll
        for (int o = 1; o <= 2; o <<= 1) {
            ps0 += __shfl_xor_sync(0xffffffffu, ps0, o);
            pd0 += __shfl_xor_sync(0xffffffffu, pd0, o);
            ps1 += __shfl_xor_sync(0xffffffffu, ps1, o);
            pd1 += __shfl_xor_sync(0xffffffffu, pd1, o);
        }
        if (tg == 0) {
            if (r0 < NN) { g_as[r0 * HH + h] = ps0; g_ad[r0 * HH + h] = pd0; }
            if (r1 < NN) { g_as[r1 * HH + h] = ps1; g_ad[r1 * HH + h] = pd1; }
        }
    }
}

// ---------------- MMA dual projection: Ya = X@Wa, Yb = X@Wb (32 cols each) ----
// smem: xh 64*STR | xl 64*STR | wh 64*STR | wl 64*STR
#define SMEM_PROJ (4 * 64 * STR * 4)

template <int K>
__global__ __launch_bounds__(256, 2) void k_projmma(
    const float* __restrict__ X, float* __restrict__ Ya, float* __restrict__ Yb) {
    extern __shared__ __align__(16) char smem[];
    uint32_t* xh = reinterpret_cast<uint32_t*>(smem);
    uint32_t* xl = xh + 64 * STR;
    uint32_t* wh = xl + 64 * STR;
    uint32_t* wl = wh + 64 * STR;
    int tid = threadIdx.x, lane = tid & 31, wid = tid >> 5;
    int gid = lane >> 2, tg = lane & 3;
    int row0 = blockIdx.x * 64;
    const unsigned short* WHi = (K == HC) ? g_W3Hi : g_W4Hi;
    const unsigned short* WLo = (K == HC) ? g_W3Lo : g_W4Lo;
    // W images: 64 rows x K/2 words
    {
        const uint4* gh4 = reinterpret_cast<const uint4*>(WHi);
        const uint4* gl4 = reinterpret_cast<const uint4*>(WLo);
        uint4* wh4 = reinterpret_cast<uint4*>(wh);
        uint4* wl4 = reinterpret_cast<uint4*>(wl);
        constexpr int WQ = K / 8;
        for (int i = tid; i < 64 * WQ; i += 256) {
            int r = i / WQ, q = i % WQ;
            wh4[r * 17 + q] = gh4[i];
            wl4[r * 17 + q] = gl4[i];
        }
    }
    // X tile: 64 rows x K floats -> bf16 hi/lo
    {
        const float4* X4 = reinterpret_cast<const float4*>(X);
        constexpr int KW = K / 4;
        for (int i = tid; i < 64 * KW; i += 256) {
            int r = i / KW, q = i % KW;
            int grow = row0 + r;
            float4 v = (grow < NN) ? X4[(size_t)grow * KW + q] : make_float4(0.f, 0.f, 0.f, 0.f);
            float vv[4] = {v.x, v.y, v.z, v.w};
#pragma unroll
            for (int q2 = 0; q2 < 2; q2++) {
                unsigned short h0, l0, h1, l1;
                bf16split(vv[2 * q2], h0, l0);
                bf16split(vv[2 * q2 + 1], h1, l1);
                xh[r * STR + 2 * q + q2] = ((uint32_t)h1 << 16) | h0;
                xl[r * STR + 2 * q + q2] = ((uint32_t)l1 << 16) | l0;
            }
        }
    }
    __syncthreads();

    int warpM = (wid & 3) * 16;
    int n0 = (wid >> 2) * 32;    // 0 -> Ya, 32 -> Yb
    float acc[4][4];
#pragma unroll
    for (int t = 0; t < 4; t++)
#pragma unroll
        for (int j = 0; j < 4; j++) acc[t][j] = 0.f;

    const uint32_t* xrh = xh + (warpM + gid) * STR + tg;
    const uint32_t* xrl = xl + (warpM + gid) * STR + tg;
#pragma unroll
    for (int kk = 0; kk < K / 16; kk++) {
        int kw = kk * 8;
        uint32_t ah0 = xrh[kw],           ah2 = xrh[kw + 4];
        uint32_t ah1 = xrh[kw + 8 * STR], ah3 = xrh[kw + 8 * STR + 4];
        uint32_t al0 = xrl[kw],           al2 = xrl[kw + 4];
        uint32_t al1 = xrl[kw + 8 * STR], al3 = xrl[kw + 8 * STR + 4];
#pragma unroll
        for (int t = 0; t < 4; t++) {
            const uint32_t* wrh = wh + (n0 + t * 8 + gid) * STR + kw + tg;
            const uint32_t* wrl = wl + (n0 + t * 8 + gid) * STR + kw + tg;
            uint32_t bh0 = wrh[0], bh1 = wrh[4];
            uint32_t bl0 = wrl[0], bl1 = wrl[4];
            MMA_BF16(acc[t], ah0, ah1, ah2, ah3, bh0, bh1);
            MMA_BF16(acc[t], ah0, ah1, ah2, ah3, bl0, bl1);
            MMA_BF16(acc[t], al0, al1, al2, al3, bh0, bh1);
        }
    }

    float* dst = (n0 == 0) ? Ya : Yb;
    int r0 = row0 + warpM + gid, r1 = r0 + 8;
#pragma unroll
    for (int t = 0; t < 4; t++) {
        int col = t * 8 + 2 * tg;
        if (r0 < NN) *reinterpret_cast<float2*>(&dst[(size_t)r0 * 32 + col]) =
            make_float2(acc[t][0], acc[t][1]);
        if (r1 < NN) *reinterpret_cast<float2*>(&dst[(size_t)r1 * 32 + col]) =
            make_float2(acc[t][2], acc[t][3]);
    }
}

// ---------------- CSR build ---------------------------------------------------
__global__ void k_count(const int* __restrict__ dst) {
    int e = blockIdx.x * blockDim.x + threadIdx.x;
    if (e < EE) atomicAdd(&g_cnt_i[dst[e]], 1);
}

__global__ void k_scan1() {
    __shared__ int wsum[32];
    int t = threadIdx.x, b = blockIdx.x;
    int i = b * 1024 + t;
    int v = (i < NN) ? g_cnt_i[i] : 0;
    int incl = v;
#pragma unroll
    for (int o = 1; o < 32; o <<= 1) {
        int n = __shfl_up_sync(0xffffffffu, incl, o);
        if ((t & 31) >= o) incl += n;
    }
    if ((t & 31) == 31) wsum[t >> 5] = incl;
    __syncthreads();
    if (t < 32) {
        int wv = wsum[t];
#pragma unroll
        for (int o = 1; o < 32; o <<= 1) {
            int n = __shfl_up_sync(0xffffffffu, wv, o);
            if (t >= o) wv += n;
        }
        wsum[t] = wv;
    }
    __syncthreads();
    int excl = incl - v + ((t >= 32) ? wsum[(t >> 5) - 1] : 0);
    if (i < NN) g_rowptr[i] = excl;
    if (t == 1023) g_bsum[b] = excl + v;
}

__global__ void k_scan2() {
    __shared__ int w0s;
    int t = threadIdx.x;
    int v = (t < NB_SCAN) ? g_bsum[t] : 0;
    int incl = v;
#pragma unroll
    for (int o = 1; o < 32; o <<= 1) {
        int n = __shfl_up_sync(0xffffffffu, incl, o);
        if ((t & 31) >= o) incl += n;
    }
    if (t == 31) w0s = incl;
    __syncthreads();
    if (t >= 32) incl += w0s;
    if (t < NB_SCAN) g_boff[t] = incl - v;
}

__global__ void k_scan3() {
    int i = blockIdx.x * blockDim.x + threadIdx.x;
    if (i < NN) {
        int v = g_rowptr[i] + g_boff[i >> 10];
        g_rowptr[i] = v;
        g_cursor[i] = v;
    }
    if (i == 0) g_rowptr[NN] = EE;
}

__global__ void k_fill(const int* __restrict__ src, const int* __restrict__ dst) {
    int e = blockIdx.x * blockDim.x + threadIdx.x;
    if (e >= EE) return;
    int pos = atomicAdd(&g_cursor[dst[e]], 1);
    g_csrc[pos] = src[e];
}

// ---------------- fused GAT aggregation: 4 edges/warp-iter, 8 lanes/edge ------
__global__ void k_gat_aggr(const float* __restrict__ bias) {
    int w = (blockIdx.x * blockDim.x + threadIdx.x) >> 5;
    if (w >= NN) return;
    int lane = threadIdx.x & 31;
    int g = lane >> 3, l = lane & 7;
    int hd = l >> 1;
    int row0 = g_rowptr[w], row1 = g_rowptr[w + 1];
    float ad_l = g_ad[w * HH + hd];
    const uint4* HV4 = reinterpret_cast<const uint4*>(g_h16);
    float acc[16];
#pragma unroll
    for (int i = 0; i < 16; i++) acc[i] = 0.f;
    float z = 0.f;
    for (int base = row0; base < row1; base += 4) {
        int e = base + g;
        bool valid = e < row1;
        int s = valid ? g_csrc[e] : 0;
        float as_l = g_as[s * HH + hd];
        uint4 q0 = HV4[(size_t)s * 16 + l * 2];
        uint4 q1 = HV4[(size_t)s * 16 + l * 2 + 1];
        float wgt = valid ? __expf(lrelu(as_l + ad_l)) : 0.f;
        z += wgt;
        const uint32_t* qa = &q0.x;
        const uint32_t* qb = &q1.x;
#pragma unroll
        for (int j = 0; j < 4; j++) {
            float2 fa = __half22float2(*reinterpret_cast<const __half2*>(&qa[j]));
            float2 fb = __half22float2(*reinterpret_cast<const __half2*>(&qb[j]));
            acc[2 * j]     = fmaf(wgt, fa.x, acc[2 * j]);
            acc[2 * j + 1] = fmaf(wgt, fa.y, acc[2 * j + 1]);
            acc[8 + 2 * j]     = fmaf(wgt, fb.x, acc[8 + 2 * j]);
            acc[8 + 2 * j + 1] = fmaf(wgt, fb.y, acc[8 + 2 * j + 1]);
        }
    }
#pragma unroll
    for (int o = 8; o <= 16; o <<= 1) {
        z += __shfl_xor_sync(0xffffffffu, z, o);
#pragma unroll
        for (int i = 0; i < 16; i++)
            acc[i] += __shfl_xor_sync(0xffffffffu, acc[i], o);
    }
    float as_self = g_as[w * HH + hd];
    float wsf = __expf(lrelu(as_self + ad_l));
    z += wsf;
    {
        uint4 q0 = HV4[(size_t)w * 16 + l * 2];
        uint4 q1 = HV4[(size_t)w * 16 + l * 2 + 1];
        const uint32_t* qa = &q0.x;
        const uint32_t* qb = &q1.x;
#pragma unroll
        for (int j = 0; j < 4; j++) {
            float2 fa = __half22float2(*reinterpret_cast<const __half2*>(&qa[j]));
            float2 fb = __half22float2(*reinterpret_cast<const __half2*>(&qb[j]));
            acc[2 * j]     = fmaf(wsf, fa.x, acc[2 * j]);
            acc[2 * j + 1] = fmaf(wsf, fa.y, acc[2 * j + 1]);
            acc[8 + 2 * j]     = fmaf(wsf, fb.x, acc[8 + 2 * j]);
            acc[8 + 2 * j + 1] = fmaf(wsf, fb.y, acc[8 + 2 * j + 1]);
        }
    }
    float inv = 1.f / (z + 1e-16f);
    int j4 = l * 4 + g;
    int fo = 4 * g;
    float4 b = reinterpret_cast<const float4*>(bias)[j4];
    float4 r;
    r.x = fmaxf(acc[fo + 0] * inv + b.x, 0.f);
    r.y = fmaxf(acc[fo + 1] * inv + b.y, 0.f);
    r.z = fmaxf(acc[fo + 2] * inv + b.z, 0.f);
    r.w = fmaxf(acc[fo + 3] * inv + b.w, 0.f);
    reinterpret_cast<float4*>(g_x)[w * 32 + j4] = r;
}

// ---------------- GraphConv epilogue: Y = relu(gather(P) + Q + bias) ----------
__global__ void k_gc_final(const float* __restrict__ P, const float* __restrict__ Q,
                           const float* __restrict__ bias, float* __restrict__ Y) {
    int q = (blockIdx.x * blockDim.x + threadIdx.x) >> 3;
    if (q >= NN) return;
    int lane = threadIdx.x & 7;
    int row0 = g_rowptr[q], row1 = g_rowptr[q + 1];
    const float4* P4 = reinterpret_cast<const float4*>(P);
    float4 acc = make_float4(0.f, 0.f, 0.f, 0.f);
    int s = (row0 < row1) ? g_csrc[row0] : 0;
    for (int k = row0; k < row1; k++) {
        int s_next = (k + 1 < row1) ? g_csrc[k + 1] : 0;
        float4 p = P4[s * 8 + lane];
        acc.x += p.x; acc.y += p.y; acc.z += p.z; acc.w += p.w;
        s = s_next;
    }
    float4 qq = reinterpret_cast<const float4*>(Q)[q * 8 + lane];
    float4 bb = reinterpret_cast<const float4*>(bias)[lane];
    float4 r;
    r.x = fmaxf(acc.x + qq.x + bb.x, 0.f);
    r.y = fmaxf(acc.y + qq.y + bb.y, 0.f);
    r.z = fmaxf(acc.z + qq.z + bb.z, 0.f);
    r.w = fmaxf(acc.w + qq.w + bb.w, 0.f);
    reinterpret_cast<float4*>(Y)[q * 8 + lane] = r;
}

// ---------------- SAGE epilogue + pool: pool += relu(mean(P) + Q + bias) ------
__global__ void k_sage_final(const float* __restrict__ P, const float* __restrict__ Q,
                             const float* __restrict__ bias,
                             const int* __restrict__ batch) {
    int q = (blockIdx.x * blockDim.x + threadIdx.x) >> 3;
    if (q >= NN) return;
    int lane = threadIdx.x & 7;
    int row0 = g_rowptr[q], row1 = g_rowptr[q + 1];
    const float4* P4 = reinterpret_cast<const float4*>(P);
    float4 acc = make_float4(0.f, 0.f, 0.f, 0.f);
    int s = (row0 < row1) ? g_csrc[row0] : 0;
    for (int k = row0; k < row1; k++) {
        int s_next = (k + 1 < row1) ? g_csrc[k + 1] : 0;
        float4 p = P4[s * 8 + lane];
        acc.x += p.x; acc.y += p.y; acc.z += p.z; acc.w += p.w;
        s = s_next;
    }
    float inv = 1.f / fmaxf((float)(row1 - row0), 1.f);
    float4 qq = reinterpret_cast<const float4*>(Q)[q * 8 + lane];
    float4 bb = reinterpret_cast<const float4*>(bias)[lane];
    float4 r;
    r.x = fmaxf(fmaf(acc.x, inv, qq.x) + bb.x, 0.f);
    r.y = fmaxf(fmaf(acc.y, inv, qq.y) + bb.y, 0.f);
    r.z = fmaxf(fmaf(acc.z, inv, qq.z) + bb.z, 0.f);
    r.w = fmaxf(fmaf(acc.w, inv, qq.w) + bb.w, 0.f);
    int b = batch[q];
    atomicAdd(reinterpret_cast<float4*>(g_pool) + b * 8 + lane, r);
    if (lane == 0) atomicAdd(&g_cnt[b], 1.f);
}

// ---------------- MLP head (single tiny block) -------------------------------
__global__ void k_head(const float* __restrict__ Wf1, const float* __restrict__ bf1,
                       const float* __restrict__ Wf2, const float* __restrict__ bf2,
                       float* __restrict__ out) {
    __shared__ float t1[NGR * CC];
    int t = threadIdx.x;
    for (int idx = t; idx < NGR * CC; idx += blockDim.x) {
        int g = idx >> 5, c = idx & 31;
        float inv = 1.f / fmaxf(g_cnt[g], 1.f);
        float s = 0.f;
#pragma unroll
        for (int k = 0; k < CC; k++) s = fmaf(g_pool[g * CC + k] * inv, Wf1[k * CC + c], s);
        t1[idx] = fmaxf(s + bf1[c], 0.f);
    }
    __syncthreads();
    for (int idx = t; idx < NGR * NOUT; idx += blockDim.x) {
        int g = idx / NOUT, o = idx - g * NOUT;
        float s = 0.f;
#pragma unroll
        for (int k = 0; k < CC; k++) s = fmaf(t1[g * CC + k], Wf2[k * NOUT + o], s);
        out[idx] = s + bf2[o];
    }
}

// =============================================================================
extern "C" void kernel_launch(void* const* d_in, const int* in_sizes, int n_in,
                              void* d_out, int out_size) {
    const float* x   = (const float*)d_in[0];
    const int*   ei  = (const int*)d_in[1];
    const int*   bat = (const int*)d_in[2];
    const float* W1  = (const float*)d_in[3];
    const float* as1 = (const float*)d_in[4];
    const float* ad1 = (const float*)d_in[5];
    const float* b1  = (const float*)d_in[6];
    const float* W2  = (const float*)d_in[7];
    const float* as2 = (const float*)d_in[8];
    const float* ad2 = (const float*)d_in[9];
    const float* b2  = (const float*)d_in[10];
    const float* W3r = (const float*)d_in[11];
    const float* W3l = (const float*)d_in[12];
    const float* b3  = (const float*)d_in[13];
    const float* W4l = (const float*)d_in[14];
    const float* b4l = (const float*)d_in[15];
    const float* W4r = (const float*)d_in[16];
    const float* Wf1 = (const float*)d_in[17];
    const float* bf1 = (const float*)d_in[18];
    const float* Wf2 = (const float*)d_in[19];
    const float* bf2 = (const float*)d_in[20];
    const int* src = ei;
    const int* dst = ei + EE;
    float* out = (float*)d_out;

    static float *p_h = nullptr, *p_acc, *p_x, *p_pool, *p_cnt;
    static int* p_cnt_i;
    static bool init_done = false;
    static cudaStream_t s2;
    static cudaEvent_t e1, e2;
    if (!p_h) {
        cudaGetSymbolAddress((void**)&p_h, g_h);
        cudaGetSymbolAddress((void**)&p_acc, g_acc);
        cudaGetSymbolAddress((void**)&p_x, g_x);
        cudaGetSymbolAddress((void**)&p_pool, g_pool);
        cudaGetSymbolAddress((void**)&p_cnt, g_cnt);
        cudaGetSymbolAddress((void**)&p_cnt_i, g_cnt_i);
    }
    if (!init_done) {
        cudaFuncSetAttribute(k_gemm128mma, cudaFuncAttributeMaxDynamicSharedMemorySize, SMEM_MMA);
        cudaFuncSetAttribute(k_projmma<HC>, cudaFuncAttributeMaxDynamicSharedMemorySize, SMEM_PROJ);
        cudaFuncSetAttribute(k_projmma<CC>, cudaFuncAttributeMaxDynamicSharedMemorySize, SMEM_PROJ);
        cudaStreamCreateWithFlags(&s2, cudaStreamNonBlocking);
        cudaEventCreateWithFlags(&e1, cudaEventDisableTiming);
        cudaEventCreateWithFlags(&e2, cudaEventDisableTiming);
        init_done = true;
    }

    const int T = 256;
    const int gE    = (EE + T - 1) / T;
    const int gWNN  = (NN * 32 + T - 1) / T;   // warp per node
    const int gQ8   = (NN * 8 + T - 1) / T;    // 8 lanes per node
    const int gR64  = (NN + 63) / 64;          // 64-row tiles

    // ---- fork: CSR build on side stream, overlapped with W prep + GEMM1 ----
    cudaEventRecord(e1, 0);
    cudaStreamWaitEvent(s2, e1, 0);
    cudaMemsetAsync(p_cnt_i, 0, NN * sizeof(int), s2);
    k_count<<<gE, T, 0, s2>>>(dst);
    k_scan1<<<NB_SCAN, 1024, 0, s2>>>();
    k_scan2<<<1, 64, 0, s2>>>();
    k_scan3<<<(NN + 1023) / 1024, 1024, 0, s2>>>();
    k_fill<<<gE, T, 0, s2>>>(src, dst);
    cudaMemsetAsync(p_pool, 0, NGR * CC * sizeof(float), s2);
    cudaMemsetAsync(p_cnt, 0, NGR * sizeof(float), s2);
    cudaEventRecord(e2, s2);

    // main stream: W prep + GAT layer-1 GEMM (independent of CSR)
    {
        dim3 gp((HC * HC + T - 1) / T, 2);
        k_prepWt2<<<gp, T>>>(W1, W2);
    }
    k_prepWcat<<<(HC * 64 + T - 1) / T, T>>>(W3r, W3l, HC, 0);
    k_prepWcat<<<(CC * 64 + T - 1) / T, T>>>(W4l, W4r, CC, 1);
    k_gemm128mma<<<gR64, 256, SMEM_MMA>>>(x, 0, as1, ad1);
    cudaStreamWaitEvent(0, e2, 0);     // CSR + pool-zero ready

    // ---- GAT layer 1 aggregation ----
    k_gat_aggr<<<gWNN, T>>>(b1);

    // ---- GAT layer 2 ----
    k_gemm128mma<<<gR64, 256, SMEM_MMA>>>(p_x, 1, as2, ad2);
    k_gat_aggr<<<gWNN, T>>>(b2);

    // ---- GraphConv: x3 = relu(segsum((x2@W3r)[src]) + x2@W3l + b3) ----
    k_projmma<HC><<<gR64, 256, SMEM_PROJ>>>(p_x, p_acc, p_h);   // Ya=g_acc, Yb=g_h
    k_gc_final<<<gQ8, T>>>(p_acc, p_h, b3, p_x);                // x3 -> g_x

    // ---- SAGEConv + pool: pool += relu(mean((x3@W4l)[src]) + x3@W4r + b4l) ----
    k_projmma<CC><<<gR64, 256, SMEM_PROJ>>>(p_x, p_acc, p_h);   // Ya=g_acc, Yb=g_h
    k_sage_final<<<gQ8, T>>>(p_acc, p_h, b4l, bat);             // pool atomics

    // ---- head ----
    k_head<<<1, 1024>>>(Wf1, bf1, Wf2, bf2, out);
}

// round 15
// speedup vs baseline: 1.4045x; 1.0265x over previous
#include <cuda_runtime.h>
#include <cuda_bf16.h>
#include <cuda_fp16.h>
#include <cstdint>

#define NN   50000
#define EE   800000
#define HH   4
#define CC   32
#define HC   128
#define NGR  64
#define NOUT 10
#define NB_SCAN 49   // ceil(NN/1024)
#define STR  68      // smem row stride in 32-bit words

// ---------------- scratch (device globals; no allocation allowed) ------------
__device__ float g_h[NN * HC];          // (spare fp32 scratch)
__device__ uint32_t g_h16[NN * 64];     // GAT h (half2); later P/Q fp16 images
__device__ float g_acc[NN * HC];
__device__ float g_x[NN * HC];
__device__ float g_as[NN * HH];
__device__ float g_ad[NN * HH];
__device__ float g_pool[NGR * CC];
__device__ float g_cnt[NGR];
// CSR by destination
__device__ int g_cnt_i[NN];
__device__ int g_rowptr[NN + 1];
__device__ int g_cursor[NN];
__device__ int g_csrc[EE];
__device__ int g_bsum[NB_SCAN];
__device__ int g_boff[NB_SCAN];
// bf16-split transposed weights Wt[n][k] per GAT layer
__device__ __align__(16) unsigned short g_WtHi[2][HC * HC];
__device__ __align__(16) unsigned short g_WtLo[2][HC * HC];
// bf16-split concatenated projection weights [64 out][K in] transposed
__device__ __align__(16) unsigned short g_W3Hi[64 * HC];
__device__ __align__(16) unsigned short g_W3Lo[64 * HC];
__device__ __align__(16) unsigned short g_W4Hi[64 * CC];
__device__ __align__(16) unsigned short g_W4Lo[64 * CC];

__device__ __forceinline__ float lrelu(float v) { return v > 0.f ? v : 0.2f * v; }
__device__ __forceinline__ uint32_t pack_h2(float a, float b) {
    __half2 h = __floats2half2_rn(a, b);
    return *reinterpret_cast<uint32_t*>(&h);
}
__device__ __forceinline__ void bf16split(float v, unsigned short& hi, unsigned short& lo) {
    __nv_bfloat16 hb = __float2bfloat16(v);
    __nv_bfloat16 lb = __float2bfloat16(v - __bfloat162float(hb));
    hi = __bfloat16_as_ushort(hb);
    lo = __bfloat16_as_ushort(lb);
}

// ---------------- W -> bf16 hi/lo transposed prep (GAT layers) ----------------
__global__ void k_prepWt2(const float* __restrict__ W1, const float* __restrict__ W2) {
    int i = blockIdx.x * blockDim.x + threadIdx.x;  // i = k*128 + n
    if (i >= HC * HC) return;
    int layer = blockIdx.y;
    const float* W = layer ? W2 : W1;
    int k = i >> 7, n = i & 127;
    unsigned short hi, lo;
    bf16split(W[i], hi, lo);
    g_WtHi[layer][n * HC + k] = hi;
    g_WtLo[layer][n * HC + k] = lo;
}

// ---------------- concat proj weights: [K][32]x2 -> [64][K] bf16 split --------
__global__ void k_prepWcat(const float* __restrict__ Wa, const float* __restrict__ Wb,
                           int K, int sel) {
    int i = blockIdx.x * blockDim.x + threadIdx.x;  // i = k*64 + n
    if (i >= K * 64) return;
    int k = i >> 6, n = i & 63;
    float w = (n < 32) ? Wa[k * 32 + n] : Wb[k * 32 + (n - 32)];
    unsigned short hi, lo;
    bf16split(w, hi, lo);
    if (sel == 0) { g_W3Hi[n * K + k] = hi; g_W3Lo[n * K + k] = lo; }
    else          { g_W4Hi[n * K + k] = hi; g_W4Lo[n * K + k] = lo; }
}

// ---------------- mma.sync bf16-split GEMM (64-row tiles, occ 2) --------------
#define MMA_BF16(c, A0, A1, A2, A3, B0, B1) \
    asm volatile("mma.sync.aligned.m16n8k16.row.col.f32.bf16.bf16.f32 " \
        "{%0,%1,%2,%3}, {%4,%5,%6,%7}, {%8,%9}, {%0,%1,%2,%3};" \
        : "+f"((c)[0]), "+f"((c)[1]), "+f"((c)[2]), "+f"((c)[3]) \
        : "r"(A0), "r"(A1), "r"(A2), "r"(A3), "r"(B0), "r"(B1))

// smem: xh 64*STR | xl 64*STR | wh 128*STR | wl 128*STR | sws 128f | swd 128f
#define SMEM_MMA ((2 * 64 + 2 * 128) * STR * 4 + 1024)

__global__ __launch_bounds__(256, 2) void k_gemm128mma(
    const float* __restrict__ X, int layer,
    const float* __restrict__ aws, const float* __restrict__ awd) {
    extern __shared__ __align__(16) char smem[];
    uint32_t* xh = reinterpret_cast<uint32_t*>(smem);
    uint32_t* xl = xh + 64 * STR;
    uint32_t* wh = xl + 64 * STR;
    uint32_t* wl = wh + 128 * STR;
    float* sws = reinterpret_cast<float*>(wl + 128 * STR);
    float* swd = sws + 128;
    int tid = threadIdx.x, lane = tid & 31, wid = tid >> 5;
    int gid = lane >> 2, tg = lane & 3;
    int row0 = blockIdx.x * 64;

    if (tid < 128) { sws[tid] = aws[tid]; swd[tid] = awd[tid]; }
    {
        const uint4* gh4 = reinterpret_cast<const uint4*>(g_WtHi[layer]);
        const uint4* gl4 = reinterpret_cast<const uint4*>(g_WtLo[layer]);
        uint4* wh4 = reinterpret_cast<uint4*>(wh);
        uint4* wl4 = reinterpret_cast<uint4*>(wl);
        for (int i = tid; i < 128 * 16; i += 256) {
            int r = i >> 4, q = i & 15;
            wh4[r * 17 + q] = gh4[i];
            wl4[r * 17 + q] = gl4[i];
        }
    }
    {
        const float4* X4 = reinterpret_cast<const float4*>(X);
        for (int i = tid; i < 64 * 32; i += 256) {
            int r = i >> 5, q = i & 31;
            int grow = row0 + r;
            float4 v = (grow < NN) ? X4[(size_t)grow * 32 + q] : make_float4(0.f, 0.f, 0.f, 0.f);
            float vv[4] = {v.x, v.y, v.z, v.w};
#pragma unroll
            for (int q2 = 0; q2 < 2; q2++) {
                unsigned short h0, l0, h1, l1;
                bf16split(vv[2 * q2], h0, l0);
                bf16split(vv[2 * q2 + 1], h1, l1);
                xh[r * STR + 2 * q + q2] = ((uint32_t)h1 << 16) | h0;
                xl[r * STR + 2 * q + q2] = ((uint32_t)l1 << 16) | l0;
            }
        }
    }
    __syncthreads();

    int warpM = (wid & 3) * 16;
    int n0 = (wid >> 2) * 64;
    float acc[8][4];
#pragma unroll
    for (int t = 0; t < 8; t++)
#pragma unroll
        for (int j = 0; j < 4; j++) acc[t][j] = 0.f;

    const uint32_t* xrh = xh + (warpM + gid) * STR + tg;
    const uint32_t* xrl = xl + (warpM + gid) * STR + tg;
#pragma unroll 1
    for (int kk = 0; kk < 8; kk++) {
        int kw = kk * 8;
        uint32_t ah0 = xrh[kw],           ah2 = xrh[kw + 4];
        uint32_t ah1 = xrh[kw + 8 * STR], ah3 = xrh[kw + 8 * STR + 4];
        uint32_t al0 = xrl[kw],           al2 = xrl[kw + 4];
        uint32_t al1 = xrl[kw + 8 * STR], al3 = xrl[kw + 8 * STR + 4];
#pragma unroll
        for (int t = 0; t < 8; t++) {
            const uint32_t* wrh = wh + (n0 + t * 8 + gid) * STR + kw + tg;
            const uint32_t* wrl = wl + (n0 + t * 8 + gid) * STR + kw + tg;
            uint32_t bh0 = wrh[0], bh1 = wrh[4];
            uint32_t bl0 = wrl[0], bl1 = wrl[4];
            MMA_BF16(acc[t], ah0, ah1, ah2, ah3, bh0, bh1);
            MMA_BF16(acc[t], ah0, ah1, ah2, ah3, bl0, bl1);
            MMA_BF16(acc[t], al0, al1, al2, al3, bh0, bh1);
        }
    }

    int r0 = row0 + warpM + gid, r1 = r0 + 8;
#pragma unroll
    for (int t = 0; t < 8; t++) {
        int cidx = (n0 >> 1) + t * 4 + tg;
        if (r0 < NN) g_h16[(size_t)r0 * 64 + cidx] = pack_h2(acc[t][0], acc[t][1]);
        if (r1 < NN) g_h16[(size_t)r1 * 64 + cidx] = pack_h2(acc[t][2], acc[t][3]);
    }
#pragma unroll
    for (int hh = 0; hh < 2; hh++) {
        int h = (n0 >> 5) + hh;
        float ps0 = 0.f, pd0 = 0.f, ps1 = 0.f, pd1 = 0.f;
#pragma unroll
        for (int j = 0; j < 4; j++) {
            int t = hh * 4 + j;
            int col = n0 + t * 8 + 2 * tg;
            float w0 = sws[col], w1 = sws[col + 1];
            float v0 = swd[col], v1 = swd[col + 1];
            ps0 = fmaf(acc[t][0], w0, fmaf(acc[t][1], w1, ps0));
            pd0 = fmaf(acc[t][0], v0, fmaf(acc[t][1], v1, pd0));
            ps1 = fmaf(acc[t][2], w0, fmaf(acc[t][3], w1, ps1));
            pd1 = fmaf(acc[t][2], v0, fmaf(acc[t][3], v1, pd1));
        }
#pragma unroll
        for (int o = 1; o <= 2; o <<= 1) {
            ps0 += __shfl_xor_sync(0xffffffffu, ps0, o);
            pd0 += __shfl_xor_sync(0xffffffffu, pd0, o);
            ps1 += __shfl_xor_sync(0xffffffffu, ps1, o);
            pd1 += __shfl_xor_sync(0xffffffffu, pd1, o);
        }
        if (tg == 0) {
            if (r0 < NN) { g_as[r0 * HH + h] = ps0; g_ad[r0 * HH + h] = pd0; }
            if (r1 < NN) { g_as[r1 * HH + h] = ps1; g_ad[r1 * HH + h] = pd1; }
        }
    }
}

// ---------------- MMA dual projection -> fp16 outputs (32 cols each) ----------
// smem: xh 64*STR | xl 64*STR | wh 64*STR | wl 64*STR
#define SMEM_PROJ (4 * 64 * STR * 4)

template <int K>
__global__ __launch_bounds__(256, 2) void k_projmma(
    const float* __restrict__ X, uint32_t* __restrict__ Ya, uint32_t* __restrict__ Yb) {
    extern __shared__ __align__(16) char smem[];
    uint32_t* xh = reinterpret_cast<uint32_t*>(smem);
    uint32_t* xl = xh + 64 * STR;
    uint32_t* wh = xl + 64 * STR;
    uint32_t* wl = wh + 64 * STR;
    int tid = threadIdx.x, lane = tid & 31, wid = tid >> 5;
    int gid = lane >> 2, tg = lane & 3;
    int row0 = blockIdx.x * 64;
    const unsigned short* WHi = (K == HC) ? g_W3Hi : g_W4Hi;
    const unsigned short* WLo = (K == HC) ? g_W3Lo : g_W4Lo;
    {
        const uint4* gh4 = reinterpret_cast<const uint4*>(WHi);
        const uint4* gl4 = reinterpret_cast<const uint4*>(WLo);
        uint4* wh4 = reinterpret_cast<uint4*>(wh);
        uint4* wl4 = reinterpret_cast<uint4*>(wl);
        constexpr int WQ = K / 8;
        for (int i = tid; i < 64 * WQ; i += 256) {
            int r = i / WQ, q = i % WQ;
            wh4[r * 17 + q] = gh4[i];
            wl4[r * 17 + q] = gl4[i];
        }
    }
    {
        const float4* X4 = reinterpret_cast<const float4*>(X);
        constexpr int KW = K / 4;
        for (int i = tid; i < 64 * KW; i += 256) {
            int r = i / KW, q = i % KW;
            int grow = row0 + r;
            float4 v = (grow < NN) ? X4[(size_t)grow * KW + q] : make_float4(0.f, 0.f, 0.f, 0.f);
            float vv[4] = {v.x, v.y, v.z, v.w};
#pragma unroll
            for (int q2 = 0; q2 < 2; q2++) {
                unsigned short h0, l0, h1, l1;
                bf16split(vv[2 * q2], h0, l0);
                bf16split(vv[2 * q2 + 1], h1, l1);
                xh[r * STR + 2 * q + q2] = ((uint32_t)h1 << 16) | h0;
                xl[r * STR + 2 * q + q2] = ((uint32_t)l1 << 16) | l0;
            }
        }
    }
    __syncthreads();

    int warpM = (wid & 3) * 16;
    int n0 = (wid >> 2) * 32;    // 0 -> Ya, 32 -> Yb
    float acc[4][4];
#pragma unroll
    for (int t = 0; t < 4; t++)
#pragma unroll
        for (int j = 0; j < 4; j++) acc[t][j] = 0.f;

    const uint32_t* xrh = xh + (warpM + gid) * STR + tg;
    const uint32_t* xrl = xl + (warpM + gid) * STR + tg;
#pragma unroll
    for (int kk = 0; kk < K / 16; kk++) {
        int kw = kk * 8;
        uint32_t ah0 = xrh[kw],           ah2 = xrh[kw + 4];
        uint32_t ah1 = xrh[kw + 8 * STR], ah3 = xrh[kw + 8 * STR + 4];
        uint32_t al0 = xrl[kw],           al2 = xrl[kw + 4];
        uint32_t al1 = xrl[kw + 8 * STR], al3 = xrl[kw + 8 * STR + 4];
#pragma unroll
        for (int t = 0; t < 4; t++) {
            const uint32_t* wrh = wh + (n0 + t * 8 + gid) * STR + kw + tg;
            const uint32_t* wrl = wl + (n0 + t * 8 + gid) * STR + kw + tg;
            uint32_t bh0 = wrh[0], bh1 = wrh[4];
            uint32_t bl0 = wrl[0], bl1 = wrl[4];
            MMA_BF16(acc[t], ah0, ah1, ah2, ah3, bh0, bh1);
            MMA_BF16(acc[t], ah0, ah1, ah2, ah3, bl0, bl1);
            MMA_BF16(acc[t], al0, al1, al2, al3, bh0, bh1);
        }
    }

    uint32_t* dst = (n0 == 0) ? Ya : Yb;
    int r0 = row0 + warpM + gid, r1 = r0 + 8;
#pragma unroll
    for (int t = 0; t < 4; t++) {
        int widx = t * 4 + tg;   // half2-word col of 16
        if (r0 < NN) dst[(size_t)r0 * 16 + widx] = pack_h2(acc[t][0], acc[t][1]);
        if (r1 < NN) dst[(size_t)r1 * 16 + widx] = pack_h2(acc[t][2], acc[t][3]);
    }
}

// ---------------- CSR build ---------------------------------------------------
__global__ void k_count(const int* __restrict__ dst) {
    int e = blockIdx.x * blockDim.x + threadIdx.x;
    if (e < EE) atomicAdd(&g_cnt_i[dst[e]], 1);
}

__global__ void k_scan1() {
    __shared__ int wsum[32];
    int t = threadIdx.x, b = blockIdx.x;
    int i = b * 1024 + t;
    int v = (i < NN) ? g_cnt_i[i] : 0;
    int incl = v;
#pragma unroll
    for (int o = 1; o < 32; o <<= 1) {
        int n = __shfl_up_sync(0xffffffffu, incl, o);
        if ((t & 31) >= o) incl += n;
    }
    if ((t & 31) == 31) wsum[t >> 5] = incl;
    __syncthreads();
    if (t < 32) {
        int wv = wsum[t];
#pragma unroll
        for (int o = 1; o < 32; o <<= 1) {
            int n = __shfl_up_sync(0xffffffffu, wv, o);
            if (t >= o) wv += n;
        }
        wsum[t] = wv;
    }
    __syncthreads();
    int excl = incl - v + ((t >= 32) ? wsum[(t >> 5) - 1] : 0);
    if (i < NN) g_rowptr[i] = excl;
    if (t == 1023) g_bsum[b] = excl + v;
}

__global__ void k_scan2() {
    __shared__ int w0s;
    int t = threadIdx.x;
    int v = (t < NB_SCAN) ? g_bsum[t] : 0;
    int incl = v;
#pragma unroll
    for (int o = 1; o < 32; o <<= 1) {
        int n = __shfl_up_sync(0xffffffffu, incl, o);
        if ((t & 31) >= o) incl += n;
    }
    if (t == 31) w0s = incl;
    __syncthreads();
    if (t >= 32) incl += w0s;
    if (t < NB_SCAN) g_boff[t] = incl - v;
}

__global__ void k_scan3() {
    int i = blockIdx.x * blockDim.x + threadIdx.x;
    if (i < NN) {
        int v = g_rowptr[i] + g_boff[i >> 10];
        g_rowptr[i] = v;
        g_cursor[i] = v;
    }
    if (i == 0) g_rowptr[NN] = EE;
}

__global__ void k_fill(const int* __restrict__ src, const int* __restrict__ dst) {
    int e = blockIdx.x * blockDim.x + threadIdx.x;
    if (e >= EE) return;
    int pos = atomicAdd(&g_cursor[dst[e]], 1);
    g_csrc[pos] = src[e];
}

// ---------------- fused GAT aggregation: 4 edges/warp-iter, 8 lanes/edge ------
__global__ void k_gat_aggr(const float* __restrict__ bias) {
    int w = (blockIdx.x * blockDim.x + threadIdx.x) >> 5;
    if (w >= NN) return;
    int lane = threadIdx.x & 31;
    int g = lane >> 3, l = lane & 7;
    int hd = l >> 1;
    int row0 = g_rowptr[w], row1 = g_rowptr[w + 1];
    float ad_l = g_ad[w * HH + hd];
    const uint4* HV4 = reinterpret_cast<const uint4*>(g_h16);
    float acc[16];
#pragma unroll
    for (int i = 0; i < 16; i++) acc[i] = 0.f;
    float z = 0.f;
    for (int base = row0; base < row1; base += 4) {
        int e = base + g;
        bool valid = e < row1;
        int s = valid ? g_csrc[e] : 0;
        float as_l = g_as[s * HH + hd];
        uint4 q0 = HV4[(size_t)s * 16 + l * 2];
        uint4 q1 = HV4[(size_t)s * 16 + l * 2 + 1];
        float wgt = valid ? __expf(lrelu(as_l + ad_l)) : 0.f;
        z += wgt;
        const uint32_t* qa = &q0.x;
        const uint32_t* qb = &q1.x;
#pragma unroll
        for (int j = 0; j < 4; j++) {
            float2 fa = __half22float2(*reinterpret_cast<const __half2*>(&qa[j]));
            float2 fb = __half22float2(*reinterpret_cast<const __half2*>(&qb[j]));
            acc[2 * j]     = fmaf(wgt, fa.x, acc[2 * j]);
            acc[2 * j + 1] = fmaf(wgt, fa.y, acc[2 * j + 1]);
            acc[8 + 2 * j]     = fmaf(wgt, fb.x, acc[8 + 2 * j]);
            acc[8 + 2 * j + 1] = fmaf(wgt, fb.y, acc[8 + 2 * j + 1]);
        }
    }
#pragma unroll
    for (int o = 8; o <= 16; o <<= 1) {
        z += __shfl_xor_sync(0xffffffffu, z, o);
#pragma unroll
        for (int i = 0; i < 16; i++)
            acc[i] += __shfl_xor_sync(0xffffffffu, acc[i], o);
    }
    float as_self = g_as[w * HH + hd];
    float wsf = __expf(lrelu(as_self + ad_l));
    z += wsf;
    {
        uint4 q0 = HV4[(size_t)w * 16 + l * 2];
        uint4 q1 = HV4[(size_t)w * 16 + l * 2 + 1];
        const uint32_t* qa = &q0.x;
        const uint32_t* qb = &q1.x;
#pragma unroll
        for (int j = 0; j < 4; j++) {
            float2 fa = __half22float2(*reinterpret_cast<const __half2*>(&qa[j]));
            float2 fb = __half22float2(*reinterpret_cast<const __half2*>(&qb[j]));
            acc[2 * j]     = fmaf(wsf, fa.x, acc[2 * j]);
            acc[2 * j + 1] = fmaf(wsf, fa.y, acc[2 * j + 1]);
            acc[8 + 2 * j]     = fmaf(wsf, fb.x, acc[8 + 2 * j]);
            acc[8 + 2 * j + 1] = fmaf(wsf, fb.y, acc[8 + 2 * j + 1]);
        }
    }
    float inv = 1.f / (z + 1e-16f);
    int j4 = l * 4 + g;
    int fo = 4 * g;
    float4 b = reinterpret_cast<const float4*>(bias)[j4];
    float4 r;
    r.x = fmaxf(acc[fo + 0] * inv + b.x, 0.f);
    r.y = fmaxf(acc[fo + 1] * inv + b.y, 0.f);
    r.z = fmaxf(acc[fo + 2] * inv + b.z, 0.f);
    r.w = fmaxf(acc[fo + 3] * inv + b.w, 0.f);
    reinterpret_cast<float4*>(g_x)[w * 32 + j4] = r;
}

// ---------------- GraphConv epilogue: Y = relu(gather(P16) + Q16 + bias) ------
__global__ void k_gc_final(const uint32_t* __restrict__ P16, const uint32_t* __restrict__ Q16,
                           const float* __restrict__ bias, float* __restrict__ Y) {
    int q = (blockIdx.x * blockDim.x + threadIdx.x) >> 3;
    if (q >= NN) return;
    int lane = threadIdx.x & 7;
    int row0 = g_rowptr[q], row1 = g_rowptr[q + 1];
    const uint2* P2 = reinterpret_cast<const uint2*>(P16);
    float4 acc = make_float4(0.f, 0.f, 0.f, 0.f);
    int s = (row0 < row1) ? g_csrc[row0] : 0;
    for (int k = row0; k < row1; k++) {
        int s_next = (k + 1 < row1) ? g_csrc[k + 1] : 0;
        uint2 p = P2[(size_t)s * 8 + lane];
        float2 f01 = __half22float2(*reinterpret_cast<const __half2*>(&p.x));
        float2 f23 = __half22float2(*reinterpret_cast<const __half2*>(&p.y));
        acc.x += f01.x; acc.y += f01.y; acc.z += f23.x; acc.w += f23.y;
        s = s_next;
    }
    uint2 qw = reinterpret_cast<const uint2*>(Q16)[(size_t)q * 8 + lane];
    float2 q01 = __half22float2(*reinterpret_cast<const __half2*>(&qw.x));
    float2 q23 = __half22float2(*reinterpret_cast<const __half2*>(&qw.y));
    float4 bb = reinterpret_cast<const float4*>(bias)[lane];
    float4 r;
    r.x = fmaxf(acc.x + q01.x + bb.x, 0.f);
    r.y = fmaxf(acc.y + q01.y + bb.y, 0.f);
    r.z = fmaxf(acc.z + q23.x + bb.z, 0.f);
    r.w = fmaxf(acc.w + q23.y + bb.w, 0.f);
    reinterpret_cast<float4*>(Y)[q * 8 + lane] = r;
}

// ---------------- SAGE epilogue + pool: pool += relu(mean(P16) + Q16 + bias) --
__global__ void k_sage_final(const uint32_t* __restrict__ P16, const uint32_t* __restrict__ Q16,
                             const float* __restrict__ bias,
                             const int* __restrict__ batch) {
    int q = (blockIdx.x * blockDim.x + threadIdx.x) >> 3;
    if (q >= NN) return;
    int lane = threadIdx.x & 7;
    int row0 = g_rowptr[q], row1 = g_rowptr[q + 1];
    const uint2* P2 = reinterpret_cast<const uint2*>(P16);
    float4 acc = make_float4(0.f, 0.f, 0.f, 0.f);
    int s = (row0 < row1) ? g_csrc[row0] : 0;
    for (int k = row0; k < row1; k++) {
        int s_next = (k + 1 < row1) ? g_csrc[k + 1] : 0;
        uint2 p = P2[(size_t)s * 8 + lane];
        float2 f01 = __half22float2(*reinterpret_cast<const __half2*>(&p.x));
        float2 f23 = __half22float2(*reinterpret_cast<const __half2*>(&p.y));
        acc.x += f01.x; acc.y += f01.y; acc.z += f23.x; acc.w += f23.y;
        s = s_next;
    }
    float inv = 1.f / fmaxf((float)(row1 - row0), 1.f);
    uint2 qw = reinterpret_cast<const uint2*>(Q16)[(size_t)q * 8 + lane];
    float2 q01 = __half22float2(*reinterpret_cast<const __half2*>(&qw.x));
    float2 q23 = __half22float2(*reinterpret_cast<const __half2*>(&qw.y));
    float4 bb = reinterpret_cast<const float4*>(bias)[lane];
    float4 r;
    r.x = fmaxf(fmaf(acc.x, inv, q01.x) + bb.x, 0.f);
    r.y = fmaxf(fmaf(acc.y, inv, q01.y) + bb.y, 0.f);
    r.z = fmaxf(fmaf(acc.z, inv, q23.x) + bb.z, 0.f);
    r.w = fmaxf(fmaf(acc.w, inv, q23.y) + bb.w, 0.f);
    int b = batch[q];
    atomicAdd(reinterpret_cast<float4*>(g_pool) + b * 8 + lane, r);
    if (lane == 0) atomicAdd(&g_cnt[b], 1.f);
}

// ---------------- MLP head (single tiny block) -------------------------------
__global__ void k_head(const float* __restrict__ Wf1, const float* __restrict__ bf1,
                       const float* __restrict__ Wf2, const float* __restrict__ bf2,
                       float* __restrict__ out) {
    __shared__ float t1[NGR * CC];
    int t = threadIdx.x;
    for (int idx = t; idx < NGR * CC; idx += blockDim.x) {
        int g = idx >> 5, c = idx & 31;
        float inv = 1.f / fmaxf(g_cnt[g], 1.f);
        float s = 0.f;
#pragma unroll
        for (int k = 0; k < CC; k++) s = fmaf(g_pool[g * CC + k] * inv, Wf1[k * CC + c], s);
        t1[idx] = fmaxf(s + bf1[c], 0.f);
    }
    __syncthreads();
    for (int idx = t; idx < NGR * NOUT; idx += blockDim.x) {
        int g = idx / NOUT, o = idx - g * NOUT;
        float s = 0.f;
#pragma unroll
        for (int k = 0; k < CC; k++) s = fmaf(t1[g * CC + k], Wf2[k * NOUT + o], s);
        out[idx] = s + bf2[o];
    }
}

// =============================================================================
extern "C" void kernel_launch(void* const* d_in, const int* in_sizes, int n_in,
                              void* d_out, int out_size) {
    const float* x   = (const float*)d_in[0];
    const int*   ei  = (const int*)d_in[1];
    const int*   bat = (const int*)d_in[2];
    const float* W1  = (const float*)d_in[3];
    const float* as1 = (const float*)d_in[4];
    const float* ad1 = (const float*)d_in[5];
    const float* b1  = (const float*)d_in[6];
    const float* W2  = (const float*)d_in[7];
    const float* as2 = (const float*)d_in[8];
    const float* ad2 = (const float*)d_in[9];
    const float* b2  = (const float*)d_in[10];
    const float* W3r = (const float*)d_in[11];
    const float* W3l = (const float*)d_in[12];
    const float* b3  = (const float*)d_in[13];
    const float* W4l = (const float*)d_in[14];
    const float* b4l = (const float*)d_in[15];
    const float* W4r = (const float*)d_in[16];
    const float* Wf1 = (const float*)d_in[17];
    const float* bf1 = (const float*)d_in[18];
    const float* Wf2 = (const float*)d_in[19];
    const float* bf2 = (const float*)d_in[20];
    const int* src = ei;
    const int* dst = ei + EE;
    float* out = (float*)d_out;

    static float *p_x = nullptr, *p_acc, *p_pool, *p_cnt;
    static uint32_t* p_h16;
    static int* p_cnt_i;
    static bool init_done = false;
    static cudaStream_t s2;
    static cudaEvent_t e1, e2;
    if (!p_x) {
        cudaGetSymbolAddress((void**)&p_x, g_x);
        cudaGetSymbolAddress((void**)&p_acc, g_acc);
        cudaGetSymbolAddress((void**)&p_h16, g_h16);
        cudaGetSymbolAddress((void**)&p_pool, g_pool);
        cudaGetSymbolAddress((void**)&p_cnt, g_cnt);
        cudaGetSymbolAddress((void**)&p_cnt_i, g_cnt_i);
    }
    if (!init_done) {
        cudaFuncSetAttribute(k_gemm128mma, cudaFuncAttributeMaxDynamicSharedMemorySize, SMEM_MMA);
        cudaFuncSetAttribute(k_projmma<HC>, cudaFuncAttributeMaxDynamicSharedMemorySize, SMEM_PROJ);
        cudaFuncSetAttribute(k_projmma<CC>, cudaFuncAttributeMaxDynamicSharedMemorySize, SMEM_PROJ);
        cudaStreamCreateWithFlags(&s2, cudaStreamNonBlocking);
        cudaEventCreateWithFlags(&e1, cudaEventDisableTiming);
        cudaEventCreateWithFlags(&e2, cudaEventDisableTiming);
        init_done = true;
    }

    const int T = 256;
    const int gE    = (EE + T - 1) / T;
    const int gWNN  = (NN * 32 + T - 1) / T;   // warp per node
    const int gQ8   = (NN * 8 + T - 1) / T;    // 8 lanes per node
    const int gR64  = (NN + 63) / 64;          // 64-row tiles

    // fp16 projection images carved from g_h16 (dead after gat_aggr2)
    uint32_t* Pa = p_h16;             // NN*16 words
    uint32_t* Pb = p_h16 + NN * 16;   // NN*16 words

    // ---- fork: CSR build on side stream, overlapped with W prep + GEMM1 ----
    cudaEventRecord(e1, 0);
    cudaStreamWaitEvent(s2, e1, 0);
    cudaMemsetAsync(p_cnt_i, 0, NN * sizeof(int), s2);
    k_count<<<gE, T, 0, s2>>>(dst);
    k_scan1<<<NB_SCAN, 1024, 0, s2>>>();
    k_scan2<<<1, 64, 0, s2>>>();
    k_scan3<<<(NN + 1023) / 1024, 1024, 0, s2>>>();
    k_fill<<<gE, T, 0, s2>>>(src, dst);
    cudaMemsetAsync(p_pool, 0, NGR * CC * sizeof(float), s2);
    cudaMemsetAsync(p_cnt, 0, NGR * sizeof(float), s2);
    cudaEventRecord(e2, s2);

    // main stream: W prep + GAT layer-1 GEMM (independent of CSR)
    {
        dim3 gp((HC * HC + T - 1) / T, 2);
        k_prepWt2<<<gp, T>>>(W1, W2);
    }
    k_prepWcat<<<(HC * 64 + T - 1) / T, T>>>(W3r, W3l, HC, 0);
    k_prepWcat<<<(CC * 64 + T - 1) / T, T>>>(W4l, W4r, CC, 1);
    k_gemm128mma<<<gR64, 256, SMEM_MMA>>>(x, 0, as1, ad1);
    cudaStreamWaitEvent(0, e2, 0);     // CSR + pool-zero ready

    // ---- GAT layer 1 aggregation ----
    k_gat_aggr<<<gWNN, T>>>(b1);

    // ---- GAT layer 2 ----
    k_gemm128mma<<<gR64, 256, SMEM_MMA>>>(p_x, 1, as2, ad2);
    k_gat_aggr<<<gWNN, T>>>(b2);

    // ---- GraphConv: x3 = relu(segsum((x2@W3r)[src]) + x2@W3l + b3) ----
    k_projmma<HC><<<gR64, 256, SMEM_PROJ>>>(p_x, Pa, Pb);     // fp16 P/Q
    k_gc_final<<<gQ8, T>>>(Pa, Pb, b3, p_acc);                // x3 -> g_acc
    // ---- SAGEConv + pool ----
    k_projmma<CC><<<gR64, 256, SMEM_PROJ>>>(p_acc, Pa, Pb);   // fp16 P/Q
    k_sage_final<<<gQ8, T>>>(Pa, Pb, b4l, bat);               // pool atomics

    // ---- head ----
    k_head<<<1, 1024>>>(Wf1, bf1, Wf2, bf2, out);
}

// round 16
// speedup vs baseline: 1.4501x; 1.0325x over previous
#include <cuda_runtime.h>
#include <cuda_bf16.h>
#include <cuda_fp16.h>
#include <cstdint>

#define NN   50000
#define EE   800000
#define HH   4
#define CC   32
#define HC   128
#define NGR  64
#define NOUT 10
#define NB_SCAN 49   // ceil(NN/1024)
#define STR  68      // smem row stride in 32-bit words

// ---------------- scratch (device globals; no allocation allowed) ------------
__device__ uint32_t g_h16[NN * 64];     // GAT h (half2); later P/Q fp16 images
__device__ float g_acc[NN * HC];        // x3 fp16 lives here (reinterpreted)
__device__ float g_x[NN * HC];          // x2 fp16 lives here (reinterpreted)
__device__ float g_as[NN * HH];
__device__ float g_ad[NN * HH];
__device__ float g_pool[NGR * CC];
__device__ float g_cnt[NGR];
// CSR by destination
__device__ int g_cnt_i[NN];
__device__ int g_rowptr[NN + 1];
__device__ int g_cursor[NN];
__device__ int g_csrc[EE];
__device__ int g_bsum[NB_SCAN];
__device__ int g_boff[NB_SCAN];
// bf16-split transposed weights Wt[n][k] per GAT layer
__device__ __align__(16) unsigned short g_WtHi[2][HC * HC];
__device__ __align__(16) unsigned short g_WtLo[2][HC * HC];
// bf16-split concatenated projection weights [64 out][K in] transposed
__device__ __align__(16) unsigned short g_W3Hi[64 * HC];
__device__ __align__(16) unsigned short g_W3Lo[64 * HC];
__device__ __align__(16) unsigned short g_W4Hi[64 * CC];
__device__ __align__(16) unsigned short g_W4Lo[64 * CC];

__device__ __forceinline__ float lrelu(float v) { return v > 0.f ? v : 0.2f * v; }
__device__ __forceinline__ uint32_t pack_h2(float a, float b) {
    __half2 h = __floats2half2_rn(a, b);
    return *reinterpret_cast<uint32_t*>(&h);
}
__device__ __forceinline__ void bf16split(float v, unsigned short& hi, unsigned short& lo) {
    __nv_bfloat16 hb = __float2bfloat16(v);
    __nv_bfloat16 lb = __float2bfloat16(v - __bfloat162float(hb));
    hi = __bfloat16_as_ushort(hb);
    lo = __bfloat16_as_ushort(lb);
}
// split a packed half2 word into bf16-hi / bf16-lo packed words (exact)
__device__ __forceinline__ void split_h2word(uint32_t w, uint32_t& xh, uint32_t& xl) {
    float2 f = __half22float2(*reinterpret_cast<const __half2*>(&w));
    unsigned short h0, l0, h1, l1;
    bf16split(f.x, h0, l0);
    bf16split(f.y, h1, l1);
    xh = ((uint32_t)h1 << 16) | h0;
    xl = ((uint32_t)l1 << 16) | l0;
}

// ---------------- W -> bf16 hi/lo transposed prep (GAT layers) ----------------
__global__ void k_prepWt2(const float* __restrict__ W1, const float* __restrict__ W2) {
    int i = blockIdx.x * blockDim.x + threadIdx.x;  // i = k*128 + n
    if (i >= HC * HC) return;
    int layer = blockIdx.y;
    const float* W = layer ? W2 : W1;
    int k = i >> 7, n = i & 127;
    unsigned short hi, lo;
    bf16split(W[i], hi, lo);
    g_WtHi[layer][n * HC + k] = hi;
    g_WtLo[layer][n * HC + k] = lo;
}

// ---------------- concat proj weights: [K][32]x2 -> [64][K] bf16 split --------
__global__ void k_prepWcat(const float* __restrict__ Wa, const float* __restrict__ Wb,
                           int K, int sel) {
    int i = blockIdx.x * blockDim.x + threadIdx.x;  // i = k*64 + n
    if (i >= K * 64) return;
    int k = i >> 6, n = i & 63;
    float w = (n < 32) ? Wa[k * 32 + n] : Wb[k * 32 + (n - 32)];
    unsigned short hi, lo;
    bf16split(w, hi, lo);
    if (sel == 0) { g_W3Hi[n * K + k] = hi; g_W3Lo[n * K + k] = lo; }
    else          { g_W4Hi[n * K + k] = hi; g_W4Lo[n * K + k] = lo; }
}

// ---------------- mma.sync bf16-split GEMM (64-row tiles, occ 2) --------------
#define MMA_BF16(c, A0, A1, A2, A3, B0, B1) \
    asm volatile("mma.sync.aligned.m16n8k16.row.col.f32.bf16.bf16.f32 " \
        "{%0,%1,%2,%3}, {%4,%5,%6,%7}, {%8,%9}, {%0,%1,%2,%3};" \
        : "+f"((c)[0]), "+f"((c)[1]), "+f"((c)[2]), "+f"((c)[3]) \
        : "r"(A0), "r"(A1), "r"(A2), "r"(A3), "r"(B0), "r"(B1))

// smem: xh 64*STR | xl 64*STR | wh 128*STR | wl 128*STR | sws 128f | swd 128f
#define SMEM_MMA ((2 * 64 + 2 * 128) * STR * 4 + 1024)

template <bool F16>
__global__ __launch_bounds__(256, 2) void k_gemm128mma(
    const void* __restrict__ Xv, int layer,
    const float* __restrict__ aws, const float* __restrict__ awd) {
    extern __shared__ __align__(16) char smem[];
    uint32_t* xh = reinterpret_cast<uint32_t*>(smem);
    uint32_t* xl = xh + 64 * STR;
    uint32_t* wh = xl + 64 * STR;
    uint32_t* wl = wh + 128 * STR;
    float* sws = reinterpret_cast<float*>(wl + 128 * STR);
    float* swd = sws + 128;
    int tid = threadIdx.x, lane = tid & 31, wid = tid >> 5;
    int gid = lane >> 2, tg = lane & 3;
    int row0 = blockIdx.x * 64;

    if (tid < 128) { sws[tid] = aws[tid]; swd[tid] = awd[tid]; }
    {
        const uint4* gh4 = reinterpret_cast<const uint4*>(g_WtHi[layer]);
        const uint4* gl4 = reinterpret_cast<const uint4*>(g_WtLo[layer]);
        uint4* wh4 = reinterpret_cast<uint4*>(wh);
        uint4* wl4 = reinterpret_cast<uint4*>(wl);
        for (int i = tid; i < 128 * 16; i += 256) {
            int r = i >> 4, q = i & 15;
            wh4[r * 17 + q] = gh4[i];
            wl4[r * 17 + q] = gl4[i];
        }
    }
    if (F16) {
        const uint4* X4 = reinterpret_cast<const uint4*>(Xv);  // row = 16 uint4 (64 words)
        for (int i = tid; i < 64 * 16; i += 256) {
            int r = i >> 4, q = i & 15;
            int grow = row0 + r;
            uint4 v = (grow < NN) ? X4[(size_t)grow * 16 + q] : make_uint4(0u, 0u, 0u, 0u);
            const uint32_t* w4 = &v.x;
#pragma unroll
            for (int j = 0; j < 4; j++) {
                uint32_t ph, pl;
                split_h2word(w4[j], ph, pl);
                xh[r * STR + q * 4 + j] = ph;
                xl[r * STR + q * 4 + j] = pl;
            }
        }
    } else {
        const float4* X4 = reinterpret_cast<const float4*>(Xv);
        for (int i = tid; i < 64 * 32; i += 256) {
            int r = i >> 5, q = i & 31;
            int grow = row0 + r;
            float4 v = (grow < NN) ? X4[(size_t)grow * 32 + q] : make_float4(0.f, 0.f, 0.f, 0.f);
            float vv[4] = {v.x, v.y, v.z, v.w};
#pragma unroll
            for (int q2 = 0; q2 < 2; q2++) {
                unsigned short h0, l0, h1, l1;
                bf16split(vv[2 * q2], h0, l0);
                bf16split(vv[2 * q2 + 1], h1, l1);
                xh[r * STR + 2 * q + q2] = ((uint32_t)h1 << 16) | h0;
                xl[r * STR + 2 * q + q2] = ((uint32_t)l1 << 16) | l0;
            }
        }
    }
    __syncthreads();

    int warpM = (wid & 3) * 16;
    int n0 = (wid >> 2) * 64;
    float acc[8][4];
#pragma unroll
    for (int t = 0; t < 8; t++)
#pragma unroll
        for (int j = 0; j < 4; j++) acc[t][j] = 0.f;

    const uint32_t* xrh = xh + (warpM + gid) * STR + tg;
    const uint32_t* xrl = xl + (warpM + gid) * STR + tg;
#pragma unroll 1
    for (int kk = 0; kk < 8; kk++) {
        int kw = kk * 8;
        uint32_t ah0 = xrh[kw],           ah2 = xrh[kw + 4];
        uint32_t ah1 = xrh[kw + 8 * STR], ah3 = xrh[kw + 8 * STR + 4];
        uint32_t al0 = xrl[kw],           al2 = xrl[kw + 4];
        uint32_t al1 = xrl[kw + 8 * STR], al3 = xrl[kw + 8 * STR + 4];
#pragma unroll
        for (int t = 0; t < 8; t++) {
            const uint32_t* wrh = wh + (n0 + t * 8 + gid) * STR + kw + tg;
            const uint32_t* wrl = wl + (n0 + t * 8 + gid) * STR + kw + tg;
            uint32_t bh0 = wrh[0], bh1 = wrh[4];
            uint32_t bl0 = wrl[0], bl1 = wrl[4];
            MMA_BF16(acc[t], ah0, ah1, ah2, ah3, bh0, bh1);
            MMA_BF16(acc[t], ah0, ah1, ah2, ah3, bl0, bl1);
            MMA_BF16(acc[t], al0, al1, al2, al3, bh0, bh1);
        }
    }

    int r0 = row0 + warpM + gid, r1 = r0 + 8;
#pragma unroll
    for (int t = 0; t < 8; t++) {
        int cidx = (n0 >> 1) + t * 4 + tg;
        if (r0 < NN) g_h16[(size_t)r0 * 64 + cidx] = pack_h2(acc[t][0], acc[t][1]);
        if (r1 < NN) g_h16[(size_t)r1 * 64 + cidx] = pack_h2(acc[t][2], acc[t][3]);
    }
#pragma unroll
    for (int hh = 0; hh < 2; hh++) {
        int h = (n0 >> 5) + hh;
        float ps0 = 0.f, pd0 = 0.f, ps1 = 0.f, pd1 = 0.f;
#pragma unroll
        for (int j = 0; j < 4; j++) {
            int t = hh * 4 + j;
            int col = n0 + t * 8 + 2 * tg;
            float w0 = sws[col], w1 = sws[col + 1];
            float v0 = swd[col], v1 = swd[col + 1];
            ps0 = fmaf(acc[t][0], w0, fmaf(acc[t][1], w1, ps0));
            pd0 = fmaf(acc[t][0], v0, fmaf(acc[t][1], v1, pd0));
            ps1 = fmaf(acc[t][2], w0, fmaf(acc[t][3], w1, ps1));
            pd1 = fmaf(acc[t][2], v0, fmaf(acc[t][3], v1, pd1));
        }
#pragma unroll
        for (int o = 1; o <= 2; o <<= 1) {
            ps0 += __shfl_xor_sync(0xffffffffu, ps0, o);
            pd0 += __shfl_xor_sync(0xffffffffu, pd0, o);
            ps1 += __shfl_xor_sync(0xffffffffu, ps1, o);
            pd1 += __shfl_xor_sync(0xffffffffu, pd1, o);
        }
        if (tg == 0) {
            if (r0 < NN) { g_as[r0 * HH + h] = ps0; g_ad[r0 * HH + h] = pd0; }
            if (r1 < NN) { g_as[r1 * HH + h] = ps1; g_ad[r1 * HH + h] = pd1; }
        }
    }
}

// ---------------- MMA dual projection -> fp16 outputs (32 cols each) ----------
// smem: xh 64*STR | xl 64*STR | wh 64*STR | wl 64*STR
#define SMEM_PROJ (4 * 64 * STR * 4)

template <int K>
__global__ __launch_bounds__(256, 2) void k_projmma(
    const uint32_t* __restrict__ X16, uint32_t* __restrict__ Ya, uint32_t* __restrict__ Yb) {
    extern __shared__ __align__(16) char smem[];
    uint32_t* xh = reinterpret_cast<uint32_t*>(smem);
    uint32_t* xl = xh + 64 * STR;
    uint32_t* wh = xl + 64 * STR;
    uint32_t* wl = wh + 64 * STR;
    int tid = threadIdx.x, lane = tid & 31, wid = tid >> 5;
    int gid = lane >> 2, tg = lane & 3;
    int row0 = blockIdx.x * 64;
    const unsigned short* WHi = (K == HC) ? g_W3Hi : g_W4Hi;
    const unsigned short* WLo = (K == HC) ? g_W3Lo : g_W4Lo;
    {
        const uint4* gh4 = reinterpret_cast<const uint4*>(WHi);
        const uint4* gl4 = reinterpret_cast<const uint4*>(WLo);
        uint4* wh4 = reinterpret_cast<uint4*>(wh);
        uint4* wl4 = reinterpret_cast<uint4*>(wl);
        constexpr int WQ = K / 8;
        for (int i = tid; i < 64 * WQ; i += 256) {
            int r = i / WQ, q = i % WQ;
            wh4[r * 17 + q] = gh4[i];
            wl4[r * 17 + q] = gl4[i];
        }
    }
    // X (fp16): row = K/2 words = K/8 uint4
    {
        const uint4* X4 = reinterpret_cast<const uint4*>(X16);
        constexpr int XQ = K / 8;
        for (int i = tid; i < 64 * XQ; i += 256) {
            int r = i / XQ, q = i % XQ;
            int grow = row0 + r;
            uint4 v = (grow < NN) ? X4[(size_t)grow * XQ + q] : make_uint4(0u, 0u, 0u, 0u);
            const uint32_t* w4 = &v.x;
#pragma unroll
            for (int j = 0; j < 4; j++) {
                uint32_t ph, pl;
                split_h2word(w4[j], ph, pl);
                xh[r * STR + q * 4 + j] = ph;
                xl[r * STR + q * 4 + j] = pl;
            }
        }
    }
    __syncthreads();

    int warpM = (wid & 3) * 16;
    int n0 = (wid >> 2) * 32;    // 0 -> Ya, 32 -> Yb
    float acc[4][4];
#pragma unroll
    for (int t = 0; t < 4; t++)
#pragma unroll
        for (int j = 0; j < 4; j++) acc[t][j] = 0.f;

    const uint32_t* xrh = xh + (warpM + gid) * STR + tg;
    const uint32_t* xrl = xl + (warpM + gid) * STR + tg;
#pragma unroll
    for (int kk = 0; kk < K / 16; kk++) {
        int kw = kk * 8;
        uint32_t ah0 = xrh[kw],           ah2 = xrh[kw + 4];
        uint32_t ah1 = xrh[kw + 8 * STR], ah3 = xrh[kw + 8 * STR + 4];
        uint32_t al0 = xrl[kw],           al2 = xrl[kw + 4];
        uint32_t al1 = xrl[kw + 8 * STR], al3 = xrl[kw + 8 * STR + 4];
#pragma unroll
        for (int t = 0; t < 4; t++) {
            const uint32_t* wrh = wh + (n0 + t * 8 + gid) * STR + kw + tg;
            const uint32_t* wrl = wl + (n0 + t * 8 + gid) * STR + kw + tg;
            uint32_t bh0 = wrh[0], bh1 = wrh[4];
            uint32_t bl0 = wrl[0], bl1 = wrl[4];
            MMA_BF16(acc[t], ah0, ah1, ah2, ah3, bh0, bh1);
            MMA_BF16(acc[t], ah0, ah1, ah2, ah3, bl0, bl1);
            MMA_BF16(acc[t], al0, al1, al2, al3, bh0, bh1);
        }
    }

    uint32_t* dst = (n0 == 0) ? Ya : Yb;
    int r0 = row0 + warpM + gid, r1 = r0 + 8;
#pragma unroll
    for (int t = 0; t < 4; t++) {
        int widx = t * 4 + tg;   // half2-word col of 16
        if (r0 < NN) dst[(size_t)r0 * 16 + widx] = pack_h2(acc[t][0], acc[t][1]);
        if (r1 < NN) dst[(size_t)r1 * 16 + widx] = pack_h2(acc[t][2], acc[t][3]);
    }
}

// ---------------- CSR build ---------------------------------------------------
__global__ void k_count(const int* __restrict__ dst) {
    int e = blockIdx.x * blockDim.x + threadIdx.x;
    if (e < EE) atomicAdd(&g_cnt_i[dst[e]], 1);
}

__global__ void k_scan1() {
    __shared__ int wsum[32];
    int t = threadIdx.x, b = blockIdx.x;
    int i = b * 1024 + t;
    int v = (i < NN) ? g_cnt_i[i] : 0;
    int incl = v;
#pragma unroll
    for (int o = 1; o < 32; o <<= 1) {
        int n = __shfl_up_sync(0xffffffffu, incl, o);
        if ((t & 31) >= o) incl += n;
    }
    if ((t & 31) == 31) wsum[t >> 5] = incl;
    __syncthreads();
    if (t < 32) {
        int wv = wsum[t];
#pragma unroll
        for (int o = 1; o < 32; o <<= 1) {
            int n = __shfl_up_sync(0xffffffffu, wv, o);
            if (t >= o) wv += n;
        }
        wsum[t] = wv;
    }
    __syncthreads();
    int excl = incl - v + ((t >= 32) ? wsum[(t >> 5) - 1] : 0);
    if (i < NN) g_rowptr[i] = excl;
    if (t == 1023) g_bsum[b] = excl + v;
}

__global__ void k_scan2() {
    __shared__ int w0s;
    int t = threadIdx.x;
    int v = (t < NB_SCAN) ? g_bsum[t] : 0;
    int incl = v;
#pragma unroll
    for (int o = 1; o < 32; o <<= 1) {
        int n = __shfl_up_sync(0xffffffffu, incl, o);
        if ((t & 31) >= o) incl += n;
    }
    if (t == 31) w0s = incl;
    __syncthreads();
    if (t >= 32) incl += w0s;
    if (t < NB_SCAN) g_boff[t] = incl - v;
}

__global__ void k_scan3() {
    int i = blockIdx.x * blockDim.x + threadIdx.x;
    if (i < NN) {
        int v = g_rowptr[i] + g_boff[i >> 10];
        g_rowptr[i] = v;
        g_cursor[i] = v;
    }
    if (i == 0) g_rowptr[NN] = EE;
}

__global__ void k_fill(const int* __restrict__ src, const int* __restrict__ dst) {
    int e = blockIdx.x * blockDim.x + threadIdx.x;
    if (e >= EE) return;
    int pos = atomicAdd(&g_cursor[dst[e]], 1);
    g_csrc[pos] = src[e];
}

// ---------------- fused GAT aggregation: 4 edges/warp-iter, 8 lanes/edge ------
// output written as fp16 (half2 words) into Xout (row = 32 uint2)
__global__ void k_gat_aggr(const float* __restrict__ bias, uint2* __restrict__ Xout) {
    int w = (blockIdx.x * blockDim.x + threadIdx.x) >> 5;
    if (w >= NN) return;
    int lane = threadIdx.x & 31;
    int g = lane >> 3, l = lane & 7;
    int hd = l >> 1;
    int row0 = g_rowptr[w], row1 = g_rowptr[w + 1];
    float ad_l = g_ad[w * HH + hd];
    const uint4* HV4 = reinterpret_cast<const uint4*>(g_h16);
    float acc[16];
#pragma unroll
    for (int i = 0; i < 16; i++) acc[i] = 0.f;
    float z = 0.f;
    for (int base = row0; base < row1; base += 4) {
        int e = base + g;
        bool valid = e < row1;
        int s = valid ? g_csrc[e] : 0;
        float as_l = g_as[s * HH + hd];
        uint4 q0 = HV4[(size_t)s * 16 + l * 2];
        uint4 q1 = HV4[(size_t)s * 16 + l * 2 + 1];
        float wgt = valid ? __expf(lrelu(as_l + ad_l)) : 0.f;
        z += wgt;
        const uint32_t* qa = &q0.x;
        const uint32_t* qb = &q1.x;
#pragma unroll
        for (int j = 0; j < 4; j++) {
            float2 fa = __half22float2(*reinterpret_cast<const __half2*>(&qa[j]));
            float2 fb = __half22float2(*reinterpret_cast<const __half2*>(&qb[j]));
            acc[2 * j]     = fmaf(wgt, fa.x, acc[2 * j]);
            acc[2 * j + 1] = fmaf(wgt, fa.y, acc[2 * j + 1]);
            acc[8 + 2 * j]     = fmaf(wgt, fb.x, acc[8 + 2 * j]);
            acc[8 + 2 * j + 1] = fmaf(wgt, fb.y, acc[8 + 2 * j + 1]);
        }
    }
#pragma unroll
    for (int o = 8; o <= 16; o <<= 1) {
        z += __shfl_xor_sync(0xffffffffu, z, o);
#pragma unroll
        for (int i = 0; i < 16; i++)
            acc[i] += __shfl_xor_sync(0xffffffffu, acc[i], o);
    }
    float as_self = g_as[w * HH + hd];
    float wsf = __expf(lrelu(as_self + ad_l));
    z += wsf;
    {
        uint4 q0 = HV4[(size_t)w * 16 + l * 2];
        uint4 q1 = HV4[(size_t)w * 16 + l * 2 + 1];
        const uint32_t* qa = &q0.x;
        const uint32_t* qb = &q1.x;
#pragma unroll
        for (int j = 0; j < 4; j++) {
            float2 fa = __half22float2(*reinterpret_cast<const __half2*>(&qa[j]));
            float2 fb = __half22float2(*reinterpret_cast<const __half2*>(&qb[j]));
            acc[2 * j]     = fmaf(wsf, fa.x, acc[2 * j]);
            acc[2 * j + 1] = fmaf(wsf, fa.y, acc[2 * j + 1]);
            acc[8 + 2 * j]     = fmaf(wsf, fb.x, acc[8 + 2 * j]);
            acc[8 + 2 * j + 1] = fmaf(wsf, fb.y, acc[8 + 2 * j + 1]);
        }
    }
    float inv = 1.f / (z + 1e-16f);
    int j4 = l * 4 + g;
    int fo = 4 * g;
    float4 b = reinterpret_cast<const float4*>(bias)[j4];
    float rx = fmaxf(acc[fo + 0] * inv + b.x, 0.f);
    float ry = fmaxf(acc[fo + 1] * inv + b.y, 0.f);
    float rz = fmaxf(acc[fo + 2] * inv + b.z, 0.f);
    float rw = fmaxf(acc[fo + 3] * inv + b.w, 0.f);
    Xout[(size_t)w * 32 + j4] = make_uint2(pack_h2(rx, ry), pack_h2(rz, rw));
}

// ---------------- GraphConv epilogue: Y16 = relu(gather(P16) + Q16 + bias) ----
__global__ void k_gc_final(const uint32_t* __restrict__ P16, const uint32_t* __restrict__ Q16,
                           const float* __restrict__ bias, uint2* __restrict__ Y16) {
    int q = (blockIdx.x * blockDim.x + threadIdx.x) >> 3;
    if (q >= NN) return;
    int lane = threadIdx.x & 7;
    int row0 = g_rowptr[q], row1 = g_rowptr[q + 1];
    const uint2* P2 = reinterpret_cast<const uint2*>(P16);
    float4 acc = make_float4(0.f, 0.f, 0.f, 0.f);
    int s = (row0 < row1) ? g_csrc[row0] : 0;
    for (int k = row0; k < row1; k++) {
        int s_next = (k + 1 < row1) ? g_csrc[k + 1] : 0;
        uint2 p = P2[(size_t)s * 8 + lane];
        float2 f01 = __half22float2(*reinterpret_cast<const __half2*>(&p.x));
        float2 f23 = __half22float2(*reinterpret_cast<const __half2*>(&p.y));
        acc.x += f01.x; acc.y += f01.y; acc.z += f23.x; acc.w += f23.y;
        s = s_next;
    }
    uint2 qw = reinterpret_cast<const uint2*>(Q16)[(size_t)q * 8 + lane];
    float2 q01 = __half22float2(*reinterpret_cast<const __half2*>(&qw.x));
    float2 q23 = __half22float2(*reinterpret_cast<const __half2*>(&qw.y));
    float4 bb = reinterpret_cast<const float4*>(bias)[lane];
    float rx = fmaxf(acc.x + q01.x + bb.x, 0.f);
    float ry = fmaxf(acc.y + q01.y + bb.y, 0.f);
    float rz = fmaxf(acc.z + q23.x + bb.z, 0.f);
    float rw = fmaxf(acc.w + q23.y + bb.w, 0.f);
    Y16[(size_t)q * 8 + lane] = make_uint2(pack_h2(rx, ry), pack_h2(rz, rw));
}

// ---------------- SAGE epilogue + pool: pool += relu(mean(P16) + Q16 + bias) --
__global__ void k_sage_final(const uint32_t* __restrict__ P16, const uint32_t* __restrict__ Q16,
                             const float* __restrict__ bias,
                             const int* __restrict__ batch) {
    int q = (blockIdx.x * blockDim.x + threadIdx.x) >> 3;
    if (q >= NN) return;
    int lane = threadIdx.x & 7;
    int row0 = g_rowptr[q], row1 = g_rowptr[q + 1];
    const uint2* P2 = reinterpret_cast<const uint2*>(P16);
    float4 acc = make_float4(0.f, 0.f, 0.f, 0.f);
    int s = (row0 < row1) ? g_csrc[row0] : 0;
    for (int k = row0; k < row1; k++) {
        int s_next = (k + 1 < row1) ? g_csrc[k + 1] : 0;
        uint2 p = P2[(size_t)s * 8 + lane];
        float2 f01 = __half22float2(*reinterpret_cast<const __half2*>(&p.x));
        float2 f23 = __half22float2(*reinterpret_cast<const __half2*>(&p.y));
        acc.x += f01.x; acc.y += f01.y; acc.z += f23.x; acc.w += f23.y;
        s = s_next;
    }
    float inv = 1.f / fmaxf((float)(row1 - row0), 1.f);
    uint2 qw = reinterpret_cast<const uint2*>(Q16)[(size_t)q * 8 + lane];
    float2 q01 = __half22float2(*reinterpret_cast<const __half2*>(&qw.x));
    float2 q23 = __half22float2(*reinterpret_cast<const __half2*>(&qw.y));
    float4 bb = reinterpret_cast<const float4*>(bias)[lane];
    float4 r;
    r.x = fmaxf(fmaf(acc.x, inv, q01.x) + bb.x, 0.f);
    r.y = fmaxf(fmaf(acc.y, inv, q01.y) + bb.y, 0.f);
    r.z = fmaxf(fmaf(acc.z, inv, q23.x) + bb.z, 0.f);
    r.w = fmaxf(fmaf(acc.w, inv, q23.y) + bb.w, 0.f);
    int b = batch[q];
    atomicAdd(reinterpret_cast<float4*>(g_pool) + b * 8 + lane, r);
    if (lane == 0) atomicAdd(&g_cnt[b], 1.f);
}

// ---------------- MLP head (single tiny block) -------------------------------
__global__ void k_head(const float* __restrict__ Wf1, const float* __restrict__ bf1,
                       const float* __restrict__ Wf2, const float* __restrict__ bf2,
                       float* __restrict__ out) {
    __shared__ float t1[NGR * CC];
    int t = threadIdx.x;
    for (int idx = t; idx < NGR * CC; idx += blockDim.x) {
        int g = idx >> 5, c = idx & 31;
        float inv = 1.f / fmaxf(g_cnt[g], 1.f);
        float s = 0.f;
#pragma unroll
        for (int k = 0; k < CC; k++) s = fmaf(g_pool[g * CC + k] * inv, Wf1[k * CC + c], s);
        t1[idx] = fmaxf(s + bf1[c], 0.f);
    }
    __syncthreads();
    for (int idx = t; idx < NGR * NOUT; idx += blockDim.x) {
        int g = idx / NOUT, o = idx - g * NOUT;
        float s = 0.f;
#pragma unroll
        for (int k = 0; k < CC; k++) s = fmaf(t1[g * CC + k], Wf2[k * NOUT + o], s);
        out[idx] = s + bf2[o];
    }
}

// =============================================================================
extern "C" void kernel_launch(void* const* d_in, const int* in_sizes, int n_in,
                              void* d_out, int out_size) {
    const float* x   = (const float*)d_in[0];
    const int*   ei  = (const int*)d_in[1];
    const int*   bat = (const int*)d_in[2];
    const float* W1  = (const float*)d_in[3];
    const float* as1 = (const float*)d_in[4];
    const float* ad1 = (const float*)d_in[5];
    const float* b1  = (const float*)d_in[6];
    const float* W2  = (const float*)d_in[7];
    const float* as2 = (const float*)d_in[8];
    const float* ad2 = (const float*)d_in[9];
    const float* b2  = (const float*)d_in[10];
    const float* W3r = (const float*)d_in[11];
    const float* W3l = (const float*)d_in[12];
    const float* b3  = (const float*)d_in[13];
    const float* W4l = (const float*)d_in[14];
    const float* b4l = (const float*)d_in[15];
    const float* W4r = (const float*)d_in[16];
    const float* Wf1 = (const float*)d_in[17];
    const float* bf1 = (const float*)d_in[18];
    const float* Wf2 = (const float*)d_in[19];
    const float* bf2 = (const float*)d_in[20];
    const int* src = ei;
    const int* dst = ei + EE;
    float* out = (float*)d_out;

    static float *p_x = nullptr, *p_acc, *p_pool, *p_cnt;
    static uint32_t* p_h16;
    static int* p_cnt_i;
    static bool init_done = false;
    static cudaStream_t s2;
    static cudaEvent_t e1, e2, e3;
    if (!p_x) {
        cudaGetSymbolAddress((void**)&p_x, g_x);
        cudaGetSymbolAddress((void**)&p_acc, g_acc);
        cudaGetSymbolAddress((void**)&p_h16, g_h16);
        cudaGetSymbolAddress((void**)&p_pool, g_pool);
        cudaGetSymbolAddress((void**)&p_cnt, g_cnt);
        cudaGetSymbolAddress((void**)&p_cnt_i, g_cnt_i);
    }
    if (!init_done) {
        cudaFuncSetAttribute(k_gemm128mma<false>, cudaFuncAttributeMaxDynamicSharedMemorySize, SMEM_MMA);
        cudaFuncSetAttribute(k_gemm128mma<true>, cudaFuncAttributeMaxDynamicSharedMemorySize, SMEM_MMA);
        cudaFuncSetAttribute(k_projmma<HC>, cudaFuncAttributeMaxDynamicSharedMemorySize, SMEM_PROJ);
        cudaFuncSetAttribute(k_projmma<CC>, cudaFuncAttributeMaxDynamicSharedMemorySize, SMEM_PROJ);
        cudaStreamCreateWithFlags(&s2, cudaStreamNonBlocking);
        cudaEventCreateWithFlags(&e1, cudaEventDisableTiming);
        cudaEventCreateWithFlags(&e2, cudaEventDisableTiming);
        cudaEventCreateWithFlags(&e3, cudaEventDisableTiming);
        init_done = true;
    }

    const int T = 256;
    const int gE    = (EE + T - 1) / T;
    const int gWNN  = (NN * 32 + T - 1) / T;   // warp per node
    const int gQ8   = (NN * 8 + T - 1) / T;    // 8 lanes per node
    const int gR64  = (NN + 63) / 64;          // 64-row tiles

    uint32_t* x2_16 = reinterpret_cast<uint32_t*>(p_x);     // x2 fp16 (NN*64 words)
    uint32_t* x3_16 = reinterpret_cast<uint32_t*>(p_acc);   // x3 fp16 (NN*16 words)
    uint32_t* Pa = p_h16;             // NN*16 words
    uint32_t* Pb = p_h16 + NN * 16;   // NN*16 words

    // ---- fork: CSR build + pool-zero + proj-W prep on side stream ----
    cudaEventRecord(e1, 0);
    cudaStreamWaitEvent(s2, e1, 0);
    cudaMemsetAsync(p_cnt_i, 0, NN * sizeof(int), s2);
    k_count<<<gE, T, 0, s2>>>(dst);
    k_scan1<<<NB_SCAN, 1024, 0, s2>>>();
    k_scan2<<<1, 64, 0, s2>>>();
    k_scan3<<<(NN + 1023) / 1024, 1024, 0, s2>>>();
    k_fill<<<gE, T, 0, s2>>>(src, dst);
    cudaMemsetAsync(p_pool, 0, NGR * CC * sizeof(float), s2);
    cudaMemsetAsync(p_cnt, 0, NGR * sizeof(float), s2);
    cudaEventRecord(e2, s2);
    k_prepWcat<<<(HC * 64 + T - 1) / T, T, 0, s2>>>(W3r, W3l, HC, 0);
    k_prepWcat<<<(CC * 64 + T - 1) / T, T, 0, s2>>>(W4l, W4r, CC, 1);
    cudaEventRecord(e3, s2);

    // main stream: GAT W prep + layer-1 GEMM (independent of CSR)
    {
        dim3 gp((HC * HC + T - 1) / T, 2);
        k_prepWt2<<<gp, T>>>(W1, W2);
    }
    k_gemm128mma<false><<<gR64, 256, SMEM_MMA>>>(x, 0, as1, ad1);
    cudaStreamWaitEvent(0, e2, 0);     // CSR + pool-zero ready

    // ---- GAT layer 1 aggregation (x2 -> fp16) ----
    k_gat_aggr<<<gWNN, T>>>(b1, reinterpret_cast<uint2*>(x2_16));

    // ---- GAT layer 2 (fp16 input) ----
    k_gemm128mma<true><<<gR64, 256, SMEM_MMA>>>(x2_16, 1, as2, ad2);
    k_gat_aggr<<<gWNN, T>>>(b2, reinterpret_cast<uint2*>(x2_16));

    cudaStreamWaitEvent(0, e3, 0);     // proj weights ready
    // ---- GraphConv: x3 = relu(segsum((x2@W3r)[src]) + x2@W3l + b3) ----
    k_projmma<HC><<<gR64, 256, SMEM_PROJ>>>(x2_16, Pa, Pb);
    k_gc_final<<<gQ8, T>>>(Pa, Pb, b3, reinterpret_cast<uint2*>(x3_16));
    // ---- SAGEConv + pool ----
    k_projmma<CC><<<gR64, 256, SMEM_PROJ>>>(x3_16, Pa, Pb);
    k_sage_final<<<gQ8, T>>>(Pa, Pb, b4l, bat);

    // ---- head ----
    k_head<<<1, 1024>>>(Wf1, bf1, Wf2, bf2, out);
}

// round 17
// speedup vs baseline: 1.4578x; 1.0053x over previous
#include <cuda_runtime.h>
#include <cuda_bf16.h>
#include <cuda_fp16.h>
#include <cstdint>

#define NN   50000
#define EE   800000
#define HH   4
#define CC   32
#define HC   128
#define NGR  64
#define NOUT 10
#define NB_SCAN 49   // ceil(NN/1024)
#define STR  68      // smem row stride in 32-bit words

// ---------------- scratch (device globals; no allocation allowed) ------------
__device__ uint32_t g_h16[NN * 64];     // GAT h (half2); later P/Q fp16 images
__device__ float g_acc[NN * HC];        // x3 fp16 lives here (reinterpreted)
__device__ float g_x[NN * HC];          // x2 fp16 lives here (reinterpreted)
__device__ float g_as[NN * HH];
__device__ float g_ad[NN * HH];
__device__ float g_pool[NGR * CC];
__device__ float g_cnt[NGR];
// CSR by destination
__device__ int g_cnt_i[NN];
__device__ int g_rowptr[NN + 1];
__device__ int g_cursor[NN];
__device__ int g_csrc[EE];
__device__ int g_bsum[NB_SCAN];
// bf16-split transposed weights Wt[n][k] per GAT layer
__device__ __align__(16) unsigned short g_WtHi[2][HC * HC];
__device__ __align__(16) unsigned short g_WtLo[2][HC * HC];
// bf16-split concatenated projection weights [64 out][K in] transposed
__device__ __align__(16) unsigned short g_W3Hi[64 * HC];
__device__ __align__(16) unsigned short g_W3Lo[64 * HC];
__device__ __align__(16) unsigned short g_W4Hi[64 * CC];
__device__ __align__(16) unsigned short g_W4Lo[64 * CC];

__device__ __forceinline__ float lrelu(float v) { return v > 0.f ? v : 0.2f * v; }
__device__ __forceinline__ uint32_t pack_h2(float a, float b) {
    __half2 h = __floats2half2_rn(a, b);
    return *reinterpret_cast<uint32_t*>(&h);
}
__device__ __forceinline__ void bf16split(float v, unsigned short& hi, unsigned short& lo) {
    __nv_bfloat16 hb = __float2bfloat16(v);
    __nv_bfloat16 lb = __float2bfloat16(v - __bfloat162float(hb));
    hi = __bfloat16_as_ushort(hb);
    lo = __bfloat16_as_ushort(lb);
}
__device__ __forceinline__ void split_h2word(uint32_t w, uint32_t& xh, uint32_t& xl) {
    float2 f = __half22float2(*reinterpret_cast<const __half2*>(&w));
    unsigned short h0, l0, h1, l1;
    bf16split(f.x, h0, l0);
    bf16split(f.y, h1, l1);
    xh = ((uint32_t)h1 << 16) | h0;
    xl = ((uint32_t)l1 << 16) | l0;
}

// ---------------- W -> bf16 hi/lo transposed prep (GAT layers) ----------------
__global__ void k_prepWt2(const float* __restrict__ W1, const float* __restrict__ W2) {
    int i = blockIdx.x * blockDim.x + threadIdx.x;  // i = k*128 + n
    if (i >= HC * HC) return;
    int layer = blockIdx.y;
    const float* W = layer ? W2 : W1;
    int k = i >> 7, n = i & 127;
    unsigned short hi, lo;
    bf16split(W[i], hi, lo);
    g_WtHi[layer][n * HC + k] = hi;
    g_WtLo[layer][n * HC + k] = lo;
}

// ---------------- concat proj weights: [K][32]x2 -> [64][K] bf16 split --------
__global__ void k_prepWcat(const float* __restrict__ Wa, const float* __restrict__ Wb,
                           int K, int sel) {
    int i = blockIdx.x * blockDim.x + threadIdx.x;  // i = k*64 + n
    if (i >= K * 64) return;
    int k = i >> 6, n = i & 63;
    float w = (n < 32) ? Wa[k * 32 + n] : Wb[k * 32 + (n - 32)];
    unsigned short hi, lo;
    bf16split(w, hi, lo);
    if (sel == 0) { g_W3Hi[n * K + k] = hi; g_W3Lo[n * K + k] = lo; }
    else          { g_W4Hi[n * K + k] = hi; g_W4Lo[n * K + k] = lo; }
}

// ---------------- mma.sync bf16-split GEMM (64-row tiles, occ 2) --------------
#define MMA_BF16(c, A0, A1, A2, A3, B0, B1) \
    asm volatile("mma.sync.aligned.m16n8k16.row.col.f32.bf16.bf16.f32 " \
        "{%0,%1,%2,%3}, {%4,%5,%6,%7}, {%8,%9}, {%0,%1,%2,%3};" \
        : "+f"((c)[0]), "+f"((c)[1]), "+f"((c)[2]), "+f"((c)[3]) \
        : "r"(A0), "r"(A1), "r"(A2), "r"(A3), "r"(B0), "r"(B1))

// smem: xh 64*STR | xl 64*STR | wh 128*STR | wl 128*STR | sws 128f | swd 128f
#define SMEM_MMA ((2 * 64 + 2 * 128) * STR * 4 + 1024)

template <bool F16>
__global__ __launch_bounds__(256, 2) void k_gemm128mma(
    const void* __restrict__ Xv, int layer,
    const float* __restrict__ aws, const float* __restrict__ awd) {
    extern __shared__ __align__(16) char smem[];
    uint32_t* xh = reinterpret_cast<uint32_t*>(smem);
    uint32_t* xl = xh + 64 * STR;
    uint32_t* wh = xl + 64 * STR;
    uint32_t* wl = wh + 128 * STR;
    float* sws = reinterpret_cast<float*>(wl + 128 * STR);
    float* swd = sws + 128;
    int tid = threadIdx.x, lane = tid & 31, wid = tid >> 5;
    int gid = lane >> 2, tg = lane & 3;
    int row0 = blockIdx.x * 64;

    if (tid < 128) { sws[tid] = aws[tid]; swd[tid] = awd[tid]; }
    {
        const uint4* gh4 = reinterpret_cast<const uint4*>(g_WtHi[layer]);
        const uint4* gl4 = reinterpret_cast<const uint4*>(g_WtLo[layer]);
        uint4* wh4 = reinterpret_cast<uint4*>(wh);
        uint4* wl4 = reinterpret_cast<uint4*>(wl);
        for (int i = tid; i < 128 * 16; i += 256) {
            int r = i >> 4, q = i & 15;
            wh4[r * 17 + q] = gh4[i];
            wl4[r * 17 + q] = gl4[i];
        }
    }
    if (F16) {
        const uint4* X4 = reinterpret_cast<const uint4*>(Xv);
        for (int i = tid; i < 64 * 16; i += 256) {
            int r = i >> 4, q = i & 15;
            int grow = row0 + r;
            uint4 v = (grow < NN) ? X4[(size_t)grow * 16 + q] : make_uint4(0u, 0u, 0u, 0u);
            const uint32_t* w4 = &v.x;
#pragma unroll
            for (int j = 0; j < 4; j++) {
                uint32_t ph, pl;
                split_h2word(w4[j], ph, pl);
                xh[r * STR + q * 4 + j] = ph;
                xl[r * STR + q * 4 + j] = pl;
            }
        }
    } else {
        const float4* X4 = reinterpret_cast<const float4*>(Xv);
        for (int i = tid; i < 64 * 32; i += 256) {
            int r = i >> 5, q = i & 31;
            int grow = row0 + r;
            float4 v = (grow < NN) ? X4[(size_t)grow * 32 + q] : make_float4(0.f, 0.f, 0.f, 0.f);
            float vv[4] = {v.x, v.y, v.z, v.w};
#pragma unroll
            for (int q2 = 0; q2 < 2; q2++) {
                unsigned short h0, l0, h1, l1;
                bf16split(vv[2 * q2], h0, l0);
                bf16split(vv[2 * q2 + 1], h1, l1);
                xh[r * STR + 2 * q + q2] = ((uint32_t)h1 << 16) | h0;
                xl[r * STR + 2 * q + q2] = ((uint32_t)l1 << 16) | l0;
            }
        }
    }
    __syncthreads();

    int warpM = (wid & 3) * 16;
    int n0 = (wid >> 2) * 64;
    float acc[8][4];
#pragma unroll
    for (int t = 0; t < 8; t++)
#pragma unroll
        for (int j = 0; j < 4; j++) acc[t][j] = 0.f;

    const uint32_t* xrh = xh + (warpM + gid) * STR + tg;
    const uint32_t* xrl = xl + (warpM + gid) * STR + tg;
#pragma unroll 1
    for (int kk = 0; kk < 8; kk++) {
        int kw = kk * 8;
        uint32_t ah0 = xrh[kw],           ah2 = xrh[kw + 4];
        uint32_t ah1 = xrh[kw + 8 * STR], ah3 = xrh[kw + 8 * STR + 4];
        uint32_t al0 = xrl[kw],           al2 = xrl[kw + 4];
        uint32_t al1 = xrl[kw + 8 * STR], al3 = xrl[kw + 8 * STR + 4];
#pragma unroll
        for (int t = 0; t < 8; t++) {
            const uint32_t* wrh = wh + (n0 + t * 8 + gid) * STR + kw + tg;
            const uint32_t* wrl = wl + (n0 + t * 8 + gid) * STR + kw + tg;
            uint32_t bh0 = wrh[0], bh1 = wrh[4];
            uint32_t bl0 = wrl[0], bl1 = wrl[4];
            MMA_BF16(acc[t], ah0, ah1, ah2, ah3, bh0, bh1);
            MMA_BF16(acc[t], ah0, ah1, ah2, ah3, bl0, bl1);
            MMA_BF16(acc[t], al0, al1, al2, al3, bh0, bh1);
        }
    }

    int r0 = row0 + warpM + gid, r1 = r0 + 8;
#pragma unroll
    for (int t = 0; t < 8; t++) {
        int cidx = (n0 >> 1) + t * 4 + tg;
        if (r0 < NN) g_h16[(size_t)r0 * 64 + cidx] = pack_h2(acc[t][0], acc[t][1]);
        if (r1 < NN) g_h16[(size_t)r1 * 64 + cidx] = pack_h2(acc[t][2], acc[t][3]);
    }
#pragma unroll
    for (int hh = 0; hh < 2; hh++) {
        int h = (n0 >> 5) + hh;
        float ps0 = 0.f, pd0 = 0.f, ps1 = 0.f, pd1 = 0.f;
#pragma unroll
        for (int j = 0; j < 4; j++) {
            int t = hh * 4 + j;
            int col = n0 + t * 8 + 2 * tg;
            float w0 = sws[col], w1 = sws[col + 1];
            float v0 = swd[col], v1 = swd[col + 1];
            ps0 = fmaf(acc[t][0], w0, fmaf(acc[t][1], w1, ps0));
            pd0 = fmaf(acc[t][0], v0, fmaf(acc[t][1], v1, pd0));
            ps1 = fmaf(acc[t][2], w0, fmaf(acc[t][3], w1, ps1));
            pd1 = fmaf(acc[t][2], v0, fmaf(acc[t][3], v1, pd1));
        }
#pragma unroll
        for (int o = 1; o <= 2; o <<= 1) {
            ps0 += __shfl_xor_sync(0xffffffffu, ps0, o);
            pd0 += __shfl_xor_sync(0xffffffffu, pd0, o);
            ps1 += __shfl_xor_sync(0xffffffffu, ps1, o);
            pd1 += __shfl_xor_sync(0xffffffffu, pd1, o);
        }
        if (tg == 0) {
            if (r0 < NN) { g_as[r0 * HH + h] = ps0; g_ad[r0 * HH + h] = pd0; }
            if (r1 < NN) { g_as[r1 * HH + h] = ps1; g_ad[r1 * HH + h] = pd1; }
        }
    }
}

// ---------------- MMA dual projection -> fp16 outputs (32 cols each) ----------
#define SMEM_PROJ (4 * 64 * STR * 4)

template <int K>
__global__ __launch_bounds__(256, 2) void k_projmma(
    const uint32_t* __restrict__ X16, uint32_t* __restrict__ Ya, uint32_t* __restrict__ Yb) {
    extern __shared__ __align__(16) char smem[];
    uint32_t* xh = reinterpret_cast<uint32_t*>(smem);
    uint32_t* xl = xh + 64 * STR;
    uint32_t* wh = xl + 64 * STR;
    uint32_t* wl = wh + 64 * STR;
    int tid = threadIdx.x, lane = tid & 31, wid = tid >> 5;
    int gid = lane >> 2, tg = lane & 3;
    int row0 = blockIdx.x * 64;
    const unsigned short* WHi = (K == HC) ? g_W3Hi : g_W4Hi;
    const unsigned short* WLo = (K == HC) ? g_W3Lo : g_W4Lo;
    {
        const uint4* gh4 = reinterpret_cast<const uint4*>(WHi);
        const uint4* gl4 = reinterpret_cast<const uint4*>(WLo);
        uint4* wh4 = reinterpret_cast<uint4*>(wh);
        uint4* wl4 = reinterpret_cast<uint4*>(wl);
        constexpr int WQ = K / 8;
        for (int i = tid; i < 64 * WQ; i += 256) {
            int r = i / WQ, q = i % WQ;
            wh4[r * 17 + q] = gh4[i];
            wl4[r * 17 + q] = gl4[i];
        }
    }
    {
        const uint4* X4 = reinterpret_cast<const uint4*>(X16);
        constexpr int XQ = K / 8;
        for (int i = tid; i < 64 * XQ; i += 256) {
            int r = i / XQ, q = i % XQ;
            int grow = row0 + r;
            uint4 v = (grow < NN) ? X4[(size_t)grow * XQ + q] : make_uint4(0u, 0u, 0u, 0u);
            const uint32_t* w4 = &v.x;
#pragma unroll
            for (int j = 0; j < 4; j++) {
                uint32_t ph, pl;
                split_h2word(w4[j], ph, pl);
                xh[r * STR + q * 4 + j] = ph;
                xl[r * STR + q * 4 + j] = pl;
            }
        }
    }
    __syncthreads();

    int warpM = (wid & 3) * 16;
    int n0 = (wid >> 2) * 32;
    float acc[4][4];
#pragma unroll
    for (int t = 0; t < 4; t++)
#pragma unroll
        for (int j = 0; j < 4; j++) acc[t][j] = 0.f;

    const uint32_t* xrh = xh + (warpM + gid) * STR + tg;
    const uint32_t* xrl = xl + (warpM + gid) * STR + tg;
#pragma unroll
    for (int kk = 0; kk < K / 16; kk++) {
        int kw = kk * 8;
        uint32_t ah0 = xrh[kw],           ah2 = xrh[kw + 4];
        uint32_t ah1 = xrh[kw + 8 * STR], ah3 = xrh[kw + 8 * STR + 4];
        uint32_t al0 = xrl[kw],           al2 = xrl[kw + 4];
        uint32_t al1 = xrl[kw + 8 * STR], al3 = xrl[kw + 8 * STR + 4];
#pragma unroll
        for (int t = 0; t < 4; t++) {
            const uint32_t* wrh = wh + (n0 + t * 8 + gid) * STR + kw + tg;
            const uint32_t* wrl = wl + (n0 + t * 8 + gid) * STR + kw + tg;
            uint32_t bh0 = wrh[0], bh1 = wrh[4];
            uint32_t bl0 = wrl[0], bl1 = wrl[4];
            MMA_BF16(acc[t], ah0, ah1, ah2, ah3, bh0, bh1);
            MMA_BF16(acc[t], ah0, ah1, ah2, ah3, bl0, bl1);
            MMA_BF16(acc[t], al0, al1, al2, al3, bh0, bh1);
        }
    }

    uint32_t* dst = (n0 == 0) ? Ya : Yb;
    int r0 = row0 + warpM + gid, r1 = r0 + 8;
#pragma unroll
    for (int t = 0; t < 4; t++) {
        int widx = t * 4 + tg;
        if (r0 < NN) dst[(size_t)r0 * 16 + widx] = pack_h2(acc[t][0], acc[t][1]);
        if (r1 < NN) dst[(size_t)r1 * 16 + widx] = pack_h2(acc[t][2], acc[t][3]);
    }
}

// ---------------- CSR build ---------------------------------------------------
__global__ void k_count(const int* __restrict__ dst) {
    int e = blockIdx.x * blockDim.x + threadIdx.x;
    if (e < EE) atomicAdd(&g_cnt_i[dst[e]], 1);
}

__global__ void k_scan1() {
    __shared__ int wsum[32];
    int t = threadIdx.x, b = blockIdx.x;
    int i = b * 1024 + t;
    int v = (i < NN) ? g_cnt_i[i] : 0;
    int incl = v;
#pragma unroll
    for (int o = 1; o < 32; o <<= 1) {
        int n = __shfl_up_sync(0xffffffffu, incl, o);
        if ((t & 31) >= o) incl += n;
    }
    if ((t & 31) == 31) wsum[t >> 5] = incl;
    __syncthreads();
    if (t < 32) {
        int wv = wsum[t];
#pragma unroll
        for (int o = 1; o < 32; o <<= 1) {
            int n = __shfl_up_sync(0xffffffffu, wv, o);
            if (t >= o) wv += n;
        }
        wsum[t] = wv;
    }
    __syncthreads();
    int excl = incl - v + ((t >= 32) ? wsum[(t >> 5) - 1] : 0);
    if (i < NN) g_rowptr[i] = excl;
    if (t == 1023) g_bsum[b] = excl + v;
}

// fused scan2+scan3: each block re-derives its own offset from the 49 bsums
__global__ void k_scan3f() {
    __shared__ int s_off;
    int t = threadIdx.x, b = blockIdx.x;
    if (t == 0) {
        int off = 0;
#pragma unroll 7
        for (int j = 0; j < NB_SCAN; j++) off += (j < b) ? g_bsum[j] : 0;
        s_off = off;
    }
    __syncthreads();
    int i = b * 1024 + t;
    if (i < NN) {
        int v = g_rowptr[i] + s_off;
        g_rowptr[i] = v;
        g_cursor[i] = v;
    }
    if (i == 0) g_rowptr[NN] = EE;
}

__global__ void k_fill(const int* __restrict__ src, const int* __restrict__ dst) {
    int e = blockIdx.x * blockDim.x + threadIdx.x;
    if (e >= EE) return;
    int pos = atomicAdd(&g_cursor[dst[e]], 1);
    g_csrc[pos] = src[e];
}

// ---------------- fused GAT aggregation: 4 edges/warp-iter + idx prefetch -----
__global__ void k_gat_aggr(const float* __restrict__ bias, uint2* __restrict__ Xout) {
    int w = (blockIdx.x * blockDim.x + threadIdx.x) >> 5;
    if (w >= NN) return;
    int lane = threadIdx.x & 31;
    int g = lane >> 3, l = lane & 7;
    int hd = l >> 1;
    int row0 = g_rowptr[w], row1 = g_rowptr[w + 1];
    float ad_l = g_ad[w * HH + hd];
    const uint4* HV4 = reinterpret_cast<const uint4*>(g_h16);
    float acc[16];
#pragma unroll
    for (int i = 0; i < 16; i++) acc[i] = 0.f;
    float z = 0.f;
    int e0 = row0 + g;
    int s = (e0 < row1) ? g_csrc[e0] : 0;
    bool valid = e0 < row1;
    for (int base = row0; base < row1; base += 4) {
        // prefetch next iteration's index before consuming current payloads
        int e2 = base + 4 + g;
        int s_nxt = (e2 < row1) ? g_csrc[e2] : 0;
        float as_l = g_as[s * HH + hd];
        uint4 q0 = HV4[(size_t)s * 16 + l * 2];
        uint4 q1 = HV4[(size_t)s * 16 + l * 2 + 1];
        float wgt = valid ? __expf(lrelu(as_l + ad_l)) : 0.f;
        z += wgt;
        const uint32_t* qa = &q0.x;
        const uint32_t* qb = &q1.x;
#pragma unroll
        for (int j = 0; j < 4; j++) {
            float2 fa = __half22float2(*reinterpret_cast<const __half2*>(&qa[j]));
            float2 fb = __half22float2(*reinterpret_cast<const __half2*>(&qb[j]));
            acc[2 * j]     = fmaf(wgt, fa.x, acc[2 * j]);
            acc[2 * j + 1] = fmaf(wgt, fa.y, acc[2 * j + 1]);
            acc[8 + 2 * j]     = fmaf(wgt, fb.x, acc[8 + 2 * j]);
            acc[8 + 2 * j + 1] = fmaf(wgt, fb.y, acc[8 + 2 * j + 1]);
        }
        s = s_nxt;
        valid = e2 < row1;
    }
#pragma unroll
    for (int o = 8; o <= 16; o <<= 1) {
        z += __shfl_xor_sync(0xffffffffu, z, o);
#pragma unroll
        for (int i = 0; i < 16; i++)
            acc[i] += __shfl_xor_sync(0xffffffffu, acc[i], o);
    }
    float as_self = g_as[w * HH + hd];
    float wsf = __expf(lrelu(as_self + ad_l));
    z += wsf;
    {
        uint4 q0 = HV4[(size_t)w * 16 + l * 2];
        uint4 q1 = HV4[(size_t)w * 16 + l * 2 + 1];
        const uint32_t* qa = &q0.x;
        const uint32_t* qb = &q1.x;
#pragma unroll
        for (int j = 0; j < 4; j++) {
            float2 fa = __half22float2(*reinterpret_cast<const __half2*>(&qa[j]));
            float2 fb = __half22float2(*reinterpret_cast<const __half2*>(&qb[j]));
            acc[2 * j]     = fmaf(wsf, fa.x, acc[2 * j]);
            acc[2 * j + 1] = fmaf(wsf, fa.y, acc[2 * j + 1]);
            acc[8 + 2 * j]     = fmaf(wsf, fb.x, acc[8 + 2 * j]);
            acc[8 + 2 * j + 1] = fmaf(wsf, fb.y, acc[8 + 2 * j + 1]);
        }
    }
    float inv = 1.f / (z + 1e-16f);
    int j4 = l * 4 + g;
    int fo = 4 * g;
    float4 b = reinterpret_cast<const float4*>(bias)[j4];
    float rx = fmaxf(acc[fo + 0] * inv + b.x, 0.f);
    float ry = fmaxf(acc[fo + 1] * inv + b.y, 0.f);
    float rz = fmaxf(acc[fo + 2] * inv + b.z, 0.f);
    float rw = fmaxf(acc[fo + 3] * inv + b.w, 0.f);
    Xout[(size_t)w * 32 + j4] = make_uint2(pack_h2(rx, ry), pack_h2(rz, rw));
}

// ---------------- GraphConv epilogue: Y16 = relu(gather(P16) + Q16 + bias) ----
__global__ void k_gc_final(const uint32_t* __restrict__ P16, const uint32_t* __restrict__ Q16,
                           const float* __restrict__ bias, uint2* __restrict__ Y16) {
    int q = (blockIdx.x * blockDim.x + threadIdx.x) >> 3;
    if (q >= NN) return;
    int lane = threadIdx.x & 7;
    int row0 = g_rowptr[q], row1 = g_rowptr[q + 1];
    const uint2* P2 = reinterpret_cast<const uint2*>(P16);
    float4 acc = make_float4(0.f, 0.f, 0.f, 0.f);
    int s = (row0 < row1) ? g_csrc[row0] : 0;
    for (int k = row0; k < row1; k++) {
        int s_next = (k + 1 < row1) ? g_csrc[k + 1] : 0;
        uint2 p = P2[(size_t)s * 8 + lane];
        float2 f01 = __half22float2(*reinterpret_cast<const __half2*>(&p.x));
        float2 f23 = __half22float2(*reinterpret_cast<const __half2*>(&p.y));
        acc.x += f01.x; acc.y += f01.y; acc.z += f23.x; acc.w += f23.y;
        s = s_next;
    }
    uint2 qw = reinterpret_cast<const uint2*>(Q16)[(size_t)q * 8 + lane];
    float2 q01 = __half22float2(*reinterpret_cast<const __half2*>(&qw.x));
    float2 q23 = __half22float2(*reinterpret_cast<const __half2*>(&qw.y));
    float4 bb = reinterpret_cast<const float4*>(bias)[lane];
    float rx = fmaxf(acc.x + q01.x + bb.x, 0.f);
    float ry = fmaxf(acc.y + q01.y + bb.y, 0.f);
    float rz = fmaxf(acc.z + q23.x + bb.z, 0.f);
    float rw = fmaxf(acc.w + q23.y + bb.w, 0.f);
    Y16[(size_t)q * 8 + lane] = make_uint2(pack_h2(rx, ry), pack_h2(rz, rw));
}

// ---------------- SAGE epilogue + pool: pool += relu(mean(P16) + Q16 + bias) --
__global__ void k_sage_final(const uint32_t* __restrict__ P16, const uint32_t* __restrict__ Q16,
                             const float* __restrict__ bias,
                             const int* __restrict__ batch) {
    int q = (blockIdx.x * blockDim.x + threadIdx.x) >> 3;
    if (q >= NN) return;
    int lane = threadIdx.x & 7;
    int row0 = g_rowptr[q], row1 = g_rowptr[q + 1];
    const uint2* P2 = reinterpret_cast<const uint2*>(P16);
    float4 acc = make_float4(0.f, 0.f, 0.f, 0.f);
    int s = (row0 < row1) ? g_csrc[row0] : 0;
    for (int k = row0; k < row1; k++) {
        int s_next = (k + 1 < row1) ? g_csrc[k + 1] : 0;
        uint2 p = P2[(size_t)s * 8 + lane];
        float2 f01 = __half22float2(*reinterpret_cast<const __half2*>(&p.x));
        float2 f23 = __half22float2(*reinterpret_cast<const __half2*>(&p.y));
        acc.x += f01.x; acc.y += f01.y; acc.z += f23.x; acc.w += f23.y;
        s = s_next;
    }
    float inv = 1.f / fmaxf((float)(row1 - row0), 1.f);
    uint2 qw = reinterpret_cast<const uint2*>(Q16)[(size_t)q * 8 + lane];
    float2 q01 = __half22float2(*reinterpret_cast<const __half2*>(&qw.x));
    float2 q23 = __half22float2(*reinterpret_cast<const __half2*>(&qw.y));
    float4 bb = reinterpret_cast<const float4*>(bias)[lane];
    float4 r;
    r.x = fmaxf(fmaf(acc.x, inv, q01.x) + bb.x, 0.f);
    r.y = fmaxf(fmaf(acc.y, inv, q01.y) + bb.y, 0.f);
    r.z = fmaxf(fmaf(acc.z, inv, q23.x) + bb.z, 0.f);
    r.w = fmaxf(fmaf(acc.w, inv, q23.y) + bb.w, 0.f);
    int b = batch[q];
    atomicAdd(reinterpret_cast<float4*>(g_pool) + b * 8 + lane, r);
    if (lane == 0) atomicAdd(&g_cnt[b], 1.f);
}

// ---------------- MLP head (single tiny block) -------------------------------
__global__ void k_head(const float* __restrict__ Wf1, const float* __restrict__ bf1,
                       const float* __restrict__ Wf2, const float* __restrict__ bf2,
                       float* __restrict__ out) {
    __shared__ float t1[NGR * CC];
    int t = threadIdx.x;
    for (int idx = t; idx < NGR * CC; idx += blockDim.x) {
        int g = idx >> 5, c = idx & 31;
        float inv = 1.f / fmaxf(g_cnt[g], 1.f);
        float s = 0.f;
#pragma unroll
        for (int k = 0; k < CC; k++) s = fmaf(g_pool[g * CC + k] * inv, Wf1[k * CC + c], s);
        t1[idx] = fmaxf(s + bf1[c], 0.f);
    }
    __syncthreads();
    for (int idx = t; idx < NGR * NOUT; idx += blockDim.x) {
        int g = idx / NOUT, o = idx - g * NOUT;
        float s = 0.f;
#pragma unroll
        for (int k = 0; k < CC; k++) s = fmaf(t1[g * CC + k], Wf2[k * NOUT + o], s);
        out[idx] = s + bf2[o];
    }
}

// =============================================================================
extern "C" void kernel_launch(void* const* d_in, const int* in_sizes, int n_in,
                              void* d_out, int out_size) {
    const float* x   = (const float*)d_in[0];
    const int*   ei  = (const int*)d_in[1];
    const int*   bat = (const int*)d_in[2];
    const float* W1  = (const float*)d_in[3];
    const float* as1 = (const float*)d_in[4];
    const float* ad1 = (const float*)d_in[5];
    const float* b1  = (const float*)d_in[6];
    const float* W2  = (const float*)d_in[7];
    const float* as2 = (const float*)d_in[8];
    const float* ad2 = (const float*)d_in[9];
    const float* b2  = (const float*)d_in[10];
    const float* W3r = (const float*)d_in[11];
    const float* W3l = (const float*)d_in[12];
    const float* b3  = (const float*)d_in[13];
    const float* W4l = (const float*)d_in[14];
    const float* b4l = (const float*)d_in[15];
    const float* W4r = (const float*)d_in[16];
    const float* Wf1 = (const float*)d_in[17];
    const float* bf1 = (const float*)d_in[18];
    const float* Wf2 = (const float*)d_in[19];
    const float* bf2 = (const float*)d_in[20];
    const int* src = ei;
    const int* dst = ei + EE;
    float* out = (float*)d_out;

    static float *p_x = nullptr, *p_acc, *p_pool, *p_cnt;
    static uint32_t* p_h16;
    static int* p_cnt_i;
    static bool init_done = false;
    static cudaStream_t s2;
    static cudaEvent_t e1, e2, e3;
    if (!p_x) {
        cudaGetSymbolAddress((void**)&p_x, g_x);
        cudaGetSymbolAddress((void**)&p_acc, g_acc);
        cudaGetSymbolAddress((void**)&p_h16, g_h16);
        cudaGetSymbolAddress((void**)&p_pool, g_pool);
        cudaGetSymbolAddress((void**)&p_cnt, g_cnt);
        cudaGetSymbolAddress((void**)&p_cnt_i, g_cnt_i);
    }
    if (!init_done) {
        cudaFuncSetAttribute(k_gemm128mma<false>, cudaFuncAttributeMaxDynamicSharedMemorySize, SMEM_MMA);
        cudaFuncSetAttribute(k_gemm128mma<true>, cudaFuncAttributeMaxDynamicSharedMemorySize, SMEM_MMA);
        cudaFuncSetAttribute(k_projmma<HC>, cudaFuncAttributeMaxDynamicSharedMemorySize, SMEM_PROJ);
        cudaFuncSetAttribute(k_projmma<CC>, cudaFuncAttributeMaxDynamicSharedMemorySize, SMEM_PROJ);
        cudaStreamCreateWithFlags(&s2, cudaStreamNonBlocking);
        cudaEventCreateWithFlags(&e1, cudaEventDisableTiming);
        cudaEventCreateWithFlags(&e2, cudaEventDisableTiming);
        cudaEventCreateWithFlags(&e3, cudaEventDisableTiming);
        init_done = true;
    }

    const int T = 256;
    const int gE    = (EE + T - 1) / T;
    const int gWNN  = (NN * 32 + T - 1) / T;   // warp per node
    const int gQ8   = (NN * 8 + T - 1) / T;    // 8 lanes per node
    const int gR64  = (NN + 63) / 64;          // 64-row tiles

    uint32_t* x2_16 = reinterpret_cast<uint32_t*>(p_x);     // x2 fp16 (NN*64 words)
    uint32_t* x3_16 = reinterpret_cast<uint32_t*>(p_acc);   // x3 fp16 (NN*16 words)
    uint32_t* Pa = p_h16;             // NN*16 words
    uint32_t* Pb = p_h16 + NN * 16;   // NN*16 words

    // ---- fork: CSR build + pool-zero + proj-W prep on side stream ----
    cudaEventRecord(e1, 0);
    cudaStreamWaitEvent(s2, e1, 0);
    cudaMemsetAsync(p_cnt_i, 0, NN * sizeof(int), s2);
    k_count<<<gE, T, 0, s2>>>(dst);
    k_scan1<<<NB_SCAN, 1024, 0, s2>>>();
    k_scan3f<<<NB_SCAN, 1024, 0, s2>>>();
    k_fill<<<gE, T, 0, s2>>>(src, dst);
    cudaMemsetAsync(p_pool, 0, NGR * CC * sizeof(float), s2);
    cudaMemsetAsync(p_cnt, 0, NGR * sizeof(float), s2);
    cudaEventRecord(e2, s2);
    k_prepWcat<<<(HC * 64 + T - 1) / T, T, 0, s2>>>(W3r, W3l, HC, 0);
    k_prepWcat<<<(CC * 64 + T - 1) / T, T, 0, s2>>>(W4l, W4r, CC, 1);
    cudaEventRecord(e3, s2);

    // main stream: GAT W prep + layer-1 GEMM (independent of CSR)
    {
        dim3 gp((HC * HC + T - 1) / T, 2);
        k_prepWt2<<<gp, T>>>(W1, W2);
    }
    k_gemm128mma<false><<<gR64, 256, SMEM_MMA>>>(x, 0, as1, ad1);
    cudaStreamWaitEvent(0, e2, 0);     // CSR + pool-zero ready

    // ---- GAT layer 1 aggregation (x2 -> fp16) ----
    k_gat_aggr<<<gWNN, T>>>(b1, reinterpret_cast<uint2*>(x2_16));

    // ---- GAT layer 2 (fp16 input) ----
    k_gemm128mma<true><<<gR64, 256, SMEM_MMA>>>(x2_16, 1, as2, ad2);
    k_gat_aggr<<<gWNN, T>>>(b2, reinterpret_cast<uint2*>(x2_16));

    cudaStreamWaitEvent(0, e3, 0);     // proj weights ready
    // ---- GraphConv: x3 = relu(segsum((x2@W3r)[src]) + x2@W3l + b3) ----
    k_projmma<HC><<<gR64, 256, SMEM_PROJ>>>(x2_16, Pa, Pb);
    k_gc_final<<<gQ8, T>>>(Pa, Pb, b3, reinterpret_cast<uint2*>(x3_16));
    // ---- SAGEConv + pool ----
    k_projmma<CC><<<gR64, 256, SMEM_PROJ>>>(x3_16, Pa, Pb);
    k_sage_final<<<gQ8, T>>>(Pa, Pb, b4l, bat);

    // ---- head ----
    k_head<<<1, 1024>>>(Wf1, bf1, Wf2, bf2, out);
}